// round 4
// baseline (speedup 1.0000x reference)
#include <cuda_runtime.h>
#include <math.h>

#define NN   50000
#define EE   800000
#define IND  128
#define OUTD 128
#define EDIMK 96

// ---- scratch (static device arrays; no allocation) ----
__device__ float g_q[NN * OUTD];
__device__ float g_k[NN * OUTD];
__device__ float g_v[NN * OUTD];
__device__ float g_skip[NN * OUTD];
__device__ float g_denom[NN * 2];

extern __shared__ float smem_dyn[];

// ---------------------------------------------------------------------------
// K0: zero d_out and denominators
// ---------------------------------------------------------------------------
__global__ void zero_kernel(float* __restrict__ out) {
    int idx = blockIdx.x * blockDim.x + threadIdx.x;
    int stride = gridDim.x * blockDim.x;
    const int total4 = NN * OUTD / 4;
    for (int i = idx; i < total4; i += stride)
        ((float4*)out)[i] = make_float4(0.f, 0.f, 0.f, 0.f);
    for (int i = idx; i < NN * 2; i += stride)
        g_denom[i] = 0.f;
}

// ---------------------------------------------------------------------------
// K1: node projections  q/k/v/skip = x @ W + b
//     grid = (ceil(N/128), 4), block = 256, dyn smem = 128*128 + 32*128 floats
// ---------------------------------------------------------------------------
__global__ __launch_bounds__(256, 2) void proj_kernel(
    const float* __restrict__ x,
    const float* __restrict__ Wq, const float* __restrict__ bq,
    const float* __restrict__ Wk, const float* __restrict__ bk,
    const float* __restrict__ Wv, const float* __restrict__ bv,
    const float* __restrict__ Wsk, const float* __restrict__ bsk)
{
    float* ws  = smem_dyn;               // [128][128]  W tile (full)
    float* xsT = smem_dyn + 128 * 128;   // [32][128]   x chunk, transposed [k][row]

    const float* W; const float* bias; float* out;
    switch (blockIdx.y) {
        case 0:  W = Wq;  bias = bq;  out = g_q;    break;
        case 1:  W = Wk;  bias = bk;  out = g_k;    break;
        case 2:  W = Wv;  bias = bv;  out = g_v;    break;
        default: W = Wsk; bias = bsk; out = g_skip; break;
    }

    int tid  = threadIdx.x;
    int row0 = blockIdx.x * 128;

    // load full W (64KB), coalesced
    for (int i = tid; i < 128 * 128 / 4; i += 256)
        ((float4*)ws)[i] = ((const float4*)W)[i];

    int tx = tid & 15, ty = tid >> 4;
    int col0 = tx * 8;

    float acc[8][8];
    #pragma unroll
    for (int i = 0; i < 8; i++)
        #pragma unroll
        for (int j = 0; j < 8; j++) acc[i][j] = 0.f;

    for (int kb = 0; kb < 4; kb++) {
        __syncthreads();
        // load x chunk [128 rows][32 k] transposed into xsT[k][row]
        for (int i = tid; i < 128 * 8; i += 256) {
            int r  = i >> 3;
            int c4 = (i & 7) * 4;
            float4 xv = make_float4(0.f, 0.f, 0.f, 0.f);
            int gr = row0 + r;
            if (gr < NN)
                xv = *(const float4*)&x[(size_t)gr * IND + kb * 32 + c4];
            xsT[(c4 + 0) * 128 + r] = xv.x;
            xsT[(c4 + 1) * 128 + r] = xv.y;
            xsT[(c4 + 2) * 128 + r] = xv.z;
            xsT[(c4 + 3) * 128 + r] = xv.w;
        }
        __syncthreads();
        #pragma unroll
        for (int k = 0; k < 32; k++) {
            float a[8], b[8];
            *(float4*)&a[0] = *(float4*)&xsT[k * 128 + ty * 8];
            *(float4*)&a[4] = *(float4*)&xsT[k * 128 + ty * 8 + 4];
            *(float4*)&b[0] = *(float4*)&ws[(kb * 32 + k) * 128 + col0];
            *(float4*)&b[4] = *(float4*)&ws[(kb * 32 + k) * 128 + col0 + 4];
            #pragma unroll
            for (int i = 0; i < 8; i++)
                #pragma unroll
                for (int j = 0; j < 8; j++)
                    acc[i][j] += a[i] * b[j];
        }
    }

    float bb[8];
    #pragma unroll
    for (int j = 0; j < 8; j++) bb[j] = bias[col0 + j];

    #pragma unroll
    for (int i = 0; i < 8; i++) {
        int gr = row0 + ty * 8 + i;
        if (gr < NN) {
            float4 o0, o1;
            o0.x = acc[i][0] + bb[0]; o0.y = acc[i][1] + bb[1];
            o0.z = acc[i][2] + bb[2]; o0.w = acc[i][3] + bb[3];
            o1.x = acc[i][4] + bb[4]; o1.y = acc[i][5] + bb[5];
            o1.z = acc[i][6] + bb[6]; o1.w = acc[i][7] + bb[7];
            *(float4*)&out[(size_t)gr * OUTD + col0]     = o0;
            *(float4*)&out[(size_t)gr * OUTD + col0 + 4] = o1;
        }
    }
}

// ---------------------------------------------------------------------------
// K2: fused edge kernel. 128 edges per block, 256 threads.
//     - build attrT[96][128] (cos time-enc + msg), W_e in smem
//     - e-tile GEMM in registers (8x8 per thread)
//     - attention logits via warp shuffle reduction, ex = exp(alpha/8)
//     - atomic denom + unnormalized scalar-atomic aggregation into out
// ---------------------------------------------------------------------------
__global__ __launch_bounds__(256, 2) void edge_kernel(
    const float* __restrict__ lu, const float* __restrict__ tt,
    const float* __restrict__ msg, const int* __restrict__ ei,
    const float* __restrict__ Wtime, const float* __restrict__ btime,
    const float* __restrict__ We, const float* __restrict__ be,
    float* __restrict__ out)
{
    float* attrT = smem_dyn;                 // [96][128]  (k-major, edge inner)
    float* wes   = smem_dyn + EDIMK * 128;   // [96][128]
    __shared__ int   srcS[128];
    __shared__ int   dstS[128];
    __shared__ float relS[128];

    int tid = threadIdx.x;
    int eb  = blockIdx.x * 128;

    if (tid < 128) {
        int e = eb + tid;
        int s = ei[e];            // edge_index row 0 (int32 — JAX x64 is off)
        srcS[tid] = s;
        dstS[tid] = ei[EE + e];   // edge_index row 1
        relS[tid] = lu[s] - tt[e];
    }
    // W_e -> smem (48KB)
    for (int i = tid; i < EDIMK * 128 / 4; i += 256)
        ((float4*)wes)[i] = ((const float4*)We)[i];
    // msg -> attrT rows 32..95 (transposed)
    for (int i = tid; i < 128 * 16; i += 256) {
        int e  = i >> 4;
        int c4 = (i & 15) * 4;
        float4 m = *(const float4*)&msg[(size_t)(eb + e) * 64 + c4];
        attrT[(32 + c4 + 0) * 128 + e] = m.x;
        attrT[(32 + c4 + 1) * 128 + e] = m.y;
        attrT[(32 + c4 + 2) * 128 + e] = m.z;
        attrT[(32 + c4 + 3) * 128 + e] = m.w;
    }
    __syncthreads();
    // time encoding -> attrT rows 0..31
    for (int i = tid; i < 32 * 128; i += 256) {
        int d = i >> 7;
        int e = i & 127;
        attrT[d * 128 + e] = __cosf(relS[e] * Wtime[d] + btime[d]);
    }
    __syncthreads();

    int tx = tid & 15, ty = tid >> 4;
    int col0 = tx * 8;
    int h = col0 >> 6;

    // e-tile accumulators, initialized with bias
    float acc[8][8];
    #pragma unroll
    for (int j = 0; j < 8; j++) {
        float bb = be[col0 + j];
        #pragma unroll
        for (int i = 0; i < 8; i++) acc[i][j] = bb;
    }
    for (int k = 0; k < EDIMK; k++) {
        float a[8], b[8];
        *(float4*)&a[0] = *(float4*)&attrT[k * 128 + ty * 8];
        *(float4*)&a[4] = *(float4*)&attrT[k * 128 + ty * 8 + 4];
        *(float4*)&b[0] = *(float4*)&wes[k * 128 + col0];
        *(float4*)&b[4] = *(float4*)&wes[k * 128 + col0 + 4];
        #pragma unroll
        for (int i = 0; i < 8; i++)
            #pragma unroll
            for (int j = 0; j < 8; j++)
                acc[i][j] += a[i] * b[j];
    }

    // partial logits: this thread covers 8 cols of head h for 8 edges
    float p[8];
    #pragma unroll
    for (int i = 0; i < 8; i++) {
        int el = ty * 8 + i;
        int s = srcS[el], d = dstS[el];
        float4 q0 = *(const float4*)&g_q[d * 128 + col0];
        float4 q1 = *(const float4*)&g_q[d * 128 + col0 + 4];
        float4 k0 = *(const float4*)&g_k[s * 128 + col0];
        float4 k1 = *(const float4*)&g_k[s * 128 + col0 + 4];
        p[i] = q0.x * (k0.x + acc[i][0]) + q0.y * (k0.y + acc[i][1])
             + q0.z * (k0.z + acc[i][2]) + q0.w * (k0.w + acc[i][3])
             + q1.x * (k1.x + acc[i][4]) + q1.y * (k1.y + acc[i][5])
             + q1.z * (k1.z + acc[i][6]) + q1.w * (k1.w + acc[i][7]);
    }
    // butterfly reduce over the 8-lane group (same ty, same head, tx&7 varies)
    #pragma unroll
    for (int m = 1; m < 8; m <<= 1)
        #pragma unroll
        for (int i = 0; i < 8; i++)
            p[i] += __shfl_xor_sync(0xffffffffu, p[i], m);

    float ex[8];
    #pragma unroll
    for (int i = 0; i < 8; i++) ex[i] = __expf(p[i] * 0.125f);   // / sqrt(64)

    // denominator: one lane per (edge, head) in each 8-lane group
    #pragma unroll
    for (int i = 0; i < 8; i++)
        if ((tx & 7) == i)
            atomicAdd(&g_denom[2 * dstS[ty * 8 + i] + h], ex[i]);

    // unnormalized aggregation: out[dst] += ex_h * (v[src] + e)
    #pragma unroll
    for (int i = 0; i < 8; i++) {
        int el = ty * 8 + i;
        int s = srcS[el], d = dstS[el];
        float4 v0 = *(const float4*)&g_v[s * 128 + col0];
        float4 v1 = *(const float4*)&g_v[s * 128 + col0 + 4];
        float w = ex[i];
        float* dp = &out[(size_t)d * 128 + col0];
        atomicAdd(dp + 0, w * (v0.x + acc[i][0]));
        atomicAdd(dp + 1, w * (v0.y + acc[i][1]));
        atomicAdd(dp + 2, w * (v0.z + acc[i][2]));
        atomicAdd(dp + 3, w * (v0.w + acc[i][3]));
        atomicAdd(dp + 4, w * (v1.x + acc[i][4]));
        atomicAdd(dp + 5, w * (v1.y + acc[i][5]));
        atomicAdd(dp + 6, w * (v1.z + acc[i][6]));
        atomicAdd(dp + 7, w * (v1.w + acc[i][7]));
    }
}

// ---------------------------------------------------------------------------
// K3: out = out / (denom + 1e-16) + skip
// ---------------------------------------------------------------------------
__global__ void finalize_kernel(float* __restrict__ out) {
    int idx = blockIdx.x * blockDim.x + threadIdx.x;
    int stride = gridDim.x * blockDim.x;
    const int total4 = NN * OUTD / 4;
    for (int i = idx; i < total4; i += stride) {
        int n = i >> 5;            // 32 float4 per node
        int h = (i >> 4) & 1;      // float4s 0..15 -> head0, 16..31 -> head1
        float inv = 1.0f / (g_denom[2 * n + h] + 1e-16f);
        float4 o  = ((float4*)out)[i];
        float4 sk = ((const float4*)g_skip)[i];
        o.x = o.x * inv + sk.x;
        o.y = o.y * inv + sk.y;
        o.z = o.z * inv + sk.z;
        o.w = o.w * inv + sk.w;
        ((float4*)out)[i] = o;
    }
}

// ---------------------------------------------------------------------------
extern "C" void kernel_launch(void* const* d_in, const int* in_sizes, int n_in,
                              void* d_out, int out_size)
{
    const float* x     = (const float*)d_in[0];
    const float* lu    = (const float*)d_in[1];
    const float* t     = (const float*)d_in[2];
    const float* msg   = (const float*)d_in[3];
    const int*   ei    = (const int*)d_in[4];     // int32! (JAX x64 disabled)
    const float* Wtime = (const float*)d_in[5];
    const float* btime = (const float*)d_in[6];
    const float* Wq = (const float*)d_in[7];  const float* bq = (const float*)d_in[8];
    const float* Wk = (const float*)d_in[9];  const float* bk = (const float*)d_in[10];
    const float* Wv = (const float*)d_in[11]; const float* bv = (const float*)d_in[12];
    const float* We = (const float*)d_in[13]; const float* be = (const float*)d_in[14];
    const float* Wsk = (const float*)d_in[15]; const float* bsk = (const float*)d_in[16];
    float* out = (float*)d_out;

    const int PROJ_SMEM = (128 * 128 + 32 * 128) * sizeof(float);   // 80 KB
    const int EDGE_SMEM = (2 * EDIMK * 128) * sizeof(float);        // 96 KB
    cudaFuncSetAttribute(proj_kernel, cudaFuncAttributeMaxDynamicSharedMemorySize, PROJ_SMEM);
    cudaFuncSetAttribute(edge_kernel, cudaFuncAttributeMaxDynamicSharedMemorySize, EDGE_SMEM);

    zero_kernel<<<512, 256>>>(out);

    dim3 pgrid((NN + 127) / 128, 4);
    proj_kernel<<<pgrid, 256, PROJ_SMEM>>>(x, Wq, bq, Wk, bk, Wv, bv, Wsk, bsk);

    edge_kernel<<<EE / 128, 256, EDGE_SMEM>>>(lu, t, msg, ei, Wtime, btime, We, be, out);

    finalize_kernel<<<512, 256>>>(out);
}

// round 5
// speedup vs baseline: 1.2502x; 1.2502x over previous
#include <cuda_runtime.h>
#include <math.h>

#define NN   50000
#define EE   800000
#define IND  128
#define OUTD 128
#define EDIMK 96

// ---- scratch (static device arrays; no allocation) ----
__device__ float g_q[NN * OUTD];
__device__ float g_k[NN * OUTD];
__device__ float g_v[NN * OUTD];
__device__ float g_skip[NN * OUTD];
__device__ float g_denom[NN * 2];

extern __shared__ float smem_dyn[];

// ---------------------------------------------------------------------------
// K0: zero d_out and denominators
// ---------------------------------------------------------------------------
__global__ void zero_kernel(float* __restrict__ out) {
    int idx = blockIdx.x * blockDim.x + threadIdx.x;
    int stride = gridDim.x * blockDim.x;
    const int total4 = NN * OUTD / 4;
    for (int i = idx; i < total4; i += stride)
        ((float4*)out)[i] = make_float4(0.f, 0.f, 0.f, 0.f);
    for (int i = idx; i < NN * 2; i += stride)
        g_denom[i] = 0.f;
}

// ---------------------------------------------------------------------------
// K1: node projections  q/k/v/skip = x @ W + b
// ---------------------------------------------------------------------------
__global__ __launch_bounds__(256, 2) void proj_kernel(
    const float* __restrict__ x,
    const float* __restrict__ Wq, const float* __restrict__ bq,
    const float* __restrict__ Wk, const float* __restrict__ bk,
    const float* __restrict__ Wv, const float* __restrict__ bv,
    const float* __restrict__ Wsk, const float* __restrict__ bsk)
{
    float* ws  = smem_dyn;               // [128][128]  W tile (full)
    float* xsT = smem_dyn + 128 * 128;   // [32][128]   x chunk, transposed

    const float* W; const float* bias; float* out;
    switch (blockIdx.y) {
        case 0:  W = Wq;  bias = bq;  out = g_q;    break;
        case 1:  W = Wk;  bias = bk;  out = g_k;    break;
        case 2:  W = Wv;  bias = bv;  out = g_v;    break;
        default: W = Wsk; bias = bsk; out = g_skip; break;
    }

    int tid  = threadIdx.x;
    int row0 = blockIdx.x * 128;

    for (int i = tid; i < 128 * 128 / 4; i += 256)
        ((float4*)ws)[i] = ((const float4*)W)[i];

    int tx = tid & 15, ty = tid >> 4;
    int col0 = tx * 8;

    float acc[8][8];
    #pragma unroll
    for (int i = 0; i < 8; i++)
        #pragma unroll
        for (int j = 0; j < 8; j++) acc[i][j] = 0.f;

    for (int kb = 0; kb < 4; kb++) {
        __syncthreads();
        for (int i = tid; i < 128 * 8; i += 256) {
            int r  = i >> 3;
            int c4 = (i & 7) * 4;
            float4 xv = make_float4(0.f, 0.f, 0.f, 0.f);
            int gr = row0 + r;
            if (gr < NN)
                xv = *(const float4*)&x[(size_t)gr * IND + kb * 32 + c4];
            xsT[(c4 + 0) * 128 + r] = xv.x;
            xsT[(c4 + 1) * 128 + r] = xv.y;
            xsT[(c4 + 2) * 128 + r] = xv.z;
            xsT[(c4 + 3) * 128 + r] = xv.w;
        }
        __syncthreads();
        #pragma unroll
        for (int k = 0; k < 32; k++) {
            float a[8], b[8];
            *(float4*)&a[0] = *(float4*)&xsT[k * 128 + ty * 8];
            *(float4*)&a[4] = *(float4*)&xsT[k * 128 + ty * 8 + 4];
            *(float4*)&b[0] = *(float4*)&ws[(kb * 32 + k) * 128 + col0];
            *(float4*)&b[4] = *(float4*)&ws[(kb * 32 + k) * 128 + col0 + 4];
            #pragma unroll
            for (int i = 0; i < 8; i++)
                #pragma unroll
                for (int j = 0; j < 8; j++)
                    acc[i][j] += a[i] * b[j];
        }
    }

    float bb[8];
    #pragma unroll
    for (int j = 0; j < 8; j++) bb[j] = bias[col0 + j];

    #pragma unroll
    for (int i = 0; i < 8; i++) {
        int gr = row0 + ty * 8 + i;
        if (gr < NN) {
            float4 o0, o1;
            o0.x = acc[i][0] + bb[0]; o0.y = acc[i][1] + bb[1];
            o0.z = acc[i][2] + bb[2]; o0.w = acc[i][3] + bb[3];
            o1.x = acc[i][4] + bb[4]; o1.y = acc[i][5] + bb[5];
            o1.z = acc[i][6] + bb[6]; o1.w = acc[i][7] + bb[7];
            *(float4*)&out[(size_t)gr * OUTD + col0]     = o0;
            *(float4*)&out[(size_t)gr * OUTD + col0 + 4] = o1;
        }
    }
}

// ---------------------------------------------------------------------------
// K2: fused edge kernel. 128 edges per block, 256 threads.
// ---------------------------------------------------------------------------
__global__ __launch_bounds__(256, 2) void edge_kernel(
    const float* __restrict__ lu, const float* __restrict__ tt,
    const float* __restrict__ msg, const int* __restrict__ ei,
    const float* __restrict__ Wtime, const float* __restrict__ btime,
    const float* __restrict__ We, const float* __restrict__ be,
    float* __restrict__ out)
{
    float* attrT = smem_dyn;                 // [96][128]
    float* wes   = smem_dyn + EDIMK * 128;   // [96][128]
    __shared__ int   srcS[128];
    __shared__ int   dstS[128];
    __shared__ float relS[128];

    int tid = threadIdx.x;
    int eb  = blockIdx.x * 128;

    if (tid < 128) {
        int e = eb + tid;
        int s = ei[e];            // int32 edge_index
        srcS[tid] = s;
        dstS[tid] = ei[EE + e];
        relS[tid] = lu[s] - tt[e];
    }
    for (int i = tid; i < EDIMK * 128 / 4; i += 256)
        ((float4*)wes)[i] = ((const float4*)We)[i];
    for (int i = tid; i < 128 * 16; i += 256) {
        int e  = i >> 4;
        int c4 = (i & 15) * 4;
        float4 m = *(const float4*)&msg[(size_t)(eb + e) * 64 + c4];
        attrT[(32 + c4 + 0) * 128 + e] = m.x;
        attrT[(32 + c4 + 1) * 128 + e] = m.y;
        attrT[(32 + c4 + 2) * 128 + e] = m.z;
        attrT[(32 + c4 + 3) * 128 + e] = m.w;
    }
    __syncthreads();
    for (int i = tid; i < 32 * 128; i += 256) {
        int d = i >> 7;
        int e = i & 127;
        attrT[d * 128 + e] = __cosf(relS[e] * Wtime[d] + btime[d]);
    }
    __syncthreads();

    int tx = tid & 15, ty = tid >> 4;
    int col0 = tx * 8;
    int h = col0 >> 6;

    float acc[8][8];
    #pragma unroll
    for (int j = 0; j < 8; j++) {
        float bb = be[col0 + j];
        #pragma unroll
        for (int i = 0; i < 8; i++) acc[i][j] = bb;
    }
    for (int k = 0; k < EDIMK; k++) {
        float a[8], b[8];
        *(float4*)&a[0] = *(float4*)&attrT[k * 128 + ty * 8];
        *(float4*)&a[4] = *(float4*)&attrT[k * 128 + ty * 8 + 4];
        *(float4*)&b[0] = *(float4*)&wes[k * 128 + col0];
        *(float4*)&b[4] = *(float4*)&wes[k * 128 + col0 + 4];
        #pragma unroll
        for (int i = 0; i < 8; i++)
            #pragma unroll
            for (int j = 0; j < 8; j++)
                acc[i][j] += a[i] * b[j];
    }

    float p[8];
    #pragma unroll
    for (int i = 0; i < 8; i++) {
        int el = ty * 8 + i;
        int s = srcS[el], d = dstS[el];
        float4 q0 = *(const float4*)&g_q[d * 128 + col0];
        float4 q1 = *(const float4*)&g_q[d * 128 + col0 + 4];
        float4 k0 = *(const float4*)&g_k[s * 128 + col0];
        float4 k1 = *(const float4*)&g_k[s * 128 + col0 + 4];
        p[i] = q0.x * (k0.x + acc[i][0]) + q0.y * (k0.y + acc[i][1])
             + q0.z * (k0.z + acc[i][2]) + q0.w * (k0.w + acc[i][3])
             + q1.x * (k1.x + acc[i][4]) + q1.y * (k1.y + acc[i][5])
             + q1.z * (k1.z + acc[i][6]) + q1.w * (k1.w + acc[i][7]);
    }
    #pragma unroll
    for (int m = 1; m < 8; m <<= 1)
        #pragma unroll
        for (int i = 0; i < 8; i++)
            p[i] += __shfl_xor_sync(0xffffffffu, p[i], m);

    float ex[8];
    #pragma unroll
    for (int i = 0; i < 8; i++) ex[i] = __expf(p[i] * 0.125f);   // / sqrt(64)

    #pragma unroll
    for (int i = 0; i < 8; i++)
        if ((tx & 7) == i)
            atomicAdd(&g_denom[2 * dstS[ty * 8 + i] + h], ex[i]);

    // unnormalized aggregation: out[dst] += ex_h * (v[src] + e)
    // 128-bit vector RED (sm_90+ atomicAdd(float4*) intrinsic)
    #pragma unroll
    for (int i = 0; i < 8; i++) {
        int el = ty * 8 + i;
        int s = srcS[el], d = dstS[el];
        float4 v0 = *(const float4*)&g_v[s * 128 + col0];
        float4 v1 = *(const float4*)&g_v[s * 128 + col0 + 4];
        float w = ex[i];
        float4 r0, r1;
        r0.x = w * (v0.x + acc[i][0]);
        r0.y = w * (v0.y + acc[i][1]);
        r0.z = w * (v0.z + acc[i][2]);
        r0.w = w * (v0.w + acc[i][3]);
        r1.x = w * (v1.x + acc[i][4]);
        r1.y = w * (v1.y + acc[i][5]);
        r1.z = w * (v1.z + acc[i][6]);
        r1.w = w * (v1.w + acc[i][7]);
        float4* dp = (float4*)&out[(size_t)d * 128 + col0];
        atomicAdd(dp, r0);
        atomicAdd(dp + 1, r1);
    }
}

// ---------------------------------------------------------------------------
// K3: out = out / (denom + 1e-16) + skip
// ---------------------------------------------------------------------------
__global__ void finalize_kernel(float* __restrict__ out) {
    int idx = blockIdx.x * blockDim.x + threadIdx.x;
    int stride = gridDim.x * blockDim.x;
    const int total4 = NN * OUTD / 4;
    for (int i = idx; i < total4; i += stride) {
        int n = i >> 5;
        int h = (i >> 4) & 1;
        float inv = 1.0f / (g_denom[2 * n + h] + 1e-16f);
        float4 o  = ((float4*)out)[i];
        float4 sk = ((const float4*)g_skip)[i];
        o.x = o.x * inv + sk.x;
        o.y = o.y * inv + sk.y;
        o.z = o.z * inv + sk.z;
        o.w = o.w * inv + sk.w;
        ((float4*)out)[i] = o;
    }
}

// ---------------------------------------------------------------------------
extern "C" void kernel_launch(void* const* d_in, const int* in_sizes, int n_in,
                              void* d_out, int out_size)
{
    const float* x     = (const float*)d_in[0];
    const float* lu    = (const float*)d_in[1];
    const float* t     = (const float*)d_in[2];
    const float* msg   = (const float*)d_in[3];
    const int*   ei    = (const int*)d_in[4];     // int32 (JAX x64 disabled)
    const float* Wtime = (const float*)d_in[5];
    const float* btime = (const float*)d_in[6];
    const float* Wq = (const float*)d_in[7];  const float* bq = (const float*)d_in[8];
    const float* Wk = (const float*)d_in[9];  const float* bk = (const float*)d_in[10];
    const float* Wv = (const float*)d_in[11]; const float* bv = (const float*)d_in[12];
    const float* We = (const float*)d_in[13]; const float* be = (const float*)d_in[14];
    const float* Wsk = (const float*)d_in[15]; const float* bsk = (const float*)d_in[16];
    float* out = (float*)d_out;

    const int PROJ_SMEM = (128 * 128 + 32 * 128) * sizeof(float);   // 80 KB
    const int EDGE_SMEM = (2 * EDIMK * 128) * sizeof(float);        // 96 KB
    cudaFuncSetAttribute(proj_kernel, cudaFuncAttributeMaxDynamicSharedMemorySize, PROJ_SMEM);
    cudaFuncSetAttribute(edge_kernel, cudaFuncAttributeMaxDynamicSharedMemorySize, EDGE_SMEM);

    zero_kernel<<<512, 256>>>(out);

    dim3 pgrid((NN + 127) / 128, 4);
    proj_kernel<<<pgrid, 256, PROJ_SMEM>>>(x, Wq, bq, Wk, bk, Wv, bv, Wsk, bsk);

    edge_kernel<<<EE / 128, 256, EDGE_SMEM>>>(lu, t, msg, ei, Wtime, btime, We, be, out);

    finalize_kernel<<<512, 256>>>(out);
}

// round 7
// speedup vs baseline: 1.5656x; 1.2523x over previous
#include <cuda_runtime.h>
#include <math.h>
#include <stdint.h>

#define NN   50000
#define EE   800000
#define IND  128
#define OUTD 128
#define TILES_PER_CTA 5
#define NTILES (EE / 128)                 // 6250
#define NCTA   (NTILES / TILES_PER_CTA)   // 1250

#define A_STRIDE 100    // attr tile row stride (floats): conflict-free A frags
#define B_STRIDE 136    // W_e row stride (floats): conflict-free B frags
#define E_STRIDE 66     // estage row stride (floats): float2-aligned

// ---- scratch (static device arrays; no allocation) ----
__device__ float g_q[NN * OUTD];
__device__ float g_k[NN * OUTD];
__device__ float g_v[NN * OUTD];
__device__ float g_skip[NN * OUTD];
__device__ float g_denom[NN * 2];

extern __shared__ float smem_dyn[];

__device__ __forceinline__ float to_tf32(float x) {
    float r; asm("cvt.rna.tf32.f32 %0, %1;" : "=f"(r) : "f"(x)); return r;
}
__device__ __forceinline__ void mma_tf32(float* d, const uint32_t* a, const uint32_t* b) {
    asm volatile("mma.sync.aligned.m16n8k8.row.col.f32.tf32.tf32.f32 "
                 "{%0,%1,%2,%3}, {%4,%5,%6,%7}, {%8,%9}, {%0,%1,%2,%3};"
                 : "+f"(d[0]), "+f"(d[1]), "+f"(d[2]), "+f"(d[3])
                 : "r"(a[0]), "r"(a[1]), "r"(a[2]), "r"(a[3]), "r"(b[0]), "r"(b[1]));
}

// ---------------------------------------------------------------------------
// K0: zero d_out and denominators
// ---------------------------------------------------------------------------
__global__ void zero_kernel(float* __restrict__ out) {
    int idx = blockIdx.x * blockDim.x + threadIdx.x;
    int stride = gridDim.x * blockDim.x;
    const int total4 = NN * OUTD / 4;
    for (int i = idx; i < total4; i += stride)
        ((float4*)out)[i] = make_float4(0.f, 0.f, 0.f, 0.f);
    for (int i = idx; i < NN * 2; i += stride)
        g_denom[i] = 0.f;
}

// ---------------------------------------------------------------------------
// K1: node projections  q/k/v/skip = x @ W + b   (fp32 — proven)
// ---------------------------------------------------------------------------
__global__ __launch_bounds__(256, 2) void proj_kernel(
    const float* __restrict__ x,
    const float* __restrict__ Wq, const float* __restrict__ bq,
    const float* __restrict__ Wk, const float* __restrict__ bk,
    const float* __restrict__ Wv, const float* __restrict__ bv,
    const float* __restrict__ Wsk, const float* __restrict__ bsk)
{
    float* ws  = smem_dyn;
    float* xsT = smem_dyn + 128 * 128;

    const float* W; const float* bias; float* out;
    switch (blockIdx.y) {
        case 0:  W = Wq;  bias = bq;  out = g_q;    break;
        case 1:  W = Wk;  bias = bk;  out = g_k;    break;
        case 2:  W = Wv;  bias = bv;  out = g_v;    break;
        default: W = Wsk; bias = bsk; out = g_skip; break;
    }

    int tid  = threadIdx.x;
    int row0 = blockIdx.x * 128;

    for (int i = tid; i < 128 * 128 / 4; i += 256)
        ((float4*)ws)[i] = ((const float4*)W)[i];

    int tx = tid & 15, ty = tid >> 4;
    int col0 = tx * 8;

    float acc[8][8];
    #pragma unroll
    for (int i = 0; i < 8; i++)
        #pragma unroll
        for (int j = 0; j < 8; j++) acc[i][j] = 0.f;

    for (int kb = 0; kb < 4; kb++) {
        __syncthreads();
        for (int i = tid; i < 128 * 8; i += 256) {
            int r  = i >> 3;
            int c4 = (i & 7) * 4;
            float4 xv = make_float4(0.f, 0.f, 0.f, 0.f);
            int gr = row0 + r;
            if (gr < NN)
                xv = *(const float4*)&x[(size_t)gr * IND + kb * 32 + c4];
            xsT[(c4 + 0) * 128 + r] = xv.x;
            xsT[(c4 + 1) * 128 + r] = xv.y;
            xsT[(c4 + 2) * 128 + r] = xv.z;
            xsT[(c4 + 3) * 128 + r] = xv.w;
        }
        __syncthreads();
        #pragma unroll
        for (int k = 0; k < 32; k++) {
            float a[8], b[8];
            *(float4*)&a[0] = *(float4*)&xsT[k * 128 + ty * 8];
            *(float4*)&a[4] = *(float4*)&xsT[k * 128 + ty * 8 + 4];
            *(float4*)&b[0] = *(float4*)&ws[(kb * 32 + k) * 128 + col0];
            *(float4*)&b[4] = *(float4*)&ws[(kb * 32 + k) * 128 + col0 + 4];
            #pragma unroll
            for (int i = 0; i < 8; i++)
                #pragma unroll
                for (int j = 0; j < 8; j++)
                    acc[i][j] += a[i] * b[j];
        }
    }

    float bb[8];
    #pragma unroll
    for (int j = 0; j < 8; j++) bb[j] = bias[col0 + j];

    #pragma unroll
    for (int i = 0; i < 8; i++) {
        int gr = row0 + ty * 8 + i;
        if (gr < NN) {
            float4 o0, o1;
            o0.x = acc[i][0] + bb[0]; o0.y = acc[i][1] + bb[1];
            o0.z = acc[i][2] + bb[2]; o0.w = acc[i][3] + bb[3];
            o1.x = acc[i][4] + bb[4]; o1.y = acc[i][5] + bb[5];
            o1.z = acc[i][6] + bb[6]; o1.w = acc[i][7] + bb[7];
            *(float4*)&out[(size_t)gr * OUTD + col0]     = o0;
            *(float4*)&out[(size_t)gr * OUTD + col0 + 4] = o1;
        }
    }
}

// ---------------------------------------------------------------------------
// K2: edge kernel with mma.sync tf32 e-GEMM. 256 threads, 5 tiles of 128 edges.
// smem floats: srcS[128](as int), dstS[128](int), relS[128],
//              attrS [128][A_STRIDE]  (reused as estage [128][E_STRIDE]),
//              WeS   [96][B_STRIDE]
// ---------------------------------------------------------------------------
#define SM_ATTR  384
#define SM_WE    (SM_ATTR + 128 * A_STRIDE)
#define EDGE_SMEM_FLOATS (SM_WE + 96 * B_STRIDE)
#define EDGE_SMEM_BYTES  (EDGE_SMEM_FLOATS * 4)

__global__ __launch_bounds__(256, 2) void edge_kernel_mma(
    const float* __restrict__ lu, const float* __restrict__ tt,
    const float* __restrict__ msg, const int* __restrict__ ei,
    const float* __restrict__ Wtime, const float* __restrict__ btime,
    const float* __restrict__ We, const float* __restrict__ be,
    float* __restrict__ out)
{
    int*   srcS  = (int*)smem_dyn;
    int*   dstS  = (int*)smem_dyn + 128;
    float* relS  = smem_dyn + 256;
    float* attrS = smem_dyn + SM_ATTR;
    float* WeS   = smem_dyn + SM_WE;
    float* estage = attrS;                    // reuse after GEMM

    int tid = threadIdx.x;
    int w    = tid >> 5;                      // warp 0..7: M-strip w*16
    int lane = tid & 31;
    int g = lane >> 2, c = lane & 3;          // mma fragment coords

    // W_e -> smem, tf32-rounded (row-major [96][128] is already K-major over N)
    for (int i = tid; i < 96 * 128; i += 256) {
        int k = i >> 7, n = i & 127;
        WeS[k * B_STRIDE + n] = to_tf32(We[i]);
    }

    int tx = tid & 7;                         // consume: 8 lanes per edge
    int ey = tid >> 3;                        // edge group 0..31

    for (int t = 0; t < TILES_PER_CTA; t++) {
        int eb = (blockIdx.x * TILES_PER_CTA + t) * 128;

        __syncthreads();                       // estage/attrS free from prev iter
        if (tid < 128) {
            int e = eb + tid;
            int s = ei[e];
            srcS[tid] = s;
            dstS[tid] = ei[EE + e];
            relS[tid] = lu[s] - tt[e];
        }
        __syncthreads();

        // attr tile: k 0..31 = cos time-enc, k 32..95 = msg (tf32-rounded)
        for (int i = tid; i < 128 * 32; i += 256) {
            int row = i >> 5, k = i & 31;
            attrS[row * A_STRIDE + k] = to_tf32(__cosf(relS[row] * Wtime[k] + btime[k]));
        }
        for (int i = tid; i < 128 * 16; i += 256) {
            int row = i >> 4, j = i & 15;
            float4 m = ((const float4*)msg)[(size_t)(eb + row) * 16 + j];
            float4 cc;
            cc.x = to_tf32(m.x); cc.y = to_tf32(m.y); cc.z = to_tf32(m.z); cc.w = to_tf32(m.w);
            *(float4*)&attrS[row * A_STRIDE + 32 + j * 4] = cc;
        }
        __syncthreads();

        // ---- e-GEMM: warp w computes rows [w*16, w*16+16) x all 128 cols ----
        float acc[16][4];
        #pragma unroll
        for (int j = 0; j < 16; j++) {
            acc[j][0] = 0.f; acc[j][1] = 0.f; acc[j][2] = 0.f; acc[j][3] = 0.f;
        }
        const float* ar0 = attrS + (w * 16 + g) * A_STRIDE;
        const float* ar1 = ar0 + 8 * A_STRIDE;
        #pragma unroll
        for (int kk = 0; kk < 12; kk++) {
            uint32_t af[4];
            af[0] = __float_as_uint(ar0[kk * 8 + c]);
            af[1] = __float_as_uint(ar1[kk * 8 + c]);
            af[2] = __float_as_uint(ar0[kk * 8 + c + 4]);
            af[3] = __float_as_uint(ar1[kk * 8 + c + 4]);
            const float* bk0 = WeS + (kk * 8 + c) * B_STRIDE + g;
            const float* bk4 = bk0 + 4 * B_STRIDE;
            #pragma unroll
            for (int j = 0; j < 16; j++) {
                uint32_t bf[2];
                bf[0] = __float_as_uint(bk0[j * 8]);
                bf[1] = __float_as_uint(bk4[j * 8]);
                mma_tf32(acc[j], af, bf);
            }
        }
        __syncthreads();                       // all A reads done -> estage may overwrite

        // ---- consume per head ----
        #pragma unroll
        for (int h = 0; h < 2; h++) {
            // stage this head's 64 cols into estage[128][E_STRIDE]
            #pragma unroll
            for (int jj = 0; jj < 8; jj++) {
                int j = h * 8 + jj;
                int colb = jj * 8 + 2 * c;
                float2 lo = make_float2(acc[j][0], acc[j][1]);
                float2 hi = make_float2(acc[j][2], acc[j][3]);
                *(float2*)&estage[(w * 16 + g) * E_STRIDE + colb]     = lo;
                *(float2*)&estage[(w * 16 + g + 8) * E_STRIDE + colb] = hi;
            }
            __syncthreads();

            float be8[8];
            #pragma unroll
            for (int j = 0; j < 8; j++) be8[j] = be[h * 64 + tx * 8 + j];

            #pragma unroll
            for (int m4 = 0; m4 < 4; m4++) {
                int el = ey + 32 * m4;
                int s = srcS[el], d = dstS[el];
                float ev[8];
                #pragma unroll
                for (int j = 0; j < 8; j++)
                    ev[j] = estage[el * E_STRIDE + tx * 8 + j] + be8[j];

                const float* qp = &g_q[(size_t)d * 128 + h * 64 + tx * 8];
                const float* kp = &g_k[(size_t)s * 128 + h * 64 + tx * 8];
                float4 q0 = *(const float4*)qp, q1 = *(const float4*)(qp + 4);
                float4 k0 = *(const float4*)kp, k1 = *(const float4*)(kp + 4);
                float p = q0.x * (k0.x + ev[0]) + q0.y * (k0.y + ev[1])
                        + q0.z * (k0.z + ev[2]) + q0.w * (k0.w + ev[3])
                        + q1.x * (k1.x + ev[4]) + q1.y * (k1.y + ev[5])
                        + q1.z * (k1.z + ev[6]) + q1.w * (k1.w + ev[7]);
                p += __shfl_xor_sync(0xffffffffu, p, 1);
                p += __shfl_xor_sync(0xffffffffu, p, 2);
                p += __shfl_xor_sync(0xffffffffu, p, 4);
                float ex = __expf(p * 0.125f);
                if (tx == 0) atomicAdd(&g_denom[2 * d + h], ex);

                const float* vp = &g_v[(size_t)s * 128 + h * 64 + tx * 8];
                float4 v0 = *(const float4*)vp, v1 = *(const float4*)(vp + 4);
                float4 r0, r1;
                r0.x = ex * (v0.x + ev[0]); r0.y = ex * (v0.y + ev[1]);
                r0.z = ex * (v0.z + ev[2]); r0.w = ex * (v0.w + ev[3]);
                r1.x = ex * (v1.x + ev[4]); r1.y = ex * (v1.y + ev[5]);
                r1.z = ex * (v1.z + ev[6]); r1.w = ex * (v1.w + ev[7]);
                float4* op = (float4*)&out[(size_t)d * 128 + h * 64 + tx * 8];
                atomicAdd(op, r0);
                atomicAdd(op + 1, r1);
            }
            __syncthreads();
        }
    }
}

// ---------------------------------------------------------------------------
// K3: out = out / (denom + 1e-16) + skip
// ---------------------------------------------------------------------------
__global__ void finalize_kernel(float* __restrict__ out) {
    int idx = blockIdx.x * blockDim.x + threadIdx.x;
    int stride = gridDim.x * blockDim.x;
    const int total4 = NN * OUTD / 4;
    for (int i = idx; i < total4; i += stride) {
        int n = i >> 5;
        int h = (i >> 4) & 1;
        float inv = 1.0f / (g_denom[2 * n + h] + 1e-16f);
        float4 o  = ((float4*)out)[i];
        float4 sk = ((const float4*)g_skip)[i];
        o.x = o.x * inv + sk.x;
        o.y = o.y * inv + sk.y;
        o.z = o.z * inv + sk.z;
        o.w = o.w * inv + sk.w;
        ((float4*)out)[i] = o;
    }
}

// ---------------------------------------------------------------------------
extern "C" void kernel_launch(void* const* d_in, const int* in_sizes, int n_in,
                              void* d_out, int out_size)
{
    const float* x     = (const float*)d_in[0];
    const float* lu    = (const float*)d_in[1];
    const float* t     = (const float*)d_in[2];
    const float* msg   = (const float*)d_in[3];
    const int*   ei    = (const int*)d_in[4];     // int32 (JAX x64 disabled)
    const float* Wtime = (const float*)d_in[5];
    const float* btime = (const float*)d_in[6];
    const float* Wq = (const float*)d_in[7];  const float* bq = (const float*)d_in[8];
    const float* Wk = (const float*)d_in[9];  const float* bk = (const float*)d_in[10];
    const float* Wv = (const float*)d_in[11]; const float* bv = (const float*)d_in[12];
    const float* We = (const float*)d_in[13]; const float* be = (const float*)d_in[14];
    const float* Wsk = (const float*)d_in[15]; const float* bsk = (const float*)d_in[16];
    float* out = (float*)d_out;

    const int PROJ_SMEM = (128 * 128 + 32 * 128) * sizeof(float);   // 80 KB
    cudaFuncSetAttribute(proj_kernel, cudaFuncAttributeMaxDynamicSharedMemorySize, PROJ_SMEM);
    cudaFuncSetAttribute(edge_kernel_mma, cudaFuncAttributeMaxDynamicSharedMemorySize, EDGE_SMEM_BYTES);

    zero_kernel<<<512, 256>>>(out);

    dim3 pgrid((NN + 127) / 128, 4);
    proj_kernel<<<pgrid, 256, PROJ_SMEM>>>(x, Wq, bq, Wk, bk, Wv, bv, Wsk, bsk);

    edge_kernel_mma<<<NCTA, 256, EDGE_SMEM_BYTES>>>(lu, t, msg, ei, Wtime, btime, We, be, out);

    finalize_kernel<<<512, 256>>>(out);
}

// round 8
// speedup vs baseline: 1.5968x; 1.0199x over previous
#include <cuda_runtime.h>
#include <math.h>
#include <stdint.h>

#define NN   50000
#define EE   800000
#define IND  128
#define OUTD 128
#define TILES_PER_CTA 5
#define NTILES (EE / 128)                 // 6250
#define NCTA   (NTILES / TILES_PER_CTA)   // 1250

#define A_STRIDE 100    // attr tile row stride (floats): conflict-free A frags
#define B_STRIDE 136    // W_e row stride (floats): conflict-free B frags
#define E_STRIDE 66     // estage row stride (floats): float2-aligned
#define XP_STRIDE 132   // proj x-tile row stride
#define WP_STRIDE 136   // proj W row stride

// ---- scratch (static device arrays; no allocation) ----
__device__ float g_q[NN * OUTD];
__device__ float g_k[NN * OUTD];
__device__ float g_v[NN * OUTD];
__device__ float g_skip[NN * OUTD];
__device__ float g_denom[NN * 2];

extern __shared__ float smem_dyn[];

__device__ __forceinline__ float to_tf32(float x) {
    float r; asm("cvt.rna.tf32.f32 %0, %1;" : "=f"(r) : "f"(x)); return r;
}
__device__ __forceinline__ void mma_tf32(float* d, const uint32_t* a, const uint32_t* b) {
    asm volatile("mma.sync.aligned.m16n8k8.row.col.f32.tf32.tf32.f32 "
                 "{%0,%1,%2,%3}, {%4,%5,%6,%7}, {%8,%9}, {%0,%1,%2,%3};"
                 : "+f"(d[0]), "+f"(d[1]), "+f"(d[2]), "+f"(d[3])
                 : "r"(a[0]), "r"(a[1]), "r"(a[2]), "r"(a[3]), "r"(b[0]), "r"(b[1]));
}

// ---------------------------------------------------------------------------
// K0: zero d_out and denominators
// ---------------------------------------------------------------------------
__global__ void zero_kernel(float* __restrict__ out) {
    int idx = blockIdx.x * blockDim.x + threadIdx.x;
    int stride = gridDim.x * blockDim.x;
    const int total4 = NN * OUTD / 4;
    for (int i = idx; i < total4; i += stride)
        ((float4*)out)[i] = make_float4(0.f, 0.f, 0.f, 0.f);
    for (int i = idx; i < NN * 2; i += stride)
        g_denom[i] = 0.f;
}

// ---------------------------------------------------------------------------
// K1: node projections via tf32 mma.sync. grid=(391, 4), 256 threads.
// smem: xs[128][XP_STRIDE], Ws[128][WP_STRIDE]   (~137 KB, 1 CTA/SM)
// ---------------------------------------------------------------------------
#define PROJ_SMEM_BYTES ((128 * XP_STRIDE + 128 * WP_STRIDE) * 4)

__global__ __launch_bounds__(256, 1) void proj_mma(
    const float* __restrict__ x,
    const float* __restrict__ Wq, const float* __restrict__ bq,
    const float* __restrict__ Wk, const float* __restrict__ bk,
    const float* __restrict__ Wv, const float* __restrict__ bv,
    const float* __restrict__ Wsk, const float* __restrict__ bsk)
{
    float* xs = smem_dyn;                     // [128][132]
    float* Ws = smem_dyn + 128 * XP_STRIDE;   // [128][136]

    const float* W; const float* bias; float* out;
    switch (blockIdx.y) {
        case 0:  W = Wq;  bias = bq;  out = g_q;    break;
        case 1:  W = Wk;  bias = bk;  out = g_k;    break;
        case 2:  W = Wv;  bias = bv;  out = g_v;    break;
        default: W = Wsk; bias = bsk; out = g_skip; break;
    }

    int tid  = threadIdx.x;
    int w    = tid >> 5;
    int lane = tid & 31;
    int g = lane >> 2, c = lane & 3;
    int row0 = blockIdx.x * 128;

    // W -> smem (tf32-rounded), [k][n]
    for (int i = tid; i < 128 * 32; i += 256) {
        int k = i >> 5, n4 = (i & 31) * 4;
        float4 v = ((const float4*)W)[i];
        v.x = to_tf32(v.x); v.y = to_tf32(v.y); v.z = to_tf32(v.z); v.w = to_tf32(v.w);
        *(float4*)&Ws[k * WP_STRIDE + n4] = v;
    }
    // x tile -> smem (tf32-rounded), zero-padded rows
    for (int i = tid; i < 128 * 32; i += 256) {
        int r = i >> 5, k4 = (i & 31) * 4;
        int gr = row0 + r;
        float4 v = make_float4(0.f, 0.f, 0.f, 0.f);
        if (gr < NN) v = ((const float4*)x)[(size_t)gr * 32 + (i & 31)];
        v.x = to_tf32(v.x); v.y = to_tf32(v.y); v.z = to_tf32(v.z); v.w = to_tf32(v.w);
        *(float4*)&xs[r * XP_STRIDE + k4] = v;
    }
    __syncthreads();

    float acc[16][4];
    #pragma unroll
    for (int j = 0; j < 16; j++) {
        acc[j][0] = 0.f; acc[j][1] = 0.f; acc[j][2] = 0.f; acc[j][3] = 0.f;
    }
    const float* ar0 = xs + (w * 16 + g) * XP_STRIDE;
    const float* ar1 = ar0 + 8 * XP_STRIDE;
    #pragma unroll
    for (int kk = 0; kk < 16; kk++) {
        uint32_t af[4];
        af[0] = __float_as_uint(ar0[kk * 8 + c]);
        af[1] = __float_as_uint(ar1[kk * 8 + c]);
        af[2] = __float_as_uint(ar0[kk * 8 + c + 4]);
        af[3] = __float_as_uint(ar1[kk * 8 + c + 4]);
        const float* bk0 = Ws + (kk * 8 + c) * WP_STRIDE + g;
        const float* bk4 = bk0 + 4 * WP_STRIDE;
        #pragma unroll
        for (int j = 0; j < 16; j++) {
            uint32_t bf[2];
            bf[0] = __float_as_uint(bk0[j * 8]);
            bf[1] = __float_as_uint(bk4[j * 8]);
            mma_tf32(acc[j], af, bf);
        }
    }

    // epilogue: rows w*16+g and +8, cols j*8+2c (+1), add bias
    int r0 = row0 + w * 16 + g;
    int r1 = r0 + 8;
    #pragma unroll
    for (int j = 0; j < 16; j++) {
        int col = j * 8 + 2 * c;
        float b0 = bias[col], b1 = bias[col + 1];
        if (r0 < NN) {
            float2 o = make_float2(acc[j][0] + b0, acc[j][1] + b1);
            *(float2*)&out[(size_t)r0 * 128 + col] = o;
        }
        if (r1 < NN) {
            float2 o = make_float2(acc[j][2] + b0, acc[j][3] + b1);
            *(float2*)&out[(size_t)r1 * 128 + col] = o;
        }
    }
}

// ---------------------------------------------------------------------------
// K2: edge kernel with mma.sync tf32 e-GEMM (unchanged from R7 — proven)
// ---------------------------------------------------------------------------
#define SM_ATTR  384
#define SM_WE    (SM_ATTR + 128 * A_STRIDE)
#define EDGE_SMEM_FLOATS (SM_WE + 96 * B_STRIDE)
#define EDGE_SMEM_BYTES  (EDGE_SMEM_FLOATS * 4)

__global__ __launch_bounds__(256, 2) void edge_kernel_mma(
    const float* __restrict__ lu, const float* __restrict__ tt,
    const float* __restrict__ msg, const int* __restrict__ ei,
    const float* __restrict__ Wtime, const float* __restrict__ btime,
    const float* __restrict__ We, const float* __restrict__ be,
    float* __restrict__ out)
{
    int*   srcS  = (int*)smem_dyn;
    int*   dstS  = (int*)smem_dyn + 128;
    float* relS  = smem_dyn + 256;
    float* attrS = smem_dyn + SM_ATTR;
    float* WeS   = smem_dyn + SM_WE;
    float* estage = attrS;

    int tid = threadIdx.x;
    int w    = tid >> 5;
    int lane = tid & 31;
    int g = lane >> 2, c = lane & 3;

    for (int i = tid; i < 96 * 128; i += 256) {
        int k = i >> 7, n = i & 127;
        WeS[k * B_STRIDE + n] = to_tf32(We[i]);
    }

    int tx = tid & 7;
    int ey = tid >> 3;

    for (int t = 0; t < TILES_PER_CTA; t++) {
        int eb = (blockIdx.x * TILES_PER_CTA + t) * 128;

        __syncthreads();
        if (tid < 128) {
            int e = eb + tid;
            int s = ei[e];
            srcS[tid] = s;
            dstS[tid] = ei[EE + e];
            relS[tid] = lu[s] - tt[e];
        }
        __syncthreads();

        for (int i = tid; i < 128 * 32; i += 256) {
            int row = i >> 5, k = i & 31;
            attrS[row * A_STRIDE + k] = to_tf32(__cosf(relS[row] * Wtime[k] + btime[k]));
        }
        for (int i = tid; i < 128 * 16; i += 256) {
            int row = i >> 4, j = i & 15;
            float4 m = ((const float4*)msg)[(size_t)(eb + row) * 16 + j];
            float4 cc;
            cc.x = to_tf32(m.x); cc.y = to_tf32(m.y); cc.z = to_tf32(m.z); cc.w = to_tf32(m.w);
            *(float4*)&attrS[row * A_STRIDE + 32 + j * 4] = cc;
        }
        __syncthreads();

        float acc[16][4];
        #pragma unroll
        for (int j = 0; j < 16; j++) {
            acc[j][0] = 0.f; acc[j][1] = 0.f; acc[j][2] = 0.f; acc[j][3] = 0.f;
        }
        const float* ar0 = attrS + (w * 16 + g) * A_STRIDE;
        const float* ar1 = ar0 + 8 * A_STRIDE;
        #pragma unroll
        for (int kk = 0; kk < 12; kk++) {
            uint32_t af[4];
            af[0] = __float_as_uint(ar0[kk * 8 + c]);
            af[1] = __float_as_uint(ar1[kk * 8 + c]);
            af[2] = __float_as_uint(ar0[kk * 8 + c + 4]);
            af[3] = __float_as_uint(ar1[kk * 8 + c + 4]);
            const float* bk0 = WeS + (kk * 8 + c) * B_STRIDE + g;
            const float* bk4 = bk0 + 4 * B_STRIDE;
            #pragma unroll
            for (int j = 0; j < 16; j++) {
                uint32_t bf[2];
                bf[0] = __float_as_uint(bk0[j * 8]);
                bf[1] = __float_as_uint(bk4[j * 8]);
                mma_tf32(acc[j], af, bf);
            }
        }
        __syncthreads();

        #pragma unroll
        for (int h = 0; h < 2; h++) {
            #pragma unroll
            for (int jj = 0; jj < 8; jj++) {
                int j = h * 8 + jj;
                int colb = jj * 8 + 2 * c;
                float2 lo = make_float2(acc[j][0], acc[j][1]);
                float2 hi = make_float2(acc[j][2], acc[j][3]);
                *(float2*)&estage[(w * 16 + g) * E_STRIDE + colb]     = lo;
                *(float2*)&estage[(w * 16 + g + 8) * E_STRIDE + colb] = hi;
            }
            __syncthreads();

            float be8[8];
            #pragma unroll
            for (int j = 0; j < 8; j++) be8[j] = be[h * 64 + tx * 8 + j];

            #pragma unroll
            for (int m4 = 0; m4 < 4; m4++) {
                int el = ey + 32 * m4;
                int s = srcS[el], d = dstS[el];
                float ev[8];
                #pragma unroll
                for (int j = 0; j < 8; j++)
                    ev[j] = estage[el * E_STRIDE + tx * 8 + j] + be8[j];

                const float* qp = &g_q[(size_t)d * 128 + h * 64 + tx * 8];
                const float* kp = &g_k[(size_t)s * 128 + h * 64 + tx * 8];
                float4 q0 = *(const float4*)qp, q1 = *(const float4*)(qp + 4);
                float4 k0 = *(const float4*)kp, k1 = *(const float4*)(kp + 4);
                float p = q0.x * (k0.x + ev[0]) + q0.y * (k0.y + ev[1])
                        + q0.z * (k0.z + ev[2]) + q0.w * (k0.w + ev[3])
                        + q1.x * (k1.x + ev[4]) + q1.y * (k1.y + ev[5])
                        + q1.z * (k1.z + ev[6]) + q1.w * (k1.w + ev[7]);
                p += __shfl_xor_sync(0xffffffffu, p, 1);
                p += __shfl_xor_sync(0xffffffffu, p, 2);
                p += __shfl_xor_sync(0xffffffffu, p, 4);
                float ex = __expf(p * 0.125f);
                if (tx == 0) atomicAdd(&g_denom[2 * d + h], ex);

                const float* vp = &g_v[(size_t)s * 128 + h * 64 + tx * 8];
                float4 v0 = *(const float4*)vp, v1 = *(const float4*)(vp + 4);
                float4 r0, r1;
                r0.x = ex * (v0.x + ev[0]); r0.y = ex * (v0.y + ev[1]);
                r0.z = ex * (v0.z + ev[2]); r0.w = ex * (v0.w + ev[3]);
                r1.x = ex * (v1.x + ev[4]); r1.y = ex * (v1.y + ev[5]);
                r1.z = ex * (v1.z + ev[6]); r1.w = ex * (v1.w + ev[7]);
                float4* op = (float4*)&out[(size_t)d * 128 + h * 64 + tx * 8];
                atomicAdd(op, r0);
                atomicAdd(op + 1, r1);
            }
            __syncthreads();
        }
    }
}

// ---------------------------------------------------------------------------
// K3: out = out / (denom + 1e-16) + skip
// ---------------------------------------------------------------------------
__global__ void finalize_kernel(float* __restrict__ out) {
    int idx = blockIdx.x * blockDim.x + threadIdx.x;
    int stride = gridDim.x * blockDim.x;
    const int total4 = NN * OUTD / 4;
    for (int i = idx; i < total4; i += stride) {
        int n = i >> 5;
        int h = (i >> 4) & 1;
        float inv = 1.0f / (g_denom[2 * n + h] + 1e-16f);
        float4 o  = ((float4*)out)[i];
        float4 sk = ((const float4*)g_skip)[i];
        o.x = o.x * inv + sk.x;
        o.y = o.y * inv + sk.y;
        o.z = o.z * inv + sk.z;
        o.w = o.w * inv + sk.w;
        ((float4*)out)[i] = o;
    }
}

// ---------------------------------------------------------------------------
extern "C" void kernel_launch(void* const* d_in, const int* in_sizes, int n_in,
                              void* d_out, int out_size)
{
    const float* x     = (const float*)d_in[0];
    const float* lu    = (const float*)d_in[1];
    const float* t     = (const float*)d_in[2];
    const float* msg   = (const float*)d_in[3];
    const int*   ei    = (const int*)d_in[4];     // int32 (JAX x64 disabled)
    const float* Wtime = (const float*)d_in[5];
    const float* btime = (const float*)d_in[6];
    const float* Wq = (const float*)d_in[7];  const float* bq = (const float*)d_in[8];
    const float* Wk = (const float*)d_in[9];  const float* bk = (const float*)d_in[10];
    const float* Wv = (const float*)d_in[11]; const float* bv = (const float*)d_in[12];
    const float* We = (const float*)d_in[13]; const float* be = (const float*)d_in[14];
    const float* Wsk = (const float*)d_in[15]; const float* bsk = (const float*)d_in[16];
    float* out = (float*)d_out;

    cudaFuncSetAttribute(proj_mma, cudaFuncAttributeMaxDynamicSharedMemorySize, PROJ_SMEM_BYTES);
    cudaFuncSetAttribute(edge_kernel_mma, cudaFuncAttributeMaxDynamicSharedMemorySize, EDGE_SMEM_BYTES);

    zero_kernel<<<512, 256>>>(out);

    dim3 pgrid((NN + 127) / 128, 4);
    proj_mma<<<pgrid, 256, PROJ_SMEM_BYTES>>>(x, Wq, bq, Wk, bk, Wv, bv, Wsk, bsk);

    edge_kernel_mma<<<NCTA, 256, EDGE_SMEM_BYTES>>>(lu, t, msg, ei, Wtime, btime, We, be, out);

    finalize_kernel<<<512, 256>>>(out);
}

// round 9
// speedup vs baseline: 1.7883x; 1.1199x over previous
#include <cuda_runtime.h>
#include <cuda_fp16.h>
#include <math.h>
#include <stdint.h>

#define NN   50000
#define EE   800000
#define IND  128
#define OUTD 128
#define TILES_PER_CTA 5
#define NTILES (EE / 128)                 // 6250
#define NCTA   (NTILES / TILES_PER_CTA)   // 1250

#define E_STRIDE 66     // estage row stride (floats)
#define XP_STRIDE 132   // proj x-tile row stride (floats)
#define WP_STRIDE 136   // proj W row stride (floats)
#define AH_STRIDE 52    // attr row stride in half2 words (96 halves = 48 + pad)
#define WH_STRIDE 136   // WeH k2-row stride in half2 words

// ---- scratch (static device arrays; no allocation) ----
__device__ float g_q[NN * OUTD];
__device__ float g_k[NN * OUTD];
__device__ float g_v[NN * OUTD];
__device__ float g_skip[NN * OUTD];
__device__ float g_denom[NN * 2];

extern __shared__ float smem_dyn[];

__device__ __forceinline__ float to_tf32(float x) {
    float r; asm("cvt.rna.tf32.f32 %0, %1;" : "=f"(r) : "f"(x)); return r;
}
__device__ __forceinline__ void mma_tf32(float* d, const uint32_t* a, const uint32_t* b) {
    asm volatile("mma.sync.aligned.m16n8k8.row.col.f32.tf32.tf32.f32 "
                 "{%0,%1,%2,%3}, {%4,%5,%6,%7}, {%8,%9}, {%0,%1,%2,%3};"
                 : "+f"(d[0]), "+f"(d[1]), "+f"(d[2]), "+f"(d[3])
                 : "r"(a[0]), "r"(a[1]), "r"(a[2]), "r"(a[3]), "r"(b[0]), "r"(b[1]));
}
__device__ __forceinline__ void mma_f16(float* d, const uint32_t* a, const uint32_t* b) {
    asm volatile("mma.sync.aligned.m16n8k16.row.col.f32.f16.f16.f32 "
                 "{%0,%1,%2,%3}, {%4,%5,%6,%7}, {%8,%9}, {%0,%1,%2,%3};"
                 : "+f"(d[0]), "+f"(d[1]), "+f"(d[2]), "+f"(d[3])
                 : "r"(a[0]), "r"(a[1]), "r"(a[2]), "r"(a[3]), "r"(b[0]), "r"(b[1]));
}
__device__ __forceinline__ uint32_t h2u(float a, float b) {
    __half2 h = __floats2half2_rn(a, b);
    return *(uint32_t*)&h;
}

// ---------------------------------------------------------------------------
// K0: zero d_out and denominators
// ---------------------------------------------------------------------------
__global__ void zero_kernel(float* __restrict__ out) {
    int idx = blockIdx.x * blockDim.x + threadIdx.x;
    int stride = gridDim.x * blockDim.x;
    const int total4 = NN * OUTD / 4;
    for (int i = idx; i < total4; i += stride)
        ((float4*)out)[i] = make_float4(0.f, 0.f, 0.f, 0.f);
    for (int i = idx; i < NN * 2; i += stride)
        g_denom[i] = 0.f;
}

// ---------------------------------------------------------------------------
// K1: node projections via tf32 mma.sync (unchanged — proven R8)
// ---------------------------------------------------------------------------
#define PROJ_SMEM_BYTES ((128 * XP_STRIDE + 128 * WP_STRIDE) * 4)

__global__ __launch_bounds__(256, 1) void proj_mma(
    const float* __restrict__ x,
    const float* __restrict__ Wq, const float* __restrict__ bq,
    const float* __restrict__ Wk, const float* __restrict__ bk,
    const float* __restrict__ Wv, const float* __restrict__ bv,
    const float* __restrict__ Wsk, const float* __restrict__ bsk)
{
    float* xs = smem_dyn;
    float* Ws = smem_dyn + 128 * XP_STRIDE;

    const float* W; const float* bias; float* out;
    switch (blockIdx.y) {
        case 0:  W = Wq;  bias = bq;  out = g_q;    break;
        case 1:  W = Wk;  bias = bk;  out = g_k;    break;
        case 2:  W = Wv;  bias = bv;  out = g_v;    break;
        default: W = Wsk; bias = bsk; out = g_skip; break;
    }

    int tid  = threadIdx.x;
    int w    = tid >> 5;
    int lane = tid & 31;
    int g = lane >> 2, c = lane & 3;
    int row0 = blockIdx.x * 128;

    for (int i = tid; i < 128 * 32; i += 256) {
        int k = i >> 5, n4 = (i & 31) * 4;
        float4 v = ((const float4*)W)[i];
        v.x = to_tf32(v.x); v.y = to_tf32(v.y); v.z = to_tf32(v.z); v.w = to_tf32(v.w);
        *(float4*)&Ws[k * WP_STRIDE + n4] = v;
    }
    for (int i = tid; i < 128 * 32; i += 256) {
        int r = i >> 5, k4 = (i & 31) * 4;
        int gr = row0 + r;
        float4 v = make_float4(0.f, 0.f, 0.f, 0.f);
        if (gr < NN) v = ((const float4*)x)[(size_t)gr * 32 + (i & 31)];
        v.x = to_tf32(v.x); v.y = to_tf32(v.y); v.z = to_tf32(v.z); v.w = to_tf32(v.w);
        *(float4*)&xs[r * XP_STRIDE + k4] = v;
    }
    __syncthreads();

    float acc[16][4];
    #pragma unroll
    for (int j = 0; j < 16; j++) {
        acc[j][0] = 0.f; acc[j][1] = 0.f; acc[j][2] = 0.f; acc[j][3] = 0.f;
    }
    const float* ar0 = xs + (w * 16 + g) * XP_STRIDE;
    const float* ar1 = ar0 + 8 * XP_STRIDE;
    #pragma unroll
    for (int kk = 0; kk < 16; kk++) {
        uint32_t af[4];
        af[0] = __float_as_uint(ar0[kk * 8 + c]);
        af[1] = __float_as_uint(ar1[kk * 8 + c]);
        af[2] = __float_as_uint(ar0[kk * 8 + c + 4]);
        af[3] = __float_as_uint(ar1[kk * 8 + c + 4]);
        const float* bk0 = Ws + (kk * 8 + c) * WP_STRIDE + g;
        const float* bk4 = bk0 + 4 * WP_STRIDE;
        #pragma unroll
        for (int j = 0; j < 16; j++) {
            uint32_t bf[2];
            bf[0] = __float_as_uint(bk0[j * 8]);
            bf[1] = __float_as_uint(bk4[j * 8]);
            mma_tf32(acc[j], af, bf);
        }
    }

    int r0 = row0 + w * 16 + g;
    int r1 = r0 + 8;
    #pragma unroll
    for (int j = 0; j < 16; j++) {
        int col = j * 8 + 2 * c;
        float b0 = bias[col], b1 = bias[col + 1];
        if (r0 < NN) {
            float2 o = make_float2(acc[j][0] + b0, acc[j][1] + b1);
            *(float2*)&out[(size_t)r0 * 128 + col] = o;
        }
        if (r1 < NN) {
            float2 o = make_float2(acc[j][2] + b0, acc[j][3] + b1);
            *(float2*)&out[(size_t)r1 * 128 + col] = o;
        }
    }
}

// ---------------------------------------------------------------------------
// K2: edge kernel — fp16 m16n8k16 e-GEMM, proven consume path.
// smem words: [0:128) srcS, [128:256) dstS, [256:384) relS,
//   [384:7040)  attrH  (half2 words, 128 rows x AH_STRIDE)
//   [7040:13568) WeH   (half2 words, 48 k2-rows x WH_STRIDE)
//   [13568:22016) estage (floats, 128 x E_STRIDE)
// total 22016 words = 88064 B  -> 2 CTA/SM
// ---------------------------------------------------------------------------
#define EDGE_SMEM_BYTES (22016 * 4)

__global__ __launch_bounds__(256, 2) void edge_kernel_mma(
    const float* __restrict__ lu, const float* __restrict__ tt,
    const float* __restrict__ msg, const int* __restrict__ ei,
    const float* __restrict__ Wtime, const float* __restrict__ btime,
    const float* __restrict__ We, const float* __restrict__ be,
    float* __restrict__ out)
{
    int*      srcS  = (int*)smem_dyn;
    int*      dstS  = (int*)smem_dyn + 128;
    float*    relS  = smem_dyn + 256;
    uint32_t* attrH = (uint32_t*)smem_dyn + 384;
    uint32_t* WeH   = (uint32_t*)smem_dyn + 7040;
    float*    estage = smem_dyn + 13568;

    int tid = threadIdx.x;
    int w    = tid >> 5;
    int lane = tid & 31;
    int g = lane >> 2, c = lane & 3;

    // W_e -> half2 smem, k-pairs interleaved: WeH[k2][n] = {We[2k2][n], We[2k2+1][n]}
    for (int i = tid; i < 48 * 128; i += 256) {
        int k2 = i >> 7, n = i & 127;
        float w0 = We[(2 * k2) * 128 + n];
        float w1 = We[(2 * k2 + 1) * 128 + n];
        WeH[k2 * WH_STRIDE + n] = h2u(w0, w1);
    }

    int tx = tid & 7;
    int ey = tid >> 3;

    for (int t = 0; t < TILES_PER_CTA; t++) {
        int eb = (blockIdx.x * TILES_PER_CTA + t) * 128;

        if (tid < 128) {
            int e = eb + tid;
            int s = ei[e];
            srcS[tid] = s;
            dstS[tid] = ei[EE + e];
            relS[tid] = lu[s] - tt[e];
        }
        __syncthreads();

        // attr: cols 0..31 time-enc (words 0..15), cols 32..95 msg (words 16..47)
        for (int i = tid; i < 128 * 16; i += 256) {
            int row = i >> 4, kp = i & 15;
            float rel = relS[row];
            float v0 = __cosf(rel * Wtime[2 * kp]     + btime[2 * kp]);
            float v1 = __cosf(rel * Wtime[2 * kp + 1] + btime[2 * kp + 1]);
            attrH[row * AH_STRIDE + kp] = h2u(v0, v1);
        }
        for (int i = tid; i < 128 * 16; i += 256) {
            int row = i >> 4, j = i & 15;
            float4 m = ((const float4*)msg)[(size_t)(eb + row) * 16 + j];
            uint2 u = make_uint2(h2u(m.x, m.y), h2u(m.z, m.w));
            *(uint2*)&attrH[row * AH_STRIDE + 16 + 2 * j] = u;
        }
        __syncthreads();

        // ---- e-GEMM: warp w rows [w*16, w*16+16) x 128 cols, fp16 k16 ----
        float acc[16][4];
        #pragma unroll
        for (int j = 0; j < 16; j++) {
            acc[j][0] = 0.f; acc[j][1] = 0.f; acc[j][2] = 0.f; acc[j][3] = 0.f;
        }
        const uint32_t* a0p = attrH + (w * 16 + g) * AH_STRIDE;
        const uint32_t* a1p = a0p + 8 * AH_STRIDE;
        #pragma unroll
        for (int kk = 0; kk < 6; kk++) {
            uint32_t af[4];
            af[0] = a0p[kk * 8 + c];
            af[1] = a1p[kk * 8 + c];
            af[2] = a0p[kk * 8 + c + 4];
            af[3] = a1p[kk * 8 + c + 4];
            const uint32_t* b0p = WeH + (kk * 8 + c) * WH_STRIDE + g;
            const uint32_t* b4p = b0p + 4 * WH_STRIDE;
            #pragma unroll
            for (int j = 0; j < 16; j++) {
                uint32_t bf[2];
                bf[0] = b0p[j * 8];
                bf[1] = b4p[j * 8];
                mma_f16(acc[j], af, bf);
            }
        }

        // ---- consume per head (identical to proven R7/R8 path) ----
        #pragma unroll
        for (int h = 0; h < 2; h++) {
            #pragma unroll
            for (int jj = 0; jj < 8; jj++) {
                int j = h * 8 + jj;
                int colb = jj * 8 + 2 * c;
                float2 lo = make_float2(acc[j][0], acc[j][1]);
                float2 hi = make_float2(acc[j][2], acc[j][3]);
                *(float2*)&estage[(w * 16 + g) * E_STRIDE + colb]     = lo;
                *(float2*)&estage[(w * 16 + g + 8) * E_STRIDE + colb] = hi;
            }
            __syncthreads();

            float be8[8];
            #pragma unroll
            for (int j = 0; j < 8; j++) be8[j] = be[h * 64 + tx * 8 + j];

            #pragma unroll
            for (int m4 = 0; m4 < 4; m4++) {
                int el = ey + 32 * m4;
                int s = srcS[el], d = dstS[el];
                float ev[8];
                #pragma unroll
                for (int j = 0; j < 8; j++)
                    ev[j] = estage[el * E_STRIDE + tx * 8 + j] + be8[j];

                const float* qp = &g_q[(size_t)d * 128 + h * 64 + tx * 8];
                const float* kp = &g_k[(size_t)s * 128 + h * 64 + tx * 8];
                float4 q0 = *(const float4*)qp, q1 = *(const float4*)(qp + 4);
                float4 k0 = *(const float4*)kp, k1 = *(const float4*)(kp + 4);
                float p = q0.x * (k0.x + ev[0]) + q0.y * (k0.y + ev[1])
                        + q0.z * (k0.z + ev[2]) + q0.w * (k0.w + ev[3])
                        + q1.x * (k1.x + ev[4]) + q1.y * (k1.y + ev[5])
                        + q1.z * (k1.z + ev[6]) + q1.w * (k1.w + ev[7]);
                p += __shfl_xor_sync(0xffffffffu, p, 1);
                p += __shfl_xor_sync(0xffffffffu, p, 2);
                p += __shfl_xor_sync(0xffffffffu, p, 4);
                float ex = __expf(p * 0.125f);
                if (tx == 0) atomicAdd(&g_denom[2 * d + h], ex);

                const float* vp = &g_v[(size_t)s * 128 + h * 64 + tx * 8];
                float4 v0 = *(const float4*)vp, v1 = *(const float4*)(vp + 4);
                float4 r0, r1;
                r0.x = ex * (v0.x + ev[0]); r0.y = ex * (v0.y + ev[1]);
                r0.z = ex * (v0.z + ev[2]); r0.w = ex * (v0.w + ev[3]);
                r1.x = ex * (v1.x + ev[4]); r1.y = ex * (v1.y + ev[5]);
                r1.z = ex * (v1.z + ev[6]); r1.w = ex * (v1.w + ev[7]);
                float4* op = (float4*)&out[(size_t)d * 128 + h * 64 + tx * 8];
                atomicAdd(op, r0);
                atomicAdd(op + 1, r1);
            }
            __syncthreads();
        }
    }
}

// ---------------------------------------------------------------------------
// K3: out = out / (denom + 1e-16) + skip
// ---------------------------------------------------------------------------
__global__ void finalize_kernel(float* __restrict__ out) {
    int idx = blockIdx.x * blockDim.x + threadIdx.x;
    int stride = gridDim.x * blockDim.x;
    const int total4 = NN * OUTD / 4;
    for (int i = idx; i < total4; i += stride) {
        int n = i >> 5;
        int h = (i >> 4) & 1;
        float inv = 1.0f / (g_denom[2 * n + h] + 1e-16f);
        float4 o  = ((float4*)out)[i];
        float4 sk = ((const float4*)g_skip)[i];
        o.x = o.x * inv + sk.x;
        o.y = o.y * inv + sk.y;
        o.z = o.z * inv + sk.z;
        o.w = o.w * inv + sk.w;
        ((float4*)out)[i] = o;
    }
}

// ---------------------------------------------------------------------------
extern "C" void kernel_launch(void* const* d_in, const int* in_sizes, int n_in,
                              void* d_out, int out_size)
{
    const float* x     = (const float*)d_in[0];
    const float* lu    = (const float*)d_in[1];
    const float* t     = (const float*)d_in[2];
    const float* msg   = (const float*)d_in[3];
    const int*   ei    = (const int*)d_in[4];     // int32 (JAX x64 disabled)
    const float* Wtime = (const float*)d_in[5];
    const float* btime = (const float*)d_in[6];
    const float* Wq = (const float*)d_in[7];  const float* bq = (const float*)d_in[8];
    const float* Wk = (const float*)d_in[9];  const float* bk = (const float*)d_in[10];
    const float* Wv = (const float*)d_in[11]; const float* bv = (const float*)d_in[12];
    const float* We = (const float*)d_in[13]; const float* be = (const float*)d_in[14];
    const float* Wsk = (const float*)d_in[15]; const float* bsk = (const float*)d_in[16];
    float* out = (float*)d_out;

    cudaFuncSetAttribute(proj_mma, cudaFuncAttributeMaxDynamicSharedMemorySize, PROJ_SMEM_BYTES);
    cudaFuncSetAttribute(edge_kernel_mma, cudaFuncAttributeMaxDynamicSharedMemorySize, EDGE_SMEM_BYTES);

    zero_kernel<<<512, 256>>>(out);

    dim3 pgrid((NN + 127) / 128, 4);
    proj_mma<<<pgrid, 256, PROJ_SMEM_BYTES>>>(x, Wq, bq, Wk, bk, Wv, bv, Wsk, bsk);

    edge_kernel_mma<<<NCTA, 256, EDGE_SMEM_BYTES>>>(lu, t, msg, ei, Wtime, btime, We, be, out);

    finalize_kernel<<<512, 256>>>(out);
}

// round 10
// speedup vs baseline: 2.3094x; 1.2914x over previous
#include <cuda_runtime.h>
#include <cuda_fp16.h>
#include <math.h>
#include <stdint.h>

#define NN   50000
#define EE   800000
#define IND  128
#define OUTD 128
#define TILES_PER_CTA 2
#define NTILES (EE / 128)                 // 6250
#define NCTA   (NTILES / TILES_PER_CTA)   // 3125

#define XP_STRIDE 132   // proj x-tile row stride (floats)
#define WP_STRIDE 136   // proj W row stride (floats)
#define AH_STRIDE 52    // attr row stride in half2 words
#define WH_STRIDE 136   // WeH k2-row stride in half2 words
#define ESH 68          // estage row stride in half2 words (128 cols = 64 + 4 pad)

// ---- scratch (static device arrays; no allocation) ----
__device__ float g_q[NN * OUTD];
__device__ float g_k[NN * OUTD];
__device__ float g_v[NN * OUTD];
__device__ float g_skip[NN * OUTD];
__device__ float g_denom[NN * 2];

extern __shared__ float smem_dyn[];

__device__ __forceinline__ float to_tf32(float x) {
    float r; asm("cvt.rna.tf32.f32 %0, %1;" : "=f"(r) : "f"(x)); return r;
}
__device__ __forceinline__ void mma_tf32(float* d, const uint32_t* a, const uint32_t* b) {
    asm volatile("mma.sync.aligned.m16n8k8.row.col.f32.tf32.tf32.f32 "
                 "{%0,%1,%2,%3}, {%4,%5,%6,%7}, {%8,%9}, {%0,%1,%2,%3};"
                 : "+f"(d[0]), "+f"(d[1]), "+f"(d[2]), "+f"(d[3])
                 : "r"(a[0]), "r"(a[1]), "r"(a[2]), "r"(a[3]), "r"(b[0]), "r"(b[1]));
}
__device__ __forceinline__ void mma_f16(float* d, const uint32_t* a, const uint32_t* b) {
    asm volatile("mma.sync.aligned.m16n8k16.row.col.f32.f16.f16.f32 "
                 "{%0,%1,%2,%3}, {%4,%5,%6,%7}, {%8,%9}, {%0,%1,%2,%3};"
                 : "+f"(d[0]), "+f"(d[1]), "+f"(d[2]), "+f"(d[3])
                 : "r"(a[0]), "r"(a[1]), "r"(a[2]), "r"(a[3]), "r"(b[0]), "r"(b[1]));
}
__device__ __forceinline__ uint32_t h2u(float a, float b) {
    __half2 h = __floats2half2_rn(a, b);
    return *(uint32_t*)&h;
}

// ---------------------------------------------------------------------------
// K0: zero d_out and denominators
// ---------------------------------------------------------------------------
__global__ void zero_kernel(float* __restrict__ out) {
    int idx = blockIdx.x * blockDim.x + threadIdx.x;
    int stride = gridDim.x * blockDim.x;
    const int total4 = NN * OUTD / 4;
    for (int i = idx; i < total4; i += stride)
        ((float4*)out)[i] = make_float4(0.f, 0.f, 0.f, 0.f);
    for (int i = idx; i < NN * 2; i += stride)
        g_denom[i] = 0.f;
}

// ---------------------------------------------------------------------------
// K1: node projections via tf32 mma.sync (unchanged — proven)
// ---------------------------------------------------------------------------
#define PROJ_SMEM_BYTES ((128 * XP_STRIDE + 128 * WP_STRIDE) * 4)

__global__ __launch_bounds__(256, 1) void proj_mma(
    const float* __restrict__ x,
    const float* __restrict__ Wq, const float* __restrict__ bq,
    const float* __restrict__ Wk, const float* __restrict__ bk,
    const float* __restrict__ Wv, const float* __restrict__ bv,
    const float* __restrict__ Wsk, const float* __restrict__ bsk)
{
    float* xs = smem_dyn;
    float* Ws = smem_dyn + 128 * XP_STRIDE;

    const float* W; const float* bias; float* out;
    switch (blockIdx.y) {
        case 0:  W = Wq;  bias = bq;  out = g_q;    break;
        case 1:  W = Wk;  bias = bk;  out = g_k;    break;
        case 2:  W = Wv;  bias = bv;  out = g_v;    break;
        default: W = Wsk; bias = bsk; out = g_skip; break;
    }

    int tid  = threadIdx.x;
    int w    = tid >> 5;
    int lane = tid & 31;
    int g = lane >> 2, c = lane & 3;
    int row0 = blockIdx.x * 128;

    for (int i = tid; i < 128 * 32; i += 256) {
        int k = i >> 5, n4 = (i & 31) * 4;
        float4 v = ((const float4*)W)[i];
        v.x = to_tf32(v.x); v.y = to_tf32(v.y); v.z = to_tf32(v.z); v.w = to_tf32(v.w);
        *(float4*)&Ws[k * WP_STRIDE + n4] = v;
    }
    for (int i = tid; i < 128 * 32; i += 256) {
        int r = i >> 5, k4 = (i & 31) * 4;
        int gr = row0 + r;
        float4 v = make_float4(0.f, 0.f, 0.f, 0.f);
        if (gr < NN) v = ((const float4*)x)[(size_t)gr * 32 + (i & 31)];
        v.x = to_tf32(v.x); v.y = to_tf32(v.y); v.z = to_tf32(v.z); v.w = to_tf32(v.w);
        *(float4*)&xs[r * XP_STRIDE + k4] = v;
    }
    __syncthreads();

    float acc[16][4];
    #pragma unroll
    for (int j = 0; j < 16; j++) {
        acc[j][0] = 0.f; acc[j][1] = 0.f; acc[j][2] = 0.f; acc[j][3] = 0.f;
    }
    const float* ar0 = xs + (w * 16 + g) * XP_STRIDE;
    const float* ar1 = ar0 + 8 * XP_STRIDE;
    #pragma unroll
    for (int kk = 0; kk < 16; kk++) {
        uint32_t af[4];
        af[0] = __float_as_uint(ar0[kk * 8 + c]);
        af[1] = __float_as_uint(ar1[kk * 8 + c]);
        af[2] = __float_as_uint(ar0[kk * 8 + c + 4]);
        af[3] = __float_as_uint(ar1[kk * 8 + c + 4]);
        const float* bk0 = Ws + (kk * 8 + c) * WP_STRIDE + g;
        const float* bk4 = bk0 + 4 * WP_STRIDE;
        #pragma unroll
        for (int j = 0; j < 16; j++) {
            uint32_t bf[2];
            bf[0] = __float_as_uint(bk0[j * 8]);
            bf[1] = __float_as_uint(bk4[j * 8]);
            mma_tf32(acc[j], af, bf);
        }
    }

    int r0 = row0 + w * 16 + g;
    int r1 = r0 + 8;
    #pragma unroll
    for (int j = 0; j < 16; j++) {
        int col = j * 8 + 2 * c;
        float b0 = bias[col], b1 = bias[col + 1];
        if (r0 < NN) {
            float2 o = make_float2(acc[j][0] + b0, acc[j][1] + b1);
            *(float2*)&out[(size_t)r0 * 128 + col] = o;
        }
        if (r1 < NN) {
            float2 o = make_float2(acc[j][2] + b0, acc[j][3] + b1);
            *(float2*)&out[(size_t)r1 * 128 + col] = o;
        }
    }
}

// ---------------------------------------------------------------------------
// K2: edge kernel — fp16 e-GEMM + single-pass dual-head consume.
// smem words (uint32): [0:128) srcS, [128:256) dstS, [256:384) relS,
//   [384:7040)   attrH  (128 x AH_STRIDE half2)
//   [7040:13568) WeH    (48 x WH_STRIDE half2)
//   [13568:22272) estageH (128 x ESH half2, both heads)
// total 22272 words = 89088 B -> 2 CTA/SM
// ---------------------------------------------------------------------------
#define EDGE_SMEM_BYTES (22272 * 4)

__global__ __launch_bounds__(256, 2) void edge_kernel_mma(
    const float* __restrict__ lu, const float* __restrict__ tt,
    const float* __restrict__ msg, const int* __restrict__ ei,
    const float* __restrict__ Wtime, const float* __restrict__ btime,
    const float* __restrict__ We, const float* __restrict__ be,
    float* __restrict__ out)
{
    int*      srcS  = (int*)smem_dyn;
    int*      dstS  = (int*)smem_dyn + 128;
    float*    relS  = smem_dyn + 256;
    uint32_t* attrH = (uint32_t*)smem_dyn + 384;
    uint32_t* WeH   = (uint32_t*)smem_dyn + 7040;
    uint32_t* estageH = (uint32_t*)smem_dyn + 13568;

    int tid = threadIdx.x;
    int w    = tid >> 5;
    int lane = tid & 31;
    int g = lane >> 2, c = lane & 3;

    // W_e -> half2 smem, k-pairs interleaved
    for (int i = tid; i < 48 * 128; i += 256) {
        int k2 = i >> 7, n = i & 127;
        float w0 = We[(2 * k2) * 128 + n];
        float w1 = We[(2 * k2 + 1) * 128 + n];
        WeH[k2 * WH_STRIDE + n] = h2u(w0, w1);
    }

    int tx = tid & 7;
    int ey = tid >> 3;

    // biases for both heads (constant across tiles)
    float be0[8], be1[8];
    #pragma unroll
    for (int j = 0; j < 8; j++) {
        be0[j] = be[tx * 8 + j];
        be1[j] = be[64 + tx * 8 + j];
    }

    for (int t = 0; t < TILES_PER_CTA; t++) {
        int eb = (blockIdx.x * TILES_PER_CTA + t) * 128;

        __syncthreads();   // prev consume done before overwriting srcS/dstS
        if (tid < 128) {
            int e = eb + tid;
            int s = ei[e];
            srcS[tid] = s;
            dstS[tid] = ei[EE + e];
            relS[tid] = lu[s] - tt[e];
        }
        __syncthreads();

        // attr: cols 0..31 time-enc, 32..95 msg (half2)
        for (int i = tid; i < 128 * 16; i += 256) {
            int row = i >> 4, kp = i & 15;
            float rel = relS[row];
            float v0 = __cosf(rel * Wtime[2 * kp]     + btime[2 * kp]);
            float v1 = __cosf(rel * Wtime[2 * kp + 1] + btime[2 * kp + 1]);
            attrH[row * AH_STRIDE + kp] = h2u(v0, v1);
        }
        for (int i = tid; i < 128 * 16; i += 256) {
            int row = i >> 4, j = i & 15;
            float4 m = ((const float4*)msg)[(size_t)(eb + row) * 16 + j];
            uint2 u = make_uint2(h2u(m.x, m.y), h2u(m.z, m.w));
            *(uint2*)&attrH[row * AH_STRIDE + 16 + 2 * j] = u;
        }
        __syncthreads();

        // ---- e-GEMM: warp w rows [w*16, w*16+16) x 128 cols ----
        float acc[16][4];
        #pragma unroll
        for (int j = 0; j < 16; j++) {
            acc[j][0] = 0.f; acc[j][1] = 0.f; acc[j][2] = 0.f; acc[j][3] = 0.f;
        }
        const uint32_t* a0p = attrH + (w * 16 + g) * AH_STRIDE;
        const uint32_t* a1p = a0p + 8 * AH_STRIDE;
        #pragma unroll
        for (int kk = 0; kk < 6; kk++) {
            uint32_t af[4];
            af[0] = a0p[kk * 8 + c];
            af[1] = a1p[kk * 8 + c];
            af[2] = a0p[kk * 8 + c + 4];
            af[3] = a1p[kk * 8 + c + 4];
            const uint32_t* b0p = WeH + (kk * 8 + c) * WH_STRIDE + g;
            const uint32_t* b4p = b0p + 4 * WH_STRIDE;
            #pragma unroll
            for (int j = 0; j < 16; j++) {
                uint32_t bf[2];
                bf[0] = b0p[j * 8];
                bf[1] = b4p[j * 8];
                mma_f16(acc[j], af, bf);
            }
        }

        // ---- stage ALL 128 cols as half2 (word col/2 = j*4 + c) ----
        #pragma unroll
        for (int j = 0; j < 16; j++) {
            estageH[(w * 16 + g)     * ESH + j * 4 + c] = h2u(acc[j][0], acc[j][1]);
            estageH[(w * 16 + g + 8) * ESH + j * 4 + c] = h2u(acc[j][2], acc[j][3]);
        }
        __syncthreads();

        // ---- single-pass dual-head consume: 4 edges per thread ----
        #pragma unroll
        for (int m4 = 0; m4 < 4; m4++) {
            int el = ey + 32 * m4;
            int s = srcS[el], d = dstS[el];

            uint4 eu0 = *(uint4*)&estageH[el * ESH + tx * 4];        // head0 cols tx*8..+8
            uint4 eu1 = *(uint4*)&estageH[el * ESH + 32 + tx * 4];   // head1
            float ev0[8], ev1[8];
            {
                float2 f;
                f = __half22float2(*(__half2*)&eu0.x); ev0[0] = f.x + be0[0]; ev0[1] = f.y + be0[1];
                f = __half22float2(*(__half2*)&eu0.y); ev0[2] = f.x + be0[2]; ev0[3] = f.y + be0[3];
                f = __half22float2(*(__half2*)&eu0.z); ev0[4] = f.x + be0[4]; ev0[5] = f.y + be0[5];
                f = __half22float2(*(__half2*)&eu0.w); ev0[6] = f.x + be0[6]; ev0[7] = f.y + be0[7];
                f = __half22float2(*(__half2*)&eu1.x); ev1[0] = f.x + be1[0]; ev1[1] = f.y + be1[1];
                f = __half22float2(*(__half2*)&eu1.y); ev1[2] = f.x + be1[2]; ev1[3] = f.y + be1[3];
                f = __half22float2(*(__half2*)&eu1.z); ev1[4] = f.x + be1[4]; ev1[5] = f.y + be1[5];
                f = __half22float2(*(__half2*)&eu1.w); ev1[6] = f.x + be1[6]; ev1[7] = f.y + be1[7];
            }

            const float* qp = &g_q[(size_t)d * 128 + tx * 8];
            const float* kp = &g_k[(size_t)s * 128 + tx * 8];
            float4 q00 = *(const float4*)qp,        q01 = *(const float4*)(qp + 4);
            float4 q10 = *(const float4*)(qp + 64), q11 = *(const float4*)(qp + 68);
            float4 k00 = *(const float4*)kp,        k01 = *(const float4*)(kp + 4);
            float4 k10 = *(const float4*)(kp + 64), k11 = *(const float4*)(kp + 68);

            float p0 = q00.x * (k00.x + ev0[0]) + q00.y * (k00.y + ev0[1])
                     + q00.z * (k00.z + ev0[2]) + q00.w * (k00.w + ev0[3])
                     + q01.x * (k01.x + ev0[4]) + q01.y * (k01.y + ev0[5])
                     + q01.z * (k01.z + ev0[6]) + q01.w * (k01.w + ev0[7]);
            float p1 = q10.x * (k10.x + ev1[0]) + q10.y * (k10.y + ev1[1])
                     + q10.z * (k10.z + ev1[2]) + q10.w * (k10.w + ev1[3])
                     + q11.x * (k11.x + ev1[4]) + q11.y * (k11.y + ev1[5])
                     + q11.z * (k11.z + ev1[6]) + q11.w * (k11.w + ev1[7]);

            p0 += __shfl_xor_sync(0xffffffffu, p0, 1);
            p1 += __shfl_xor_sync(0xffffffffu, p1, 1);
            p0 += __shfl_xor_sync(0xffffffffu, p0, 2);
            p1 += __shfl_xor_sync(0xffffffffu, p1, 2);
            p0 += __shfl_xor_sync(0xffffffffu, p0, 4);
            p1 += __shfl_xor_sync(0xffffffffu, p1, 4);

            float ex0 = __expf(p0 * 0.125f);
            float ex1 = __expf(p1 * 0.125f);
            if (tx == 0) {
                atomicAdd(&g_denom[2 * d], ex0);
                atomicAdd(&g_denom[2 * d + 1], ex1);
            }

            const float* vp = &g_v[(size_t)s * 128 + tx * 8];
            float4 v00 = *(const float4*)vp,        v01 = *(const float4*)(vp + 4);
            float4 v10 = *(const float4*)(vp + 64), v11 = *(const float4*)(vp + 68);

            float4 r0, r1, r2, r3;
            r0.x = ex0 * (v00.x + ev0[0]); r0.y = ex0 * (v00.y + ev0[1]);
            r0.z = ex0 * (v00.z + ev0[2]); r0.w = ex0 * (v00.w + ev0[3]);
            r1.x = ex0 * (v01.x + ev0[4]); r1.y = ex0 * (v01.y + ev0[5]);
            r1.z = ex0 * (v01.z + ev0[6]); r1.w = ex0 * (v01.w + ev0[7]);
            r2.x = ex1 * (v10.x + ev1[0]); r2.y = ex1 * (v10.y + ev1[1]);
            r2.z = ex1 * (v10.z + ev1[2]); r2.w = ex1 * (v10.w + ev1[3]);
            r3.x = ex1 * (v11.x + ev1[4]); r3.y = ex1 * (v11.y + ev1[5]);
            r3.z = ex1 * (v11.z + ev1[6]); r3.w = ex1 * (v11.w + ev1[7]);

            float4* op = (float4*)&out[(size_t)d * 128 + tx * 8];
            atomicAdd(op, r0);
            atomicAdd(op + 1, r1);
            atomicAdd(op + 16, r2);
            atomicAdd(op + 17, r3);
        }
    }
}

// ---------------------------------------------------------------------------
// K3: out = out / (denom + 1e-16) + skip
// ---------------------------------------------------------------------------
__global__ void finalize_kernel(float* __restrict__ out) {
    int idx = blockIdx.x * blockDim.x + threadIdx.x;
    int stride = gridDim.x * blockDim.x;
    const int total4 = NN * OUTD / 4;
    for (int i = idx; i < total4; i += stride) {
        int n = i >> 5;
        int h = (i >> 4) & 1;
        float inv = 1.0f / (g_denom[2 * n + h] + 1e-16f);
        float4 o  = ((float4*)out)[i];
        float4 sk = ((const float4*)g_skip)[i];
        o.x = o.x * inv + sk.x;
        o.y = o.y * inv + sk.y;
        o.z = o.z * inv + sk.z;
        o.w = o.w * inv + sk.w;
        ((float4*)out)[i] = o;
    }
}

// ---------------------------------------------------------------------------
extern "C" void kernel_launch(void* const* d_in, const int* in_sizes, int n_in,
                              void* d_out, int out_size)
{
    const float* x     = (const float*)d_in[0];
    const float* lu    = (const float*)d_in[1];
    const float* t     = (const float*)d_in[2];
    const float* msg   = (const float*)d_in[3];
    const int*   ei    = (const int*)d_in[4];     // int32 (JAX x64 disabled)
    const float* Wtime = (const float*)d_in[5];
    const float* btime = (const float*)d_in[6];
    const float* Wq = (const float*)d_in[7];  const float* bq = (const float*)d_in[8];
    const float* Wk = (const float*)d_in[9];  const float* bk = (const float*)d_in[10];
    const float* Wv = (const float*)d_in[11]; const float* bv = (const float*)d_in[12];
    const float* We = (const float*)d_in[13]; const float* be = (const float*)d_in[14];
    const float* Wsk = (const float*)d_in[15]; const float* bsk = (const float*)d_in[16];
    float* out = (float*)d_out;

    cudaFuncSetAttribute(proj_mma, cudaFuncAttributeMaxDynamicSharedMemorySize, PROJ_SMEM_BYTES);
    cudaFuncSetAttribute(edge_kernel_mma, cudaFuncAttributeMaxDynamicSharedMemorySize, EDGE_SMEM_BYTES);

    zero_kernel<<<512, 256>>>(out);

    dim3 pgrid((NN + 127) / 128, 4);
    proj_mma<<<pgrid, 256, PROJ_SMEM_BYTES>>>(x, Wq, bq, Wk, bk, Wv, bv, Wsk, bsk);

    edge_kernel_mma<<<NCTA, 256, EDGE_SMEM_BYTES>>>(lu, t, msg, ei, Wtime, btime, We, be, out);

    finalize_kernel<<<512, 256>>>(out);
}

// round 11
// speedup vs baseline: 2.8269x; 1.2241x over previous
#include <cuda_runtime.h>
#include <cuda_fp16.h>
#include <math.h>
#include <stdint.h>

#define NN   50000
#define EE   800000
#define IND  128
#define OUTD 128
#define TILES_PER_CTA 2
#define NTILES (EE / 128)                 // 6250
#define NCTA   (NTILES / TILES_PER_CTA)   // 3125

#define AH_STRIDE 52    // edge attr row stride in half2 words
#define WH_STRIDE 136   // WeH / WsH k2-row stride in half2 words
#define ESH 68          // estage row stride in half2 words
#define XH_STRIDE 68    // proj x row stride in half2 words (banks 4g+c distinct)

// ---- scratch (static device arrays; no allocation) ----
__device__ float g_q[NN * OUTD];
__device__ float g_k[NN * OUTD];
__device__ float g_v[NN * OUTD];
__device__ float g_skip[NN * OUTD];
__device__ float g_denom[NN * 2];

extern __shared__ float smem_dyn[];

__device__ __forceinline__ void mma_f16(float* d, const uint32_t* a, const uint32_t* b) {
    asm volatile("mma.sync.aligned.m16n8k16.row.col.f32.f16.f16.f32 "
                 "{%0,%1,%2,%3}, {%4,%5,%6,%7}, {%8,%9}, {%0,%1,%2,%3};"
                 : "+f"(d[0]), "+f"(d[1]), "+f"(d[2]), "+f"(d[3])
                 : "r"(a[0]), "r"(a[1]), "r"(a[2]), "r"(a[3]), "r"(b[0]), "r"(b[1]));
}
__device__ __forceinline__ uint32_t h2u(float a, float b) {
    __half2 h = __floats2half2_rn(a, b);
    return *(uint32_t*)&h;
}

// ---------------------------------------------------------------------------
// K0: zero d_out and denominators
// ---------------------------------------------------------------------------
__global__ void zero_kernel(float* __restrict__ out) {
    int idx = blockIdx.x * blockDim.x + threadIdx.x;
    int stride = gridDim.x * blockDim.x;
    const int total4 = NN * OUTD / 4;
    for (int i = idx; i < total4; i += stride)
        ((float4*)out)[i] = make_float4(0.f, 0.f, 0.f, 0.f);
    for (int i = idx; i < NN * 2; i += stride)
        g_denom[i] = 0.f;
}

// ---------------------------------------------------------------------------
// K1: node projections via fp16 m16n8k16 mma (same fragment map as edge kernel)
// smem words: xsH 128 x XH_STRIDE, WsH 64 x WH_STRIDE   (~70KB -> 2 CTA/SM)
// ---------------------------------------------------------------------------
#define PROJ_SMEM_BYTES ((128 * XH_STRIDE + 64 * WH_STRIDE) * 4)

__global__ __launch_bounds__(256, 2) void proj_f16(
    const float* __restrict__ x,
    const float* __restrict__ Wq, const float* __restrict__ bq,
    const float* __restrict__ Wk, const float* __restrict__ bk,
    const float* __restrict__ Wv, const float* __restrict__ bv,
    const float* __restrict__ Wsk, const float* __restrict__ bsk)
{
    uint32_t* xsH = (uint32_t*)smem_dyn;                     // [128][68]
    uint32_t* WsH = (uint32_t*)smem_dyn + 128 * XH_STRIDE;   // [64][136]

    const float* W; const float* bias; float* out;
    switch (blockIdx.y) {
        case 0:  W = Wq;  bias = bq;  out = g_q;    break;
        case 1:  W = Wk;  bias = bk;  out = g_k;    break;
        case 2:  W = Wv;  bias = bv;  out = g_v;    break;
        default: W = Wsk; bias = bsk; out = g_skip; break;
    }

    int tid  = threadIdx.x;
    int w    = tid >> 5;
    int lane = tid & 31;
    int g = lane >> 2, c = lane & 3;
    int row0 = blockIdx.x * 128;

    // W[k][n] -> WsH[k2][n] = {W[2k2][n], W[2k2+1][n]}
    for (int i = tid; i < 64 * 128; i += 256) {
        int k2 = i >> 7, n = i & 127;
        float w0 = W[(2 * k2) * 128 + n];
        float w1 = W[(2 * k2 + 1) * 128 + n];
        WsH[k2 * WH_STRIDE + n] = h2u(w0, w1);
    }
    // x tile -> half2 words, zero-padded rows
    for (int i = tid; i < 128 * 32; i += 256) {
        int r = i >> 5, j = i & 31;          // j = float4 index (4 floats = 2 words)
        int gr = row0 + r;
        float4 v = make_float4(0.f, 0.f, 0.f, 0.f);
        if (gr < NN) v = ((const float4*)x)[(size_t)gr * 32 + j];
        uint2 u = make_uint2(h2u(v.x, v.y), h2u(v.z, v.w));
        *(uint2*)&xsH[r * XH_STRIDE + 2 * j] = u;
    }
    __syncthreads();

    float acc[16][4];
    #pragma unroll
    for (int j = 0; j < 16; j++) {
        acc[j][0] = 0.f; acc[j][1] = 0.f; acc[j][2] = 0.f; acc[j][3] = 0.f;
    }
    const uint32_t* a0p = xsH + (w * 16 + g) * XH_STRIDE;
    const uint32_t* a1p = a0p + 8 * XH_STRIDE;
    #pragma unroll
    for (int kk = 0; kk < 8; kk++) {
        uint32_t af[4];
        af[0] = a0p[kk * 8 + c];
        af[1] = a1p[kk * 8 + c];
        af[2] = a0p[kk * 8 + c + 4];
        af[3] = a1p[kk * 8 + c + 4];
        const uint32_t* b0p = WsH + (kk * 8 + c) * WH_STRIDE + g;
        const uint32_t* b4p = b0p + 4 * WH_STRIDE;
        #pragma unroll
        for (int j = 0; j < 16; j++) {
            uint32_t bf[2];
            bf[0] = b0p[j * 8];
            bf[1] = b4p[j * 8];
            mma_f16(acc[j], af, bf);
        }
    }

    int r0 = row0 + w * 16 + g;
    int r1 = r0 + 8;
    #pragma unroll
    for (int j = 0; j < 16; j++) {
        int col = j * 8 + 2 * c;
        float b0 = bias[col], b1 = bias[col + 1];
        if (r0 < NN) {
            float2 o = make_float2(acc[j][0] + b0, acc[j][1] + b1);
            *(float2*)&out[(size_t)r0 * 128 + col] = o;
        }
        if (r1 < NN) {
            float2 o = make_float2(acc[j][2] + b0, acc[j][3] + b1);
            *(float2*)&out[(size_t)r1 * 128 + col] = o;
        }
    }
}

// ---------------------------------------------------------------------------
// K2: edge kernel — fp16 e-GEMM + single-pass dual-head consume (proven R10)
// ---------------------------------------------------------------------------
#define EDGE_SMEM_BYTES (22272 * 4)

__global__ __launch_bounds__(256, 2) void edge_kernel_mma(
    const float* __restrict__ lu, const float* __restrict__ tt,
    const float* __restrict__ msg, const int* __restrict__ ei,
    const float* __restrict__ Wtime, const float* __restrict__ btime,
    const float* __restrict__ We, const float* __restrict__ be,
    float* __restrict__ out)
{
    int*      srcS  = (int*)smem_dyn;
    int*      dstS  = (int*)smem_dyn + 128;
    float*    relS  = smem_dyn + 256;
    uint32_t* attrH = (uint32_t*)smem_dyn + 384;
    uint32_t* WeH   = (uint32_t*)smem_dyn + 7040;
    uint32_t* estageH = (uint32_t*)smem_dyn + 13568;

    int tid = threadIdx.x;
    int w    = tid >> 5;
    int lane = tid & 31;
    int g = lane >> 2, c = lane & 3;

    for (int i = tid; i < 48 * 128; i += 256) {
        int k2 = i >> 7, n = i & 127;
        float w0 = We[(2 * k2) * 128 + n];
        float w1 = We[(2 * k2 + 1) * 128 + n];
        WeH[k2 * WH_STRIDE + n] = h2u(w0, w1);
    }

    int tx = tid & 7;
    int ey = tid >> 3;

    float be0[8], be1[8];
    #pragma unroll
    for (int j = 0; j < 8; j++) {
        be0[j] = be[tx * 8 + j];
        be1[j] = be[64 + tx * 8 + j];
    }

    for (int t = 0; t < TILES_PER_CTA; t++) {
        int eb = (blockIdx.x * TILES_PER_CTA + t) * 128;

        __syncthreads();
        if (tid < 128) {
            int e = eb + tid;
            int s = ei[e];
            srcS[tid] = s;
            dstS[tid] = ei[EE + e];
            relS[tid] = lu[s] - tt[e];
        }
        __syncthreads();

        for (int i = tid; i < 128 * 16; i += 256) {
            int row = i >> 4, kp = i & 15;
            float rel = relS[row];
            float v0 = __cosf(rel * Wtime[2 * kp]     + btime[2 * kp]);
            float v1 = __cosf(rel * Wtime[2 * kp + 1] + btime[2 * kp + 1]);
            attrH[row * AH_STRIDE + kp] = h2u(v0, v1);
        }
        for (int i = tid; i < 128 * 16; i += 256) {
            int row = i >> 4, j = i & 15;
            float4 m = ((const float4*)msg)[(size_t)(eb + row) * 16 + j];
            uint2 u = make_uint2(h2u(m.x, m.y), h2u(m.z, m.w));
            *(uint2*)&attrH[row * AH_STRIDE + 16 + 2 * j] = u;
        }
        __syncthreads();

        float acc[16][4];
        #pragma unroll
        for (int j = 0; j < 16; j++) {
            acc[j][0] = 0.f; acc[j][1] = 0.f; acc[j][2] = 0.f; acc[j][3] = 0.f;
        }
        const uint32_t* a0p = attrH + (w * 16 + g) * AH_STRIDE;
        const uint32_t* a1p = a0p + 8 * AH_STRIDE;
        #pragma unroll
        for (int kk = 0; kk < 6; kk++) {
            uint32_t af[4];
            af[0] = a0p[kk * 8 + c];
            af[1] = a1p[kk * 8 + c];
            af[2] = a0p[kk * 8 + c + 4];
            af[3] = a1p[kk * 8 + c + 4];
            const uint32_t* b0p = WeH + (kk * 8 + c) * WH_STRIDE + g;
            const uint32_t* b4p = b0p + 4 * WH_STRIDE;
            #pragma unroll
            for (int j = 0; j < 16; j++) {
                uint32_t bf[2];
                bf[0] = b0p[j * 8];
                bf[1] = b4p[j * 8];
                mma_f16(acc[j], af, bf);
            }
        }

        #pragma unroll
        for (int j = 0; j < 16; j++) {
            estageH[(w * 16 + g)     * ESH + j * 4 + c] = h2u(acc[j][0], acc[j][1]);
            estageH[(w * 16 + g + 8) * ESH + j * 4 + c] = h2u(acc[j][2], acc[j][3]);
        }
        __syncthreads();

        #pragma unroll
        for (int m4 = 0; m4 < 4; m4++) {
            int el = ey + 32 * m4;
            int s = srcS[el], d = dstS[el];

            uint4 eu0 = *(uint4*)&estageH[el * ESH + tx * 4];
            uint4 eu1 = *(uint4*)&estageH[el * ESH + 32 + tx * 4];
            float ev0[8], ev1[8];
            {
                float2 f;
                f = __half22float2(*(__half2*)&eu0.x); ev0[0] = f.x + be0[0]; ev0[1] = f.y + be0[1];
                f = __half22float2(*(__half2*)&eu0.y); ev0[2] = f.x + be0[2]; ev0[3] = f.y + be0[3];
                f = __half22float2(*(__half2*)&eu0.z); ev0[4] = f.x + be0[4]; ev0[5] = f.y + be0[5];
                f = __half22float2(*(__half2*)&eu0.w); ev0[6] = f.x + be0[6]; ev0[7] = f.y + be0[7];
                f = __half22float2(*(__half2*)&eu1.x); ev1[0] = f.x + be1[0]; ev1[1] = f.y + be1[1];
                f = __half22float2(*(__half2*)&eu1.y); ev1[2] = f.x + be1[2]; ev1[3] = f.y + be1[3];
                f = __half22float2(*(__half2*)&eu1.z); ev1[4] = f.x + be1[4]; ev1[5] = f.y + be1[5];
                f = __half22float2(*(__half2*)&eu1.w); ev1[6] = f.x + be1[6]; ev1[7] = f.y + be1[7];
            }

            const float* qp = &g_q[(size_t)d * 128 + tx * 8];
            const float* kp = &g_k[(size_t)s * 128 + tx * 8];
            float4 q00 = *(const float4*)qp,        q01 = *(const float4*)(qp + 4);
            float4 q10 = *(const float4*)(qp + 64), q11 = *(const float4*)(qp + 68);
            float4 k00 = *(const float4*)kp,        k01 = *(const float4*)(kp + 4);
            float4 k10 = *(const float4*)(kp + 64), k11 = *(const float4*)(kp + 68);

            float p0 = q00.x * (k00.x + ev0[0]) + q00.y * (k00.y + ev0[1])
                     + q00.z * (k00.z + ev0[2]) + q00.w * (k00.w + ev0[3])
                     + q01.x * (k01.x + ev0[4]) + q01.y * (k01.y + ev0[5])
                     + q01.z * (k01.z + ev0[6]) + q01.w * (k01.w + ev0[7]);
            float p1 = q10.x * (k10.x + ev1[0]) + q10.y * (k10.y + ev1[1])
                     + q10.z * (k10.z + ev1[2]) + q10.w * (k10.w + ev1[3])
                     + q11.x * (k11.x + ev1[4]) + q11.y * (k11.y + ev1[5])
                     + q11.z * (k11.z + ev1[6]) + q11.w * (k11.w + ev1[7]);

            p0 += __shfl_xor_sync(0xffffffffu, p0, 1);
            p1 += __shfl_xor_sync(0xffffffffu, p1, 1);
            p0 += __shfl_xor_sync(0xffffffffu, p0, 2);
            p1 += __shfl_xor_sync(0xffffffffu, p1, 2);
            p0 += __shfl_xor_sync(0xffffffffu, p0, 4);
            p1 += __shfl_xor_sync(0xffffffffu, p1, 4);

            float ex0 = __expf(p0 * 0.125f);
            float ex1 = __expf(p1 * 0.125f);
            if (tx == 0) {
                atomicAdd(&g_denom[2 * d], ex0);
                atomicAdd(&g_denom[2 * d + 1], ex1);
            }

            const float* vp = &g_v[(size_t)s * 128 + tx * 8];
            float4 v00 = *(const float4*)vp,        v01 = *(const float4*)(vp + 4);
            float4 v10 = *(const float4*)(vp + 64), v11 = *(const float4*)(vp + 68);

            float4 r0, r1, r2, r3;
            r0.x = ex0 * (v00.x + ev0[0]); r0.y = ex0 * (v00.y + ev0[1]);
            r0.z = ex0 * (v00.z + ev0[2]); r0.w = ex0 * (v00.w + ev0[3]);
            r1.x = ex0 * (v01.x + ev0[4]); r1.y = ex0 * (v01.y + ev0[5]);
            r1.z = ex0 * (v01.z + ev0[6]); r1.w = ex0 * (v01.w + ev0[7]);
            r2.x = ex1 * (v10.x + ev1[0]); r2.y = ex1 * (v10.y + ev1[1]);
            r2.z = ex1 * (v10.z + ev1[2]); r2.w = ex1 * (v10.w + ev1[3]);
            r3.x = ex1 * (v11.x + ev1[4]); r3.y = ex1 * (v11.y + ev1[5]);
            r3.z = ex1 * (v11.z + ev1[6]); r3.w = ex1 * (v11.w + ev1[7]);

            float4* op = (float4*)&out[(size_t)d * 128 + tx * 8];
            atomicAdd(op, r0);
            atomicAdd(op + 1, r1);
            atomicAdd(op + 16, r2);
            atomicAdd(op + 17, r3);
        }
    }
}

// ---------------------------------------------------------------------------
// K3: out = out / (denom + 1e-16) + skip
// ---------------------------------------------------------------------------
__global__ void finalize_kernel(float* __restrict__ out) {
    int idx = blockIdx.x * blockDim.x + threadIdx.x;
    int stride = gridDim.x * blockDim.x;
    const int total4 = NN * OUTD / 4;
    for (int i = idx; i < total4; i += stride) {
        int n = i >> 5;
        int h = (i >> 4) & 1;
        float inv = 1.0f / (g_denom[2 * n + h] + 1e-16f);
        float4 o  = ((float4*)out)[i];
        float4 sk = ((const float4*)g_skip)[i];
        o.x = o.x * inv + sk.x;
        o.y = o.y * inv + sk.y;
        o.z = o.z * inv + sk.z;
        o.w = o.w * inv + sk.w;
        ((float4*)out)[i] = o;
    }
}

// ---------------------------------------------------------------------------
extern "C" void kernel_launch(void* const* d_in, const int* in_sizes, int n_in,
                              void* d_out, int out_size)
{
    const float* x     = (const float*)d_in[0];
    const float* lu    = (const float*)d_in[1];
    const float* t     = (const float*)d_in[2];
    const float* msg   = (const float*)d_in[3];
    const int*   ei    = (const int*)d_in[4];     // int32 (JAX x64 disabled)
    const float* Wtime = (const float*)d_in[5];
    const float* btime = (const float*)d_in[6];
    const float* Wq = (const float*)d_in[7];  const float* bq = (const float*)d_in[8];
    const float* Wk = (const float*)d_in[9];  const float* bk = (const float*)d_in[10];
    const float* Wv = (const float*)d_in[11]; const float* bv = (const float*)d_in[12];
    const float* We = (const float*)d_in[13]; const float* be = (const float*)d_in[14];
    const float* Wsk = (const float*)d_in[15]; const float* bsk = (const float*)d_in[16];
    float* out = (float*)d_out;

    cudaFuncSetAttribute(proj_f16, cudaFuncAttributeMaxDynamicSharedMemorySize, PROJ_SMEM_BYTES);
    cudaFuncSetAttribute(edge_kernel_mma, cudaFuncAttributeMaxDynamicSharedMemorySize, EDGE_SMEM_BYTES);

    zero_kernel<<<2048, 256>>>(out);

    dim3 pgrid((NN + 127) / 128, 4);
    proj_f16<<<pgrid, 256, PROJ_SMEM_BYTES>>>(x, Wq, bq, Wk, bk, Wv, bv, Wsk, bsk);

    edge_kernel_mma<<<NCTA, 256, EDGE_SMEM_BYTES>>>(lu, t, msg, ei, Wtime, btime, We, be, out);

    finalize_kernel<<<2048, 256>>>(out);
}

// round 12
// speedup vs baseline: 3.3557x; 1.1871x over previous
#include <cuda_runtime.h>
#include <cuda_fp16.h>
#include <math.h>
#include <stdint.h>

#define NN   50000
#define EE   800000
#define IND  128
#define OUTD 128
#define TILES_PER_CTA 2
#define NTILES (EE / 128)                 // 6250
#define NCTA   (NTILES / TILES_PER_CTA)   // 3125

#define AH_STRIDE 52    // edge attr row stride in half2 words
#define WH_STRIDE 136   // WeH / WsH k2-row stride in half2 words
#define ESH 68          // estage row stride in half2 words
#define XH_STRIDE 68    // proj x row stride in half2 words

// ---- scratch (static device arrays; no allocation) ----
__device__ uint32_t g_qh[NN * 64];   // q as half2 words (64 words = 128 halfs/node)
__device__ uint32_t g_kh[NN * 64];
__device__ uint32_t g_vh[NN * 64];
__device__ float    g_skip[NN * OUTD];
__device__ float    g_denom[NN * 2];

extern __shared__ float smem_dyn[];

__device__ __forceinline__ void mma_f16(float* d, const uint32_t* a, const uint32_t* b) {
    asm volatile("mma.sync.aligned.m16n8k16.row.col.f32.f16.f16.f32 "
                 "{%0,%1,%2,%3}, {%4,%5,%6,%7}, {%8,%9}, {%0,%1,%2,%3};"
                 : "+f"(d[0]), "+f"(d[1]), "+f"(d[2]), "+f"(d[3])
                 : "r"(a[0]), "r"(a[1]), "r"(a[2]), "r"(a[3]), "r"(b[0]), "r"(b[1]));
}
__device__ __forceinline__ uint32_t h2u(float a, float b) {
    __half2 h = __floats2half2_rn(a, b);
    return *(uint32_t*)&h;
}
__device__ __forceinline__ float2 u2f(uint32_t u) {
    return __half22float2(*(__half2*)&u);
}

// ---------------------------------------------------------------------------
// K0: zero d_out and denominators
// ---------------------------------------------------------------------------
__global__ void zero_kernel(float* __restrict__ out) {
    int idx = blockIdx.x * blockDim.x + threadIdx.x;
    int stride = gridDim.x * blockDim.x;
    const int total4 = NN * OUTD / 4;
    for (int i = idx; i < total4; i += stride)
        ((float4*)out)[i] = make_float4(0.f, 0.f, 0.f, 0.f);
    for (int i = idx; i < NN * 2; i += stride)
        g_denom[i] = 0.f;
}

// ---------------------------------------------------------------------------
// K1: node projections via fp16 m16n8k16. q/k/v stored as half2; skip as fp32.
// ---------------------------------------------------------------------------
#define PROJ_SMEM_BYTES ((128 * XH_STRIDE + 64 * WH_STRIDE) * 4)

__global__ __launch_bounds__(256, 2) void proj_f16(
    const float* __restrict__ x,
    const float* __restrict__ Wq, const float* __restrict__ bq,
    const float* __restrict__ Wk, const float* __restrict__ bk,
    const float* __restrict__ Wv, const float* __restrict__ bv,
    const float* __restrict__ Wsk, const float* __restrict__ bsk)
{
    uint32_t* xsH = (uint32_t*)smem_dyn;                     // [128][68]
    uint32_t* WsH = (uint32_t*)smem_dyn + 128 * XH_STRIDE;   // [64][136]

    const float* W; const float* bias;
    uint32_t* outh = 0; float* outf = 0;
    switch (blockIdx.y) {
        case 0:  W = Wq;  bias = bq;  outh = g_qh;   break;
        case 1:  W = Wk;  bias = bk;  outh = g_kh;   break;
        case 2:  W = Wv;  bias = bv;  outh = g_vh;   break;
        default: W = Wsk; bias = bsk; outf = g_skip; break;
    }

    int tid  = threadIdx.x;
    int w    = tid >> 5;
    int lane = tid & 31;
    int g = lane >> 2, c = lane & 3;
    int row0 = blockIdx.x * 128;

    for (int i = tid; i < 64 * 128; i += 256) {
        int k2 = i >> 7, n = i & 127;
        float w0 = W[(2 * k2) * 128 + n];
        float w1 = W[(2 * k2 + 1) * 128 + n];
        WsH[k2 * WH_STRIDE + n] = h2u(w0, w1);
    }
    for (int i = tid; i < 128 * 32; i += 256) {
        int r = i >> 5, j = i & 31;
        int gr = row0 + r;
        float4 v = make_float4(0.f, 0.f, 0.f, 0.f);
        if (gr < NN) v = ((const float4*)x)[(size_t)gr * 32 + j];
        uint2 u = make_uint2(h2u(v.x, v.y), h2u(v.z, v.w));
        *(uint2*)&xsH[r * XH_STRIDE + 2 * j] = u;
    }
    __syncthreads();

    float acc[16][4];
    #pragma unroll
    for (int j = 0; j < 16; j++) {
        acc[j][0] = 0.f; acc[j][1] = 0.f; acc[j][2] = 0.f; acc[j][3] = 0.f;
    }
    const uint32_t* a0p = xsH + (w * 16 + g) * XH_STRIDE;
    const uint32_t* a1p = a0p + 8 * XH_STRIDE;
    #pragma unroll
    for (int kk = 0; kk < 8; kk++) {
        uint32_t af[4];
        af[0] = a0p[kk * 8 + c];
        af[1] = a1p[kk * 8 + c];
        af[2] = a0p[kk * 8 + c + 4];
        af[3] = a1p[kk * 8 + c + 4];
        const uint32_t* b0p = WsH + (kk * 8 + c) * WH_STRIDE + g;
        const uint32_t* b4p = b0p + 4 * WH_STRIDE;
        #pragma unroll
        for (int j = 0; j < 16; j++) {
            uint32_t bf[2];
            bf[0] = b0p[j * 8];
            bf[1] = b4p[j * 8];
            mma_f16(acc[j], af, bf);
        }
    }

    int r0 = row0 + w * 16 + g;
    int r1 = r0 + 8;
    if (outh) {
        #pragma unroll
        for (int j = 0; j < 16; j++) {
            int col = j * 8 + 2 * c;
            float b0 = bias[col], b1 = bias[col + 1];
            if (r0 < NN) outh[(size_t)r0 * 64 + j * 4 + c] = h2u(acc[j][0] + b0, acc[j][1] + b1);
            if (r1 < NN) outh[(size_t)r1 * 64 + j * 4 + c] = h2u(acc[j][2] + b0, acc[j][3] + b1);
        }
    } else {
        #pragma unroll
        for (int j = 0; j < 16; j++) {
            int col = j * 8 + 2 * c;
            float b0 = bias[col], b1 = bias[col + 1];
            if (r0 < NN) {
                float2 o = make_float2(acc[j][0] + b0, acc[j][1] + b1);
                *(float2*)&outf[(size_t)r0 * 128 + col] = o;
            }
            if (r1 < NN) {
                float2 o = make_float2(acc[j][2] + b0, acc[j][3] + b1);
                *(float2*)&outf[(size_t)r1 * 128 + col] = o;
            }
        }
    }
}

// ---------------------------------------------------------------------------
// K2: edge kernel — fp16 e-GEMM + single-pass dual-head consume, half gathers
// ---------------------------------------------------------------------------
#define EDGE_SMEM_BYTES (22272 * 4)

__global__ __launch_bounds__(256, 2) void edge_kernel_mma(
    const float* __restrict__ lu, const float* __restrict__ tt,
    const float* __restrict__ msg, const int* __restrict__ ei,
    const float* __restrict__ Wtime, const float* __restrict__ btime,
    const float* __restrict__ We, const float* __restrict__ be,
    float* __restrict__ out)
{
    int*      srcS  = (int*)smem_dyn;
    int*      dstS  = (int*)smem_dyn + 128;
    float*    relS  = smem_dyn + 256;
    uint32_t* attrH = (uint32_t*)smem_dyn + 384;
    uint32_t* WeH   = (uint32_t*)smem_dyn + 7040;
    uint32_t* estageH = (uint32_t*)smem_dyn + 13568;

    int tid = threadIdx.x;
    int w    = tid >> 5;
    int lane = tid & 31;
    int g = lane >> 2, c = lane & 3;

    for (int i = tid; i < 48 * 128; i += 256) {
        int k2 = i >> 7, n = i & 127;
        float w0 = We[(2 * k2) * 128 + n];
        float w1 = We[(2 * k2 + 1) * 128 + n];
        WeH[k2 * WH_STRIDE + n] = h2u(w0, w1);
    }

    int tx = tid & 7;
    int ey = tid >> 3;

    float be0[8], be1[8];
    #pragma unroll
    for (int j = 0; j < 8; j++) {
        be0[j] = be[tx * 8 + j];
        be1[j] = be[64 + tx * 8 + j];
    }

    for (int t = 0; t < TILES_PER_CTA; t++) {
        int eb = (blockIdx.x * TILES_PER_CTA + t) * 128;

        __syncthreads();
        if (tid < 128) {
            int e = eb + tid;
            int s = ei[e];
            srcS[tid] = s;
            dstS[tid] = ei[EE + e];
            relS[tid] = lu[s] - tt[e];
        }
        __syncthreads();

        for (int i = tid; i < 128 * 16; i += 256) {
            int row = i >> 4, kp = i & 15;
            float rel = relS[row];
            float v0 = __cosf(rel * Wtime[2 * kp]     + btime[2 * kp]);
            float v1 = __cosf(rel * Wtime[2 * kp + 1] + btime[2 * kp + 1]);
            attrH[row * AH_STRIDE + kp] = h2u(v0, v1);
        }
        for (int i = tid; i < 128 * 16; i += 256) {
            int row = i >> 4, j = i & 15;
            float4 m = ((const float4*)msg)[(size_t)(eb + row) * 16 + j];
            uint2 u = make_uint2(h2u(m.x, m.y), h2u(m.z, m.w));
            *(uint2*)&attrH[row * AH_STRIDE + 16 + 2 * j] = u;
        }
        __syncthreads();

        float acc[16][4];
        #pragma unroll
        for (int j = 0; j < 16; j++) {
            acc[j][0] = 0.f; acc[j][1] = 0.f; acc[j][2] = 0.f; acc[j][3] = 0.f;
        }
        const uint32_t* a0p = attrH + (w * 16 + g) * AH_STRIDE;
        const uint32_t* a1p = a0p + 8 * AH_STRIDE;
        #pragma unroll
        for (int kk = 0; kk < 6; kk++) {
            uint32_t af[4];
            af[0] = a0p[kk * 8 + c];
            af[1] = a1p[kk * 8 + c];
            af[2] = a0p[kk * 8 + c + 4];
            af[3] = a1p[kk * 8 + c + 4];
            const uint32_t* b0p = WeH + (kk * 8 + c) * WH_STRIDE + g;
            const uint32_t* b4p = b0p + 4 * WH_STRIDE;
            #pragma unroll
            for (int j = 0; j < 16; j++) {
                uint32_t bf[2];
                bf[0] = b0p[j * 8];
                bf[1] = b4p[j * 8];
                mma_f16(acc[j], af, bf);
            }
        }

        #pragma unroll
        for (int j = 0; j < 16; j++) {
            estageH[(w * 16 + g)     * ESH + j * 4 + c] = h2u(acc[j][0], acc[j][1]);
            estageH[(w * 16 + g + 8) * ESH + j * 4 + c] = h2u(acc[j][2], acc[j][3]);
        }
        __syncthreads();

        #pragma unroll
        for (int m4 = 0; m4 < 4; m4++) {
            int el = ey + 32 * m4;
            int s = srcS[el], d = dstS[el];

            // gathers: 16B per head per array (half2 packed)
            const uint32_t* qp = &g_qh[(size_t)d * 64 + tx * 4];
            const uint32_t* kp = &g_kh[(size_t)s * 64 + tx * 4];
            const uint32_t* vp = &g_vh[(size_t)s * 64 + tx * 4];
            uint4 qu0 = *(const uint4*)qp,        qu1 = *(const uint4*)(qp + 32);
            uint4 ku0 = *(const uint4*)kp,        ku1 = *(const uint4*)(kp + 32);
            uint4 vu0 = *(const uint4*)vp,        vu1 = *(const uint4*)(vp + 32);
            uint4 eu0 = *(uint4*)&estageH[el * ESH + tx * 4];
            uint4 eu1 = *(uint4*)&estageH[el * ESH + 32 + tx * 4];

            float ev0[8], ev1[8];
            {
                float2 f;
                f = u2f(eu0.x); ev0[0] = f.x + be0[0]; ev0[1] = f.y + be0[1];
                f = u2f(eu0.y); ev0[2] = f.x + be0[2]; ev0[3] = f.y + be0[3];
                f = u2f(eu0.z); ev0[4] = f.x + be0[4]; ev0[5] = f.y + be0[5];
                f = u2f(eu0.w); ev0[6] = f.x + be0[6]; ev0[7] = f.y + be0[7];
                f = u2f(eu1.x); ev1[0] = f.x + be1[0]; ev1[1] = f.y + be1[1];
                f = u2f(eu1.y); ev1[2] = f.x + be1[2]; ev1[3] = f.y + be1[3];
                f = u2f(eu1.z); ev1[4] = f.x + be1[4]; ev1[5] = f.y + be1[5];
                f = u2f(eu1.w); ev1[6] = f.x + be1[6]; ev1[7] = f.y + be1[7];
            }
            float q0[8], q1[8], k0[8], k1[8], v0[8], v1[8];
            {
                float2 f;
                f = u2f(qu0.x); q0[0]=f.x; q0[1]=f.y;  f = u2f(qu0.y); q0[2]=f.x; q0[3]=f.y;
                f = u2f(qu0.z); q0[4]=f.x; q0[5]=f.y;  f = u2f(qu0.w); q0[6]=f.x; q0[7]=f.y;
                f = u2f(qu1.x); q1[0]=f.x; q1[1]=f.y;  f = u2f(qu1.y); q1[2]=f.x; q1[3]=f.y;
                f = u2f(qu1.z); q1[4]=f.x; q1[5]=f.y;  f = u2f(qu1.w); q1[6]=f.x; q1[7]=f.y;
                f = u2f(ku0.x); k0[0]=f.x; k0[1]=f.y;  f = u2f(ku0.y); k0[2]=f.x; k0[3]=f.y;
                f = u2f(ku0.z); k0[4]=f.x; k0[5]=f.y;  f = u2f(ku0.w); k0[6]=f.x; k0[7]=f.y;
                f = u2f(ku1.x); k1[0]=f.x; k1[1]=f.y;  f = u2f(ku1.y); k1[2]=f.x; k1[3]=f.y;
                f = u2f(ku1.z); k1[4]=f.x; k1[5]=f.y;  f = u2f(ku1.w); k1[6]=f.x; k1[7]=f.y;
                f = u2f(vu0.x); v0[0]=f.x; v0[1]=f.y;  f = u2f(vu0.y); v0[2]=f.x; v0[3]=f.y;
                f = u2f(vu0.z); v0[4]=f.x; v0[5]=f.y;  f = u2f(vu0.w); v0[6]=f.x; v0[7]=f.y;
                f = u2f(vu1.x); v1[0]=f.x; v1[1]=f.y;  f = u2f(vu1.y); v1[2]=f.x; v1[3]=f.y;
                f = u2f(vu1.z); v1[4]=f.x; v1[5]=f.y;  f = u2f(vu1.w); v1[6]=f.x; v1[7]=f.y;
            }

            float p0 = 0.f, p1 = 0.f;
            #pragma unroll
            for (int j = 0; j < 8; j++) {
                p0 += q0[j] * (k0[j] + ev0[j]);
                p1 += q1[j] * (k1[j] + ev1[j]);
            }

            p0 += __shfl_xor_sync(0xffffffffu, p0, 1);
            p1 += __shfl_xor_sync(0xffffffffu, p1, 1);
            p0 += __shfl_xor_sync(0xffffffffu, p0, 2);
            p1 += __shfl_xor_sync(0xffffffffu, p1, 2);
            p0 += __shfl_xor_sync(0xffffffffu, p0, 4);
            p1 += __shfl_xor_sync(0xffffffffu, p1, 4);

            float ex0 = __expf(p0 * 0.125f);
            float ex1 = __expf(p1 * 0.125f);
            if (tx == 0) {
                atomicAdd(&g_denom[2 * d], ex0);
                atomicAdd(&g_denom[2 * d + 1], ex1);
            }

            float4 r0, r1, r2, r3;
            r0.x = ex0 * (v0[0] + ev0[0]); r0.y = ex0 * (v0[1] + ev0[1]);
            r0.z = ex0 * (v0[2] + ev0[2]); r0.w = ex0 * (v0[3] + ev0[3]);
            r1.x = ex0 * (v0[4] + ev0[4]); r1.y = ex0 * (v0[5] + ev0[5]);
            r1.z = ex0 * (v0[6] + ev0[6]); r1.w = ex0 * (v0[7] + ev0[7]);
            r2.x = ex1 * (v1[0] + ev1[0]); r2.y = ex1 * (v1[1] + ev1[1]);
            r2.z = ex1 * (v1[2] + ev1[2]); r2.w = ex1 * (v1[3] + ev1[3]);
            r3.x = ex1 * (v1[4] + ev1[4]); r3.y = ex1 * (v1[5] + ev1[5]);
            r3.z = ex1 * (v1[6] + ev1[6]); r3.w = ex1 * (v1[7] + ev1[7]);

            float4* op = (float4*)&out[(size_t)d * 128 + tx * 8];
            atomicAdd(op, r0);
            atomicAdd(op + 1, r1);
            atomicAdd(op + 16, r2);
            atomicAdd(op + 17, r3);
        }
    }
}

// ---------------------------------------------------------------------------
// K3: out = out / (denom + 1e-16) + skip
// ---------------------------------------------------------------------------
__global__ void finalize_kernel(float* __restrict__ out) {
    int idx = blockIdx.x * blockDim.x + threadIdx.x;
    int stride = gridDim.x * blockDim.x;
    const int total4 = NN * OUTD / 4;
    for (int i = idx; i < total4; i += stride) {
        int n = i >> 5;
        int h = (i >> 4) & 1;
        float inv = 1.0f / (g_denom[2 * n + h] + 1e-16f);
        float4 o  = ((float4*)out)[i];
        float4 sk = ((const float4*)g_skip)[i];
        o.x = o.x * inv + sk.x;
        o.y = o.y * inv + sk.y;
        o.z = o.z * inv + sk.z;
        o.w = o.w * inv + sk.w;
        ((float4*)out)[i] = o;
    }
}

// ---------------------------------------------------------------------------
extern "C" void kernel_launch(void* const* d_in, const int* in_sizes, int n_in,
                              void* d_out, int out_size)
{
    const float* x     = (const float*)d_in[0];
    const float* lu    = (const float*)d_in[1];
    const float* t     = (const float*)d_in[2];
    const float* msg   = (const float*)d_in[3];
    const int*   ei    = (const int*)d_in[4];     // int32 (JAX x64 disabled)
    const float* Wtime = (const float*)d_in[5];
    const float* btime = (const float*)d_in[6];
    const float* Wq = (const float*)d_in[7];  const float* bq = (const float*)d_in[8];
    const float* Wk = (const float*)d_in[9];  const float* bk = (const float*)d_in[10];
    const float* Wv = (const float*)d_in[11]; const float* bv = (const float*)d_in[12];
    const float* We = (const float*)d_in[13]; const float* be = (const float*)d_in[14];
    const float* Wsk = (const float*)d_in[15]; const float* bsk = (const float*)d_in[16];
    float* out = (float*)d_out;

    cudaFuncSetAttribute(proj_f16, cudaFuncAttributeMaxDynamicSharedMemorySize, PROJ_SMEM_BYTES);
    cudaFuncSetAttribute(edge_kernel_mma, cudaFuncAttributeMaxDynamicSharedMemorySize, EDGE_SMEM_BYTES);

    zero_kernel<<<2048, 256>>>(out);

    dim3 pgrid((NN + 127) / 128, 4);
    proj_f16<<<pgrid, 256, PROJ_SMEM_BYTES>>>(x, Wq, bq, Wk, bk, Wv, bv, Wsk, bsk);

    edge_kernel_mma<<<NCTA, 256, EDGE_SMEM_BYTES>>>(lu, t, msg, ei, Wtime, btime, We, be, out);

    finalize_kernel<<<2048, 256>>>(out);
}

// round 13
// speedup vs baseline: 3.7651x; 1.1220x over previous
#include <cuda_runtime.h>
#include <cuda_fp16.h>
#include <math.h>
#include <stdint.h>

#define NN   50000
#define EE   800000
#define IND  128
#define OUTD 128
#define TILES_PER_CTA 2
#define NTILES (EE / 128)                 // 6250
#define NCTA   (NTILES / TILES_PER_CTA)   // 3125

#define AH_STRIDE 52    // edge attr row stride in half2 words
#define WH_STRIDE 136   // WeH / WsH k2-row stride in half2 words
#define ESH 68          // estage row stride in half2 words
#define XH_STRIDE 68    // proj x row stride in half2 words

#define LAMBDA 0.0625f  // softmax scale shift (cancels in normalization)

// ---- scratch (static device arrays; no allocation) ----
__device__ uint32_t g_qh[NN * 64];   // q as half2 words
__device__ uint32_t g_kh[NN * 64];
__device__ uint32_t g_vh[NN * 64];
__device__ uint32_t g_outh[NN * 64]; // unnormalized attention accum (half2)
__device__ float    g_skip[NN * OUTD];
__device__ float    g_denom[NN * 2];

extern __shared__ float smem_dyn[];

__device__ __forceinline__ void mma_f16(float* d, const uint32_t* a, const uint32_t* b) {
    asm volatile("mma.sync.aligned.m16n8k16.row.col.f32.f16.f16.f32 "
                 "{%0,%1,%2,%3}, {%4,%5,%6,%7}, {%8,%9}, {%0,%1,%2,%3};"
                 : "+f"(d[0]), "+f"(d[1]), "+f"(d[2]), "+f"(d[3])
                 : "r"(a[0]), "r"(a[1]), "r"(a[2]), "r"(a[3]), "r"(b[0]), "r"(b[1]));
}
__device__ __forceinline__ uint32_t h2u(float a, float b) {
    __half2 h = __floats2half2_rn(a, b);
    return *(uint32_t*)&h;
}
__device__ __forceinline__ float2 u2f(uint32_t u) {
    return __half22float2(*(__half2*)&u);
}

// ---------------------------------------------------------------------------
// K0: zero half accumulator and denominators
// ---------------------------------------------------------------------------
__global__ void zero_kernel() {
    int idx = blockIdx.x * blockDim.x + threadIdx.x;
    int stride = gridDim.x * blockDim.x;
    const int totw4 = NN * 64 / 4;
    uint4 z = make_uint4(0, 0, 0, 0);
    for (int i = idx; i < totw4; i += stride)
        ((uint4*)g_outh)[i] = z;
    for (int i = idx; i < NN * 2; i += stride)
        g_denom[i] = 0.f;
}

// ---------------------------------------------------------------------------
// K1: node projections via fp16 m16n8k16. q/k/v stored as half2; skip as fp32.
// ---------------------------------------------------------------------------
#define PROJ_SMEM_BYTES ((128 * XH_STRIDE + 64 * WH_STRIDE) * 4)

__global__ __launch_bounds__(256, 2) void proj_f16(
    const float* __restrict__ x,
    const float* __restrict__ Wq, const float* __restrict__ bq,
    const float* __restrict__ Wk, const float* __restrict__ bk,
    const float* __restrict__ Wv, const float* __restrict__ bv,
    const float* __restrict__ Wsk, const float* __restrict__ bsk)
{
    uint32_t* xsH = (uint32_t*)smem_dyn;                     // [128][68]
    uint32_t* WsH = (uint32_t*)smem_dyn + 128 * XH_STRIDE;   // [64][136]

    const float* W; const float* bias;
    uint32_t* outh = 0; float* outf = 0;
    switch (blockIdx.y) {
        case 0:  W = Wq;  bias = bq;  outh = g_qh;   break;
        case 1:  W = Wk;  bias = bk;  outh = g_kh;   break;
        case 2:  W = Wv;  bias = bv;  outh = g_vh;   break;
        default: W = Wsk; bias = bsk; outf = g_skip; break;
    }

    int tid  = threadIdx.x;
    int w    = tid >> 5;
    int lane = tid & 31;
    int g = lane >> 2, c = lane & 3;
    int row0 = blockIdx.x * 128;

    for (int i = tid; i < 64 * 128; i += 256) {
        int k2 = i >> 7, n = i & 127;
        float w0 = W[(2 * k2) * 128 + n];
        float w1 = W[(2 * k2 + 1) * 128 + n];
        WsH[k2 * WH_STRIDE + n] = h2u(w0, w1);
    }
    for (int i = tid; i < 128 * 32; i += 256) {
        int r = i >> 5, j = i & 31;
        int gr = row0 + r;
        float4 v = make_float4(0.f, 0.f, 0.f, 0.f);
        if (gr < NN) v = ((const float4*)x)[(size_t)gr * 32 + j];
        uint2 u = make_uint2(h2u(v.x, v.y), h2u(v.z, v.w));
        *(uint2*)&xsH[r * XH_STRIDE + 2 * j] = u;
    }
    __syncthreads();

    float acc[16][4];
    #pragma unroll
    for (int j = 0; j < 16; j++) {
        acc[j][0] = 0.f; acc[j][1] = 0.f; acc[j][2] = 0.f; acc[j][3] = 0.f;
    }
    const uint32_t* a0p = xsH + (w * 16 + g) * XH_STRIDE;
    const uint32_t* a1p = a0p + 8 * XH_STRIDE;
    #pragma unroll
    for (int kk = 0; kk < 8; kk++) {
        uint32_t af[4];
        af[0] = a0p[kk * 8 + c];
        af[1] = a1p[kk * 8 + c];
        af[2] = a0p[kk * 8 + c + 4];
        af[3] = a1p[kk * 8 + c + 4];
        const uint32_t* b0p = WsH + (kk * 8 + c) * WH_STRIDE + g;
        const uint32_t* b4p = b0p + 4 * WH_STRIDE;
        #pragma unroll
        for (int j = 0; j < 16; j++) {
            uint32_t bf[2];
            bf[0] = b0p[j * 8];
            bf[1] = b4p[j * 8];
            mma_f16(acc[j], af, bf);
        }
    }

    int r0 = row0 + w * 16 + g;
    int r1 = r0 + 8;
    if (outh) {
        #pragma unroll
        for (int j = 0; j < 16; j++) {
            int col = j * 8 + 2 * c;
            float b0 = bias[col], b1 = bias[col + 1];
            if (r0 < NN) outh[(size_t)r0 * 64 + j * 4 + c] = h2u(acc[j][0] + b0, acc[j][1] + b1);
            if (r1 < NN) outh[(size_t)r1 * 64 + j * 4 + c] = h2u(acc[j][2] + b0, acc[j][3] + b1);
        }
    } else {
        #pragma unroll
        for (int j = 0; j < 16; j++) {
            int col = j * 8 + 2 * c;
            float b0 = bias[col], b1 = bias[col + 1];
            if (r0 < NN) {
                float2 o = make_float2(acc[j][0] + b0, acc[j][1] + b1);
                *(float2*)&outf[(size_t)r0 * 128 + col] = o;
            }
            if (r1 < NN) {
                float2 o = make_float2(acc[j][2] + b0, acc[j][3] + b1);
                *(float2*)&outf[(size_t)r1 * 128 + col] = o;
            }
        }
    }
}

// ---------------------------------------------------------------------------
// K2: edge kernel — fp16 e-GEMM, half gathers, f16x2 vector-RED scatter
// ---------------------------------------------------------------------------
#define EDGE_SMEM_BYTES (22272 * 4)

__global__ __launch_bounds__(256, 2) void edge_kernel_mma(
    const float* __restrict__ lu, const float* __restrict__ tt,
    const float* __restrict__ msg, const int* __restrict__ ei,
    const float* __restrict__ Wtime, const float* __restrict__ btime,
    const float* __restrict__ We, const float* __restrict__ be)
{
    int*      srcS  = (int*)smem_dyn;
    int*      dstS  = (int*)smem_dyn + 128;
    float*    relS  = smem_dyn + 256;
    uint32_t* attrH = (uint32_t*)smem_dyn + 384;
    uint32_t* WeH   = (uint32_t*)smem_dyn + 7040;
    uint32_t* estageH = (uint32_t*)smem_dyn + 13568;

    int tid = threadIdx.x;
    int w    = tid >> 5;
    int lane = tid & 31;
    int g = lane >> 2, c = lane & 3;

    for (int i = tid; i < 48 * 128; i += 256) {
        int k2 = i >> 7, n = i & 127;
        float w0 = We[(2 * k2) * 128 + n];
        float w1 = We[(2 * k2 + 1) * 128 + n];
        WeH[k2 * WH_STRIDE + n] = h2u(w0, w1);
    }

    int tx = tid & 7;
    int ey = tid >> 3;

    float be0[8], be1[8];
    #pragma unroll
    for (int j = 0; j < 8; j++) {
        be0[j] = be[tx * 8 + j];
        be1[j] = be[64 + tx * 8 + j];
    }

    for (int t = 0; t < TILES_PER_CTA; t++) {
        int eb = (blockIdx.x * TILES_PER_CTA + t) * 128;

        __syncthreads();
        if (tid < 128) {
            int e = eb + tid;
            int s = ei[e];
            srcS[tid] = s;
            dstS[tid] = ei[EE + e];
            relS[tid] = lu[s] - tt[e];
        }
        __syncthreads();

        for (int i = tid; i < 128 * 16; i += 256) {
            int row = i >> 4, kp = i & 15;
            float rel = relS[row];
            float v0 = __cosf(rel * Wtime[2 * kp]     + btime[2 * kp]);
            float v1 = __cosf(rel * Wtime[2 * kp + 1] + btime[2 * kp + 1]);
            attrH[row * AH_STRIDE + kp] = h2u(v0, v1);
        }
        for (int i = tid; i < 128 * 16; i += 256) {
            int row = i >> 4, j = i & 15;
            float4 m = ((const float4*)msg)[(size_t)(eb + row) * 16 + j];
            uint2 u = make_uint2(h2u(m.x, m.y), h2u(m.z, m.w));
            *(uint2*)&attrH[row * AH_STRIDE + 16 + 2 * j] = u;
        }
        __syncthreads();

        float acc[16][4];
        #pragma unroll
        for (int j = 0; j < 16; j++) {
            acc[j][0] = 0.f; acc[j][1] = 0.f; acc[j][2] = 0.f; acc[j][3] = 0.f;
        }
        const uint32_t* a0p = attrH + (w * 16 + g) * AH_STRIDE;
        const uint32_t* a1p = a0p + 8 * AH_STRIDE;
        #pragma unroll
        for (int kk = 0; kk < 6; kk++) {
            uint32_t af[4];
            af[0] = a0p[kk * 8 + c];
            af[1] = a1p[kk * 8 + c];
            af[2] = a0p[kk * 8 + c + 4];
            af[3] = a1p[kk * 8 + c + 4];
            const uint32_t* b0p = WeH + (kk * 8 + c) * WH_STRIDE + g;
            const uint32_t* b4p = b0p + 4 * WH_STRIDE;
            #pragma unroll
            for (int j = 0; j < 16; j++) {
                uint32_t bf[2];
                bf[0] = b0p[j * 8];
                bf[1] = b4p[j * 8];
                mma_f16(acc[j], af, bf);
            }
        }

        #pragma unroll
        for (int j = 0; j < 16; j++) {
            estageH[(w * 16 + g)     * ESH + j * 4 + c] = h2u(acc[j][0], acc[j][1]);
            estageH[(w * 16 + g + 8) * ESH + j * 4 + c] = h2u(acc[j][2], acc[j][3]);
        }
        __syncthreads();

        #pragma unroll
        for (int m4 = 0; m4 < 4; m4++) {
            int el = ey + 32 * m4;
            int s = srcS[el], d = dstS[el];

            const uint32_t* qp = &g_qh[(size_t)d * 64 + tx * 4];
            const uint32_t* kp = &g_kh[(size_t)s * 64 + tx * 4];
            const uint32_t* vp = &g_vh[(size_t)s * 64 + tx * 4];
            uint4 qu0 = *(const uint4*)qp,        qu1 = *(const uint4*)(qp + 32);
            uint4 ku0 = *(const uint4*)kp,        ku1 = *(const uint4*)(kp + 32);
            uint4 vu0 = *(const uint4*)vp,        vu1 = *(const uint4*)(vp + 32);
            uint4 eu0 = *(uint4*)&estageH[el * ESH + tx * 4];
            uint4 eu1 = *(uint4*)&estageH[el * ESH + 32 + tx * 4];

            float ev0[8], ev1[8];
            {
                float2 f;
                f = u2f(eu0.x); ev0[0] = f.x + be0[0]; ev0[1] = f.y + be0[1];
                f = u2f(eu0.y); ev0[2] = f.x + be0[2]; ev0[3] = f.y + be0[3];
                f = u2f(eu0.z); ev0[4] = f.x + be0[4]; ev0[5] = f.y + be0[5];
                f = u2f(eu0.w); ev0[6] = f.x + be0[6]; ev0[7] = f.y + be0[7];
                f = u2f(eu1.x); ev1[0] = f.x + be1[0]; ev1[1] = f.y + be1[1];
                f = u2f(eu1.y); ev1[2] = f.x + be1[2]; ev1[3] = f.y + be1[3];
                f = u2f(eu1.z); ev1[4] = f.x + be1[4]; ev1[5] = f.y + be1[5];
                f = u2f(eu1.w); ev1[6] = f.x + be1[6]; ev1[7] = f.y + be1[7];
            }
            float q0[8], q1[8], k0[8], k1[8], v0[8], v1[8];
            {
                float2 f;
                f = u2f(qu0.x); q0[0]=f.x; q0[1]=f.y;  f = u2f(qu0.y); q0[2]=f.x; q0[3]=f.y;
                f = u2f(qu0.z); q0[4]=f.x; q0[5]=f.y;  f = u2f(qu0.w); q0[6]=f.x; q0[7]=f.y;
                f = u2f(qu1.x); q1[0]=f.x; q1[1]=f.y;  f = u2f(qu1.y); q1[2]=f.x; q1[3]=f.y;
                f = u2f(qu1.z); q1[4]=f.x; q1[5]=f.y;  f = u2f(qu1.w); q1[6]=f.x; q1[7]=f.y;
                f = u2f(ku0.x); k0[0]=f.x; k0[1]=f.y;  f = u2f(ku0.y); k0[2]=f.x; k0[3]=f.y;
                f = u2f(ku0.z); k0[4]=f.x; k0[5]=f.y;  f = u2f(ku0.w); k0[6]=f.x; k0[7]=f.y;
                f = u2f(ku1.x); k1[0]=f.x; k1[1]=f.y;  f = u2f(ku1.y); k1[2]=f.x; k1[3]=f.y;
                f = u2f(ku1.z); k1[4]=f.x; k1[5]=f.y;  f = u2f(ku1.w); k1[6]=f.x; k1[7]=f.y;
                f = u2f(vu0.x); v0[0]=f.x; v0[1]=f.y;  f = u2f(vu0.y); v0[2]=f.x; v0[3]=f.y;
                f = u2f(vu0.z); v0[4]=f.x; v0[5]=f.y;  f = u2f(vu0.w); v0[6]=f.x; v0[7]=f.y;
                f = u2f(vu1.x); v1[0]=f.x; v1[1]=f.y;  f = u2f(vu1.y); v1[2]=f.x; v1[3]=f.y;
                f = u2f(vu1.z); v1[4]=f.x; v1[5]=f.y;  f = u2f(vu1.w); v1[6]=f.x; v1[7]=f.y;
            }

            float p0 = 0.f, p1 = 0.f;
            #pragma unroll
            for (int j = 0; j < 8; j++) {
                p0 += q0[j] * (k0[j] + ev0[j]);
                p1 += q1[j] * (k1[j] + ev1[j]);
            }

            p0 += __shfl_xor_sync(0xffffffffu, p0, 1);
            p1 += __shfl_xor_sync(0xffffffffu, p1, 1);
            p0 += __shfl_xor_sync(0xffffffffu, p0, 2);
            p1 += __shfl_xor_sync(0xffffffffu, p1, 2);
            p0 += __shfl_xor_sync(0xffffffffu, p0, 4);
            p1 += __shfl_xor_sync(0xffffffffu, p1, 4);

            float ex0 = __expf(p0 * 0.125f);
            float ex1 = __expf(p1 * 0.125f);
            if (tx == 0) {
                atomicAdd(&g_denom[2 * d], ex0);
                atomicAdd(&g_denom[2 * d + 1], ex1);
            }

            float s0 = ex0 * LAMBDA, s1 = ex1 * LAMBDA;
            uint32_t h00 = h2u(s0 * (v0[0] + ev0[0]), s0 * (v0[1] + ev0[1]));
            uint32_t h01 = h2u(s0 * (v0[2] + ev0[2]), s0 * (v0[3] + ev0[3]));
            uint32_t h02 = h2u(s0 * (v0[4] + ev0[4]), s0 * (v0[5] + ev0[5]));
            uint32_t h03 = h2u(s0 * (v0[6] + ev0[6]), s0 * (v0[7] + ev0[7]));
            uint32_t h10 = h2u(s1 * (v1[0] + ev1[0]), s1 * (v1[1] + ev1[1]));
            uint32_t h11 = h2u(s1 * (v1[2] + ev1[2]), s1 * (v1[3] + ev1[3]));
            uint32_t h12 = h2u(s1 * (v1[4] + ev1[4]), s1 * (v1[5] + ev1[5]));
            uint32_t h13 = h2u(s1 * (v1[6] + ev1[6]), s1 * (v1[7] + ev1[7]));

            uint32_t* op = &g_outh[(size_t)d * 64 + tx * 4];
            asm volatile("red.global.add.noftz.v4.f16x2 [%0], {%1,%2,%3,%4};"
                         :: "l"(op), "r"(h00), "r"(h01), "r"(h02), "r"(h03) : "memory");
            asm volatile("red.global.add.noftz.v4.f16x2 [%0], {%1,%2,%3,%4};"
                         :: "l"(op + 32), "r"(h10), "r"(h11), "r"(h12), "r"(h13) : "memory");
        }
    }
}

// ---------------------------------------------------------------------------
// K3: out = outh/(lambda*(denom+1e-16)) + skip
// ---------------------------------------------------------------------------
__global__ void finalize_kernel(float* __restrict__ out) {
    int idx = blockIdx.x * blockDim.x + threadIdx.x;
    int stride = gridDim.x * blockDim.x;
    const int total4 = NN * OUTD / 4;
    for (int i = idx; i < total4; i += stride) {
        int n = i >> 5;
        int gi = i & 31;
        int h = gi >> 4;
        float inv = (1.0f / LAMBDA) / (g_denom[2 * n + h] + 1e-16f);
        uint2 u = *(const uint2*)&g_outh[(size_t)n * 64 + gi * 2];
        float2 a = u2f(u.x), b = u2f(u.y);
        float4 sk = ((const float4*)g_skip)[i];
        float4 o;
        o.x = a.x * inv + sk.x;
        o.y = a.y * inv + sk.y;
        o.z = b.x * inv + sk.z;
        o.w = b.y * inv + sk.w;
        ((float4*)out)[i] = o;
    }
}

// ---------------------------------------------------------------------------
extern "C" void kernel_launch(void* const* d_in, const int* in_sizes, int n_in,
                              void* d_out, int out_size)
{
    const float* x     = (const float*)d_in[0];
    const float* lu    = (const float*)d_in[1];
    const float* t     = (const float*)d_in[2];
    const float* msg   = (const float*)d_in[3];
    const int*   ei    = (const int*)d_in[4];     // int32 (JAX x64 disabled)
    const float* Wtime = (const float*)d_in[5];
    const float* btime = (const float*)d_in[6];
    const float* Wq = (const float*)d_in[7];  const float* bq = (const float*)d_in[8];
    const float* Wk = (const float*)d_in[9];  const float* bk = (const float*)d_in[10];
    const float* Wv = (const float*)d_in[11]; const float* bv = (const float*)d_in[12];
    const float* We = (const float*)d_in[13]; const float* be = (const float*)d_in[14];
    const float* Wsk = (const float*)d_in[15]; const float* bsk = (const float*)d_in[16];
    float* out = (float*)d_out;

    cudaFuncSetAttribute(proj_f16, cudaFuncAttributeMaxDynamicSharedMemorySize, PROJ_SMEM_BYTES);
    cudaFuncSetAttribute(edge_kernel_mma, cudaFuncAttributeMaxDynamicSharedMemorySize, EDGE_SMEM_BYTES);

    zero_kernel<<<2048, 256>>>();

    dim3 pgrid((NN + 127) / 128, 4);
    proj_f16<<<pgrid, 256, PROJ_SMEM_BYTES>>>(x, Wq, bq, Wk, bk, Wv, bv, Wsk, bsk);

    edge_kernel_mma<<<NCTA, 256, EDGE_SMEM_BYTES>>>(lu, t, msg, ei, Wtime, btime, We, be);

    finalize_kernel<<<2048, 256>>>(out);
}

// round 14
// speedup vs baseline: 3.9722x; 1.0550x over previous
#include <cuda_runtime.h>
#include <cuda_fp16.h>
#include <math.h>
#include <stdint.h>

#define NN   50000
#define EE   800000
#define IND  128
#define OUTD 128
#define TILES_PER_CTA 2
#define NTILES (EE / 128)                 // 6250
#define NCTA   (NTILES / TILES_PER_CTA)   // 3125

#define AH_STRIDE 52    // edge attr row stride in half2 words
#define WH_STRIDE 136   // WeH / WsH k2-row stride in half2 words
#define ESH 68          // estage row stride in half2 words
#define XH_STRIDE 68    // proj x row stride in half2 words

#define LAMBDA 0.0625f  // softmax scale shift (cancels in normalization)

// ---- scratch (static device arrays; no allocation) ----
__device__ uint32_t g_qh[NN * 64];   // q as half2 words
__device__ uint32_t g_kh[NN * 64];
__device__ uint32_t g_vh[NN * 64];
__device__ uint32_t g_outh[NN * 64]; // unnormalized attention accum (half2)
__device__ float    g_skip[NN * OUTD];
__device__ float    g_denom[NN * 2];

extern __shared__ float smem_dyn[];

__device__ __forceinline__ void mma_f16(float* d, const uint32_t* a, const uint32_t* b) {
    asm volatile("mma.sync.aligned.m16n8k16.row.col.f32.f16.f16.f32 "
                 "{%0,%1,%2,%3}, {%4,%5,%6,%7}, {%8,%9}, {%0,%1,%2,%3};"
                 : "+f"(d[0]), "+f"(d[1]), "+f"(d[2]), "+f"(d[3])
                 : "r"(a[0]), "r"(a[1]), "r"(a[2]), "r"(a[3]), "r"(b[0]), "r"(b[1]));
}
__device__ __forceinline__ uint32_t h2u(float a, float b) {
    __half2 h = __floats2half2_rn(a, b);
    return *(uint32_t*)&h;
}
__device__ __forceinline__ float2 u2f(uint32_t u) {
    return __half22float2(*(__half2*)&u);
}
__device__ __forceinline__ uint32_t hadd2u(uint32_t a, uint32_t b) {
    __half2 r = __hadd2(*(__half2*)&a, *(__half2*)&b);
    return *(uint32_t*)&r;
}
__device__ __forceinline__ uint32_t hmul2u(uint32_t a, uint32_t b) {
    __half2 r = __hmul2(*(__half2*)&a, *(__half2*)&b);
    return *(uint32_t*)&r;
}

// ---------------------------------------------------------------------------
// K1: node projections via fp16 m16n8k16, persistent over 4 row-tiles.
// blockIdx.y==0 CTAs also zero g_outh / g_denom for their node range.
// ---------------------------------------------------------------------------
#define PROJ_SMEM_BYTES ((128 * XH_STRIDE + 64 * WH_STRIDE) * 4)

__global__ __launch_bounds__(256, 2) void proj_f16(
    const float* __restrict__ x,
    const float* __restrict__ Wq, const float* __restrict__ bq,
    const float* __restrict__ Wk, const float* __restrict__ bk,
    const float* __restrict__ Wv, const float* __restrict__ bv,
    const float* __restrict__ Wsk, const float* __restrict__ bsk)
{
    uint32_t* xsH = (uint32_t*)smem_dyn;                     // [128][68]
    uint32_t* WsH = (uint32_t*)smem_dyn + 128 * XH_STRIDE;   // [64][136]

    const float* W; const float* bias;
    uint32_t* outh = 0; float* outf = 0;
    switch (blockIdx.y) {
        case 0:  W = Wq;  bias = bq;  outh = g_qh;   break;
        case 1:  W = Wk;  bias = bk;  outh = g_kh;   break;
        case 2:  W = Wv;  bias = bv;  outh = g_vh;   break;
        default: W = Wsk; bias = bsk; outf = g_skip; break;
    }

    int tid  = threadIdx.x;
    int w    = tid >> 5;
    int lane = tid & 31;
    int g = lane >> 2, c = lane & 3;

    // Weight -> smem once per CTA
    for (int i = tid; i < 64 * 128; i += 256) {
        int k2 = i >> 7, n = i & 127;
        float w0 = W[(2 * k2) * 128 + n];
        float w1 = W[(2 * k2 + 1) * 128 + n];
        WsH[k2 * WH_STRIDE + n] = h2u(w0, w1);
    }

    // y==0 CTAs: zero accumulators for node range [bx*512, bx*512+512)
    if (blockIdx.y == 0) {
        size_t base = (size_t)blockIdx.x * 512 * 64;        // words
        size_t lim  = (size_t)NN * 64;
        for (int i = tid; i < 512 * 64 / 4; i += 256) {
            size_t wd = base + (size_t)i * 4;
            if (wd + 3 < lim)
                *(uint4*)&g_outh[wd] = make_uint4(0, 0, 0, 0);
            else
                for (int j = 0; j < 4 && wd + j < lim; j++) g_outh[wd + j] = 0;
        }
        int nb = blockIdx.x * 512;
        for (int i = tid; i < 1024; i += 256) {
            int n = nb + (i >> 1);
            if (n < NN) g_denom[2 * n + (i & 1)] = 0.f;
        }
    }

    for (int r4 = 0; r4 < 4; r4++) {
        int row0 = (blockIdx.x * 4 + r4) * 128;
        __syncthreads();        // xsH free (prev MMA reads done)

        for (int i = tid; i < 128 * 32; i += 256) {
            int r = i >> 5, j = i & 31;
            int gr = row0 + r;
            float4 v = make_float4(0.f, 0.f, 0.f, 0.f);
            if (gr < NN) v = ((const float4*)x)[(size_t)gr * 32 + j];
            uint2 u = make_uint2(h2u(v.x, v.y), h2u(v.z, v.w));
            *(uint2*)&xsH[r * XH_STRIDE + 2 * j] = u;
        }
        __syncthreads();

        float acc[16][4];
        #pragma unroll
        for (int j = 0; j < 16; j++) {
            acc[j][0] = 0.f; acc[j][1] = 0.f; acc[j][2] = 0.f; acc[j][3] = 0.f;
        }
        const uint32_t* a0p = xsH + (w * 16 + g) * XH_STRIDE;
        const uint32_t* a1p = a0p + 8 * XH_STRIDE;
        #pragma unroll
        for (int kk = 0; kk < 8; kk++) {
            uint32_t af[4];
            af[0] = a0p[kk * 8 + c];
            af[1] = a1p[kk * 8 + c];
            af[2] = a0p[kk * 8 + c + 4];
            af[3] = a1p[kk * 8 + c + 4];
            const uint32_t* b0p = WsH + (kk * 8 + c) * WH_STRIDE + g;
            const uint32_t* b4p = b0p + 4 * WH_STRIDE;
            #pragma unroll
            for (int j = 0; j < 16; j++) {
                uint32_t bf[2];
                bf[0] = b0p[j * 8];
                bf[1] = b4p[j * 8];
                mma_f16(acc[j], af, bf);
            }
        }

        int r0 = row0 + w * 16 + g;
        int r1 = r0 + 8;
        if (outh) {
            #pragma unroll
            for (int j = 0; j < 16; j++) {
                int col = j * 8 + 2 * c;
                float b0 = bias[col], b1 = bias[col + 1];
                if (r0 < NN) outh[(size_t)r0 * 64 + j * 4 + c] = h2u(acc[j][0] + b0, acc[j][1] + b1);
                if (r1 < NN) outh[(size_t)r1 * 64 + j * 4 + c] = h2u(acc[j][2] + b0, acc[j][3] + b1);
            }
        } else {
            #pragma unroll
            for (int j = 0; j < 16; j++) {
                int col = j * 8 + 2 * c;
                float b0 = bias[col], b1 = bias[col + 1];
                if (r0 < NN) {
                    float2 o = make_float2(acc[j][0] + b0, acc[j][1] + b1);
                    *(float2*)&outf[(size_t)r0 * 128 + col] = o;
                }
                if (r1 < NN) {
                    float2 o = make_float2(acc[j][2] + b0, acc[j][3] + b1);
                    *(float2*)&outf[(size_t)r1 * 128 + col] = o;
                }
            }
        }
    }
}

// ---------------------------------------------------------------------------
// K2: edge kernel — fp16 e-GEMM, half gathers, half2 value path, f16x2 REDs
// ---------------------------------------------------------------------------
#define EDGE_SMEM_BYTES (22272 * 4)

__global__ __launch_bounds__(256, 2) void edge_kernel_mma(
    const float* __restrict__ lu, const float* __restrict__ tt,
    const float* __restrict__ msg, const int* __restrict__ ei,
    const float* __restrict__ Wtime, const float* __restrict__ btime,
    const float* __restrict__ We, const float* __restrict__ be)
{
    int*      srcS  = (int*)smem_dyn;
    int*      dstS  = (int*)smem_dyn + 128;
    float*    relS  = smem_dyn + 256;
    uint32_t* attrH = (uint32_t*)smem_dyn + 384;
    uint32_t* WeH   = (uint32_t*)smem_dyn + 7040;
    uint32_t* estageH = (uint32_t*)smem_dyn + 13568;

    int tid = threadIdx.x;
    int w    = tid >> 5;
    int lane = tid & 31;
    int g = lane >> 2, c = lane & 3;

    for (int i = tid; i < 48 * 128; i += 256) {
        int k2 = i >> 7, n = i & 127;
        float w0 = We[(2 * k2) * 128 + n];
        float w1 = We[(2 * k2 + 1) * 128 + n];
        WeH[k2 * WH_STRIDE + n] = h2u(w0, w1);
    }

    int tx = tid & 7;
    int ey = tid >> 3;

    // biases as half2 words
    uint32_t beh0[4], beh1[4];
    #pragma unroll
    for (int j = 0; j < 4; j++) {
        beh0[j] = h2u(be[tx * 8 + 2 * j], be[tx * 8 + 2 * j + 1]);
        beh1[j] = h2u(be[64 + tx * 8 + 2 * j], be[64 + tx * 8 + 2 * j + 1]);
    }

    for (int t = 0; t < TILES_PER_CTA; t++) {
        int eb = (blockIdx.x * TILES_PER_CTA + t) * 128;

        __syncthreads();
        if (tid < 128) {
            int e = eb + tid;
            int s = ei[e];
            srcS[tid] = s;
            dstS[tid] = ei[EE + e];
            relS[tid] = lu[s] - tt[e];
        }
        __syncthreads();

        for (int i = tid; i < 128 * 16; i += 256) {
            int row = i >> 4, kp = i & 15;
            float rel = relS[row];
            float v0 = __cosf(rel * Wtime[2 * kp]     + btime[2 * kp]);
            float v1 = __cosf(rel * Wtime[2 * kp + 1] + btime[2 * kp + 1]);
            attrH[row * AH_STRIDE + kp] = h2u(v0, v1);
        }
        for (int i = tid; i < 128 * 16; i += 256) {
            int row = i >> 4, j = i & 15;
            float4 m = ((const float4*)msg)[(size_t)(eb + row) * 16 + j];
            uint2 u = make_uint2(h2u(m.x, m.y), h2u(m.z, m.w));
            *(uint2*)&attrH[row * AH_STRIDE + 16 + 2 * j] = u;
        }
        __syncthreads();

        float acc[16][4];
        #pragma unroll
        for (int j = 0; j < 16; j++) {
            acc[j][0] = 0.f; acc[j][1] = 0.f; acc[j][2] = 0.f; acc[j][3] = 0.f;
        }
        const uint32_t* a0p = attrH + (w * 16 + g) * AH_STRIDE;
        const uint32_t* a1p = a0p + 8 * AH_STRIDE;
        #pragma unroll
        for (int kk = 0; kk < 6; kk++) {
            uint32_t af[4];
            af[0] = a0p[kk * 8 + c];
            af[1] = a1p[kk * 8 + c];
            af[2] = a0p[kk * 8 + c + 4];
            af[3] = a1p[kk * 8 + c + 4];
            const uint32_t* b0p = WeH + (kk * 8 + c) * WH_STRIDE + g;
            const uint32_t* b4p = b0p + 4 * WH_STRIDE;
            #pragma unroll
            for (int j = 0; j < 16; j++) {
                uint32_t bf[2];
                bf[0] = b0p[j * 8];
                bf[1] = b4p[j * 8];
                mma_f16(acc[j], af, bf);
            }
        }

        #pragma unroll
        for (int j = 0; j < 16; j++) {
            estageH[(w * 16 + g)     * ESH + j * 4 + c] = h2u(acc[j][0], acc[j][1]);
            estageH[(w * 16 + g + 8) * ESH + j * 4 + c] = h2u(acc[j][2], acc[j][3]);
        }
        __syncthreads();

        #pragma unroll
        for (int m4 = 0; m4 < 4; m4++) {
            int el = ey + 32 * m4;
            int s = srcS[el], d = dstS[el];

            const uint32_t* qp = &g_qh[(size_t)d * 64 + tx * 4];
            const uint32_t* kp = &g_kh[(size_t)s * 64 + tx * 4];
            const uint32_t* vp = &g_vh[(size_t)s * 64 + tx * 4];
            uint4 qu0 = *(const uint4*)qp,        qu1 = *(const uint4*)(qp + 32);
            uint4 ku0 = *(const uint4*)kp,        ku1 = *(const uint4*)(kp + 32);
            uint4 vu0 = *(const uint4*)vp,        vu1 = *(const uint4*)(vp + 32);
            uint4 eu0 = *(uint4*)&estageH[el * ESH + tx * 4];
            uint4 eu1 = *(uint4*)&estageH[el * ESH + 32 + tx * 4];

            // ev (= e + be) in half2
            uint32_t ev0h[4], ev1h[4];
            ev0h[0] = hadd2u(eu0.x, beh0[0]); ev0h[1] = hadd2u(eu0.y, beh0[1]);
            ev0h[2] = hadd2u(eu0.z, beh0[2]); ev0h[3] = hadd2u(eu0.w, beh0[3]);
            ev1h[0] = hadd2u(eu1.x, beh1[0]); ev1h[1] = hadd2u(eu1.y, beh1[1]);
            ev1h[2] = hadd2u(eu1.z, beh1[2]); ev1h[3] = hadd2u(eu1.w, beh1[3]);

            // logits in fp32
            float p0 = 0.f, p1 = 0.f;
            {
                const uint32_t* qw0 = (const uint32_t*)&qu0;
                const uint32_t* kw0 = (const uint32_t*)&ku0;
                const uint32_t* qw1 = (const uint32_t*)&qu1;
                const uint32_t* kw1 = (const uint32_t*)&ku1;
                #pragma unroll
                for (int j = 0; j < 4; j++) {
                    float2 qf = u2f(qw0[j]), kf = u2f(kw0[j]), ef = u2f(ev0h[j]);
                    p0 += qf.x * (kf.x + ef.x) + qf.y * (kf.y + ef.y);
                    float2 qg = u2f(qw1[j]), kg = u2f(kw1[j]), eg = u2f(ev1h[j]);
                    p1 += qg.x * (kg.x + eg.x) + qg.y * (kg.y + eg.y);
                }
            }

            p0 += __shfl_xor_sync(0xffffffffu, p0, 1);
            p1 += __shfl_xor_sync(0xffffffffu, p1, 1);
            p0 += __shfl_xor_sync(0xffffffffu, p0, 2);
            p1 += __shfl_xor_sync(0xffffffffu, p1, 2);
            p0 += __shfl_xor_sync(0xffffffffu, p0, 4);
            p1 += __shfl_xor_sync(0xffffffffu, p1, 4);

            float ex0 = __expf(p0 * 0.125f);
            float ex1 = __expf(p1 * 0.125f);
            if (tx == 0)
                atomicAdd((float2*)&g_denom[2 * d], make_float2(ex0, ex1));

            // value path in half2: r = s * (v + ev)
            __half2 s0h = __float2half2_rn(ex0 * LAMBDA);
            __half2 s1h = __float2half2_rn(ex1 * LAMBDA);
            uint32_t s0u = *(uint32_t*)&s0h, s1u = *(uint32_t*)&s1h;

            uint32_t h00 = hmul2u(s0u, hadd2u(vu0.x, ev0h[0]));
            uint32_t h01 = hmul2u(s0u, hadd2u(vu0.y, ev0h[1]));
            uint32_t h02 = hmul2u(s0u, hadd2u(vu0.z, ev0h[2]));
            uint32_t h03 = hmul2u(s0u, hadd2u(vu0.w, ev0h[3]));
            uint32_t h10 = hmul2u(s1u, hadd2u(vu1.x, ev1h[0]));
            uint32_t h11 = hmul2u(s1u, hadd2u(vu1.y, ev1h[1]));
            uint32_t h12 = hmul2u(s1u, hadd2u(vu1.z, ev1h[2]));
            uint32_t h13 = hmul2u(s1u, hadd2u(vu1.w, ev1h[3]));

            uint32_t* op = &g_outh[(size_t)d * 64 + tx * 4];
            asm volatile("red.global.add.noftz.v4.f16x2 [%0], {%1,%2,%3,%4};"
                         :: "l"(op), "r"(h00), "r"(h01), "r"(h02), "r"(h03) : "memory");
            asm volatile("red.global.add.noftz.v4.f16x2 [%0], {%1,%2,%3,%4};"
                         :: "l"(op + 32), "r"(h10), "r"(h11), "r"(h12), "r"(h13) : "memory");
        }
    }
}

// ---------------------------------------------------------------------------
// K3: out = outh/(lambda*(denom+1e-16)) + skip
// ---------------------------------------------------------------------------
__global__ void finalize_kernel(float* __restrict__ out) {
    int idx = blockIdx.x * blockDim.x + threadIdx.x;
    int stride = gridDim.x * blockDim.x;
    const int total4 = NN * OUTD / 4;
    for (int i = idx; i < total4; i += stride) {
        int n = i >> 5;
        int gi = i & 31;
        int h = gi >> 4;
        float inv = (1.0f / LAMBDA) / (g_denom[2 * n + h] + 1e-16f);
        uint2 u = *(const uint2*)&g_outh[(size_t)n * 64 + gi * 2];
        float2 a = u2f(u.x), b = u2f(u.y);
        float4 sk = ((const float4*)g_skip)[i];
        float4 o;
        o.x = a.x * inv + sk.x;
        o.y = a.y * inv + sk.y;
        o.z = b.x * inv + sk.z;
        o.w = b.y * inv + sk.w;
        ((float4*)out)[i] = o;
    }
}

// ---------------------------------------------------------------------------
extern "C" void kernel_launch(void* const* d_in, const int* in_sizes, int n_in,
                              void* d_out, int out_size)
{
    const float* x     = (const float*)d_in[0];
    const float* lu    = (const float*)d_in[1];
    const float* t     = (const float*)d_in[2];
    const float* msg   = (const float*)d_in[3];
    const int*   ei    = (const int*)d_in[4];     // int32 (JAX x64 disabled)
    const float* Wtime = (const float*)d_in[5];
    const float* btime = (const float*)d_in[6];
    const float* Wq = (const float*)d_in[7];  const float* bq = (const float*)d_in[8];
    const float* Wk = (const float*)d_in[9];  const float* bk = (const float*)d_in[10];
    const float* Wv = (const float*)d_in[11]; const float* bv = (const float*)d_in[12];
    const float* We = (const float*)d_in[13]; const float* be = (const float*)d_in[14];
    const float* Wsk = (const float*)d_in[15]; const float* bsk = (const float*)d_in[16];
    float* out = (float*)d_out;

    cudaFuncSetAttribute(proj_f16, cudaFuncAttributeMaxDynamicSharedMemorySize, PROJ_SMEM_BYTES);
    cudaFuncSetAttribute(edge_kernel_mma, cudaFuncAttributeMaxDynamicSharedMemorySize, EDGE_SMEM_BYTES);

    dim3 pgrid(98, 4);   // 98*4*128 = 50176 >= NN rows, 4 row-tiles per CTA
    proj_f16<<<pgrid, 256, PROJ_SMEM_BYTES>>>(x, Wq, bq, Wk, bk, Wv, bv, Wsk, bsk);

    edge_kernel_mma<<<NCTA, 256, EDGE_SMEM_BYTES>>>(lu, t, msg, ei, Wtime, btime, We, be);

    finalize_kernel<<<2048, 256>>>(out);
}

// round 15
// speedup vs baseline: 4.1393x; 1.0421x over previous
#include <cuda_runtime.h>
#include <cuda_fp16.h>
#include <math.h>
#include <stdint.h>

#define NN   50000
#define EE   800000
#define IND  128
#define OUTD 128
#define TILES_PER_CTA 2
#define NTILES (EE / 128)                 // 6250
#define NCTA   (NTILES / TILES_PER_CTA)   // 3125

#define AH_STRIDE 52    // edge attr row stride in half2 words
#define WH_STRIDE 136   // WeH / WsH k2-row stride in half2 words
#define ESH 68          // estage row stride in half2 words
#define XH_STRIDE 68    // proj x row stride in half2 words

#define LAMBDA 0.0625f  // softmax scale shift (cancels in normalization)

// ---- scratch (static device arrays; no allocation) ----
__device__ uint32_t g_qh[NN * 64];   // q as half2 words
__device__ uint32_t g_kh[NN * 64];
__device__ uint32_t g_vh[NN * 64];
__device__ uint32_t g_outh[NN * 64]; // unnormalized attention accum (half2)
__device__ float    g_skip[NN * OUTD];
__device__ float    g_denom[NN * 2];

extern __shared__ float smem_dyn[];

__device__ __forceinline__ void mma_f16(float* d, const uint32_t* a, const uint32_t* b) {
    asm volatile("mma.sync.aligned.m16n8k16.row.col.f32.f16.f16.f32 "
                 "{%0,%1,%2,%3}, {%4,%5,%6,%7}, {%8,%9}, {%0,%1,%2,%3};"
                 : "+f"(d[0]), "+f"(d[1]), "+f"(d[2]), "+f"(d[3])
                 : "r"(a[0]), "r"(a[1]), "r"(a[2]), "r"(a[3]), "r"(b[0]), "r"(b[1]));
}
__device__ __forceinline__ uint32_t h2u(float a, float b) {
    __half2 h = __floats2half2_rn(a, b);
    return *(uint32_t*)&h;
}
__device__ __forceinline__ float2 u2f(uint32_t u) {
    return __half22float2(*(__half2*)&u);
}
__device__ __forceinline__ uint32_t hadd2u(uint32_t a, uint32_t b) {
    __half2 r = __hadd2(*(__half2*)&a, *(__half2*)&b);
    return *(uint32_t*)&r;
}
__device__ __forceinline__ uint32_t hmul2u(uint32_t a, uint32_t b) {
    __half2 r = __hmul2(*(__half2*)&a, *(__half2*)&b);
    return *(uint32_t*)&r;
}

// ---------------------------------------------------------------------------
// K1: node projections via fp16 m16n8k16, persistent over 4 row-tiles.
// N split into two halves (acc[8][4]) -> ~70 regs -> 3 CTA/SM, one wave.
// blockIdx.y==0 CTAs also zero g_outh / g_denom for their node range.
// ---------------------------------------------------------------------------
#define PROJ_SMEM_BYTES ((128 * XH_STRIDE + 64 * WH_STRIDE) * 4)

__global__ __launch_bounds__(256, 3) void proj_f16(
    const float* __restrict__ x,
    const float* __restrict__ Wq, const float* __restrict__ bq,
    const float* __restrict__ Wk, const float* __restrict__ bk,
    const float* __restrict__ Wv, const float* __restrict__ bv,
    const float* __restrict__ Wsk, const float* __restrict__ bsk)
{
    uint32_t* xsH = (uint32_t*)smem_dyn;                     // [128][68]
    uint32_t* WsH = (uint32_t*)smem_dyn + 128 * XH_STRIDE;   // [64][136]

    const float* W; const float* bias;
    uint32_t* outh = 0; float* outf = 0;
    switch (blockIdx.y) {
        case 0:  W = Wq;  bias = bq;  outh = g_qh;   break;
        case 1:  W = Wk;  bias = bk;  outh = g_kh;   break;
        case 2:  W = Wv;  bias = bv;  outh = g_vh;   break;
        default: W = Wsk; bias = bsk; outf = g_skip; break;
    }

    int tid  = threadIdx.x;
    int w    = tid >> 5;
    int lane = tid & 31;
    int g = lane >> 2, c = lane & 3;

    // Weight -> smem once per CTA
    for (int i = tid; i < 64 * 128; i += 256) {
        int k2 = i >> 7, n = i & 127;
        float w0 = W[(2 * k2) * 128 + n];
        float w1 = W[(2 * k2 + 1) * 128 + n];
        WsH[k2 * WH_STRIDE + n] = h2u(w0, w1);
    }

    // y==0 CTAs: zero accumulators for node range [bx*512, bx*512+512)
    if (blockIdx.y == 0) {
        size_t base = (size_t)blockIdx.x * 512 * 64;        // words
        size_t lim  = (size_t)NN * 64;
        for (int i = tid; i < 512 * 64 / 4; i += 256) {
            size_t wd = base + (size_t)i * 4;
            if (wd + 3 < lim)
                *(uint4*)&g_outh[wd] = make_uint4(0, 0, 0, 0);
            else
                for (int j = 0; j < 4 && wd + j < lim; j++) g_outh[wd + j] = 0;
        }
        int nb = blockIdx.x * 512;
        for (int i = tid; i < 1024; i += 256) {
            int n = nb + (i >> 1);
            if (n < NN) g_denom[2 * n + (i & 1)] = 0.f;
        }
    }

    for (int r4 = 0; r4 < 4; r4++) {
        int row0 = (blockIdx.x * 4 + r4) * 128;
        __syncthreads();        // xsH free (prev MMA reads done)

        for (int i = tid; i < 128 * 32; i += 256) {
            int r = i >> 5, j = i & 31;
            int gr = row0 + r;
            float4 v = make_float4(0.f, 0.f, 0.f, 0.f);
            if (gr < NN) v = ((const float4*)x)[(size_t)gr * 32 + j];
            uint2 u = make_uint2(h2u(v.x, v.y), h2u(v.z, v.w));
            *(uint2*)&xsH[r * XH_STRIDE + 2 * j] = u;
        }
        __syncthreads();

        int r0 = row0 + w * 16 + g;
        int r1 = r0 + 8;
        const uint32_t* a0p = xsH + (w * 16 + g) * XH_STRIDE;
        const uint32_t* a1p = a0p + 8 * XH_STRIDE;

        #pragma unroll
        for (int nh = 0; nh < 2; nh++) {
            float acc[8][4];
            #pragma unroll
            for (int j = 0; j < 8; j++) {
                acc[j][0] = 0.f; acc[j][1] = 0.f; acc[j][2] = 0.f; acc[j][3] = 0.f;
            }
            #pragma unroll
            for (int kk = 0; kk < 8; kk++) {
                uint32_t af[4];
                af[0] = a0p[kk * 8 + c];
                af[1] = a1p[kk * 8 + c];
                af[2] = a0p[kk * 8 + c + 4];
                af[3] = a1p[kk * 8 + c + 4];
                const uint32_t* b0p = WsH + (kk * 8 + c) * WH_STRIDE + nh * 64 + g;
                const uint32_t* b4p = b0p + 4 * WH_STRIDE;
                #pragma unroll
                for (int j = 0; j < 8; j++) {
                    uint32_t bf[2];
                    bf[0] = b0p[j * 8];
                    bf[1] = b4p[j * 8];
                    mma_f16(acc[j], af, bf);
                }
            }

            if (outh) {
                #pragma unroll
                for (int j = 0; j < 8; j++) {
                    int col = nh * 64 + j * 8 + 2 * c;
                    float b0 = bias[col], b1 = bias[col + 1];
                    if (r0 < NN) outh[(size_t)r0 * 64 + (col >> 1)] = h2u(acc[j][0] + b0, acc[j][1] + b1);
                    if (r1 < NN) outh[(size_t)r1 * 64 + (col >> 1)] = h2u(acc[j][2] + b0, acc[j][3] + b1);
                }
            } else {
                #pragma unroll
                for (int j = 0; j < 8; j++) {
                    int col = nh * 64 + j * 8 + 2 * c;
                    float b0 = bias[col], b1 = bias[col + 1];
                    if (r0 < NN) {
                        float2 o = make_float2(acc[j][0] + b0, acc[j][1] + b1);
                        *(float2*)&outf[(size_t)r0 * 128 + col] = o;
                    }
                    if (r1 < NN) {
                        float2 o = make_float2(acc[j][2] + b0, acc[j][3] + b1);
                        *(float2*)&outf[(size_t)r1 * 128 + col] = o;
                    }
                }
            }
        }
    }
}

// ---------------------------------------------------------------------------
// K2: edge kernel — fp16 e-GEMM, half gathers, half2 value path, f16x2 REDs
// (unchanged — proven R14)
// ---------------------------------------------------------------------------
#define EDGE_SMEM_BYTES (22272 * 4)

__global__ __launch_bounds__(256, 2) void edge_kernel_mma(
    const float* __restrict__ lu, const float* __restrict__ tt,
    const float* __restrict__ msg, const int* __restrict__ ei,
    const float* __restrict__ Wtime, const float* __restrict__ btime,
    const float* __restrict__ We, const float* __restrict__ be)
{
    int*      srcS  = (int*)smem_dyn;
    int*      dstS  = (int*)smem_dyn + 128;
    float*    relS  = smem_dyn + 256;
    uint32_t* attrH = (uint32_t*)smem_dyn + 384;
    uint32_t* WeH   = (uint32_t*)smem_dyn + 7040;
    uint32_t* estageH = (uint32_t*)smem_dyn + 13568;

    int tid = threadIdx.x;
    int w    = tid >> 5;
    int lane = tid & 31;
    int g = lane >> 2, c = lane & 3;

    for (int i = tid; i < 48 * 128; i += 256) {
        int k2 = i >> 7, n = i & 127;
        float w0 = We[(2 * k2) * 128 + n];
        float w1 = We[(2 * k2 + 1) * 128 + n];
        WeH[k2 * WH_STRIDE + n] = h2u(w0, w1);
    }

    int tx = tid & 7;
    int ey = tid >> 3;

    uint32_t beh0[4], beh1[4];
    #pragma unroll
    for (int j = 0; j < 4; j++) {
        beh0[j] = h2u(be[tx * 8 + 2 * j], be[tx * 8 + 2 * j + 1]);
        beh1[j] = h2u(be[64 + tx * 8 + 2 * j], be[64 + tx * 8 + 2 * j + 1]);
    }

    for (int t = 0; t < TILES_PER_CTA; t++) {
        int eb = (blockIdx.x * TILES_PER_CTA + t) * 128;

        __syncthreads();
        if (tid < 128) {
            int e = eb + tid;
            int s = ei[e];
            srcS[tid] = s;
            dstS[tid] = ei[EE + e];
            relS[tid] = lu[s] - tt[e];
        }
        __syncthreads();

        for (int i = tid; i < 128 * 16; i += 256) {
            int row = i >> 4, kp = i & 15;
            float rel = relS[row];
            float v0 = __cosf(rel * Wtime[2 * kp]     + btime[2 * kp]);
            float v1 = __cosf(rel * Wtime[2 * kp + 1] + btime[2 * kp + 1]);
            attrH[row * AH_STRIDE + kp] = h2u(v0, v1);
        }
        for (int i = tid; i < 128 * 16; i += 256) {
            int row = i >> 4, j = i & 15;
            float4 m = ((const float4*)msg)[(size_t)(eb + row) * 16 + j];
            uint2 u = make_uint2(h2u(m.x, m.y), h2u(m.z, m.w));
            *(uint2*)&attrH[row * AH_STRIDE + 16 + 2 * j] = u;
        }
        __syncthreads();

        float acc[16][4];
        #pragma unroll
        for (int j = 0; j < 16; j++) {
            acc[j][0] = 0.f; acc[j][1] = 0.f; acc[j][2] = 0.f; acc[j][3] = 0.f;
        }
        const uint32_t* a0p = attrH + (w * 16 + g) * AH_STRIDE;
        const uint32_t* a1p = a0p + 8 * AH_STRIDE;
        #pragma unroll
        for (int kk = 0; kk < 6; kk++) {
            uint32_t af[4];
            af[0] = a0p[kk * 8 + c];
            af[1] = a1p[kk * 8 + c];
            af[2] = a0p[kk * 8 + c + 4];
            af[3] = a1p[kk * 8 + c + 4];
            const uint32_t* b0p = WeH + (kk * 8 + c) * WH_STRIDE + g;
            const uint32_t* b4p = b0p + 4 * WH_STRIDE;
            #pragma unroll
            for (int j = 0; j < 16; j++) {
                uint32_t bf[2];
                bf[0] = b0p[j * 8];
                bf[1] = b4p[j * 8];
                mma_f16(acc[j], af, bf);
            }
        }

        #pragma unroll
        for (int j = 0; j < 16; j++) {
            estageH[(w * 16 + g)     * ESH + j * 4 + c] = h2u(acc[j][0], acc[j][1]);
            estageH[(w * 16 + g + 8) * ESH + j * 4 + c] = h2u(acc[j][2], acc[j][3]);
        }
        __syncthreads();

        #pragma unroll
        for (int m4 = 0; m4 < 4; m4++) {
            int el = ey + 32 * m4;
            int s = srcS[el], d = dstS[el];

            const uint32_t* qp = &g_qh[(size_t)d * 64 + tx * 4];
            const uint32_t* kp = &g_kh[(size_t)s * 64 + tx * 4];
            const uint32_t* vp = &g_vh[(size_t)s * 64 + tx * 4];
            uint4 qu0 = *(const uint4*)qp,        qu1 = *(const uint4*)(qp + 32);
            uint4 ku0 = *(const uint4*)kp,        ku1 = *(const uint4*)(kp + 32);
            uint4 vu0 = *(const uint4*)vp,        vu1 = *(const uint4*)(vp + 32);
            uint4 eu0 = *(uint4*)&estageH[el * ESH + tx * 4];
            uint4 eu1 = *(uint4*)&estageH[el * ESH + 32 + tx * 4];

            uint32_t ev0h[4], ev1h[4];
            ev0h[0] = hadd2u(eu0.x, beh0[0]); ev0h[1] = hadd2u(eu0.y, beh0[1]);
            ev0h[2] = hadd2u(eu0.z, beh0[2]); ev0h[3] = hadd2u(eu0.w, beh0[3]);
            ev1h[0] = hadd2u(eu1.x, beh1[0]); ev1h[1] = hadd2u(eu1.y, beh1[1]);
            ev1h[2] = hadd2u(eu1.z, beh1[2]); ev1h[3] = hadd2u(eu1.w, beh1[3]);

            float p0 = 0.f, p1 = 0.f;
            {
                const uint32_t* qw0 = (const uint32_t*)&qu0;
                const uint32_t* kw0 = (const uint32_t*)&ku0;
                const uint32_t* qw1 = (const uint32_t*)&qu1;
                const uint32_t* kw1 = (const uint32_t*)&ku1;
                #pragma unroll
                for (int j = 0; j < 4; j++) {
                    float2 qf = u2f(qw0[j]), kf = u2f(kw0[j]), ef = u2f(ev0h[j]);
                    p0 += qf.x * (kf.x + ef.x) + qf.y * (kf.y + ef.y);
                    float2 qg = u2f(qw1[j]), kg = u2f(kw1[j]), eg = u2f(ev1h[j]);
                    p1 += qg.x * (kg.x + eg.x) + qg.y * (kg.y + eg.y);
                }
            }

            p0 += __shfl_xor_sync(0xffffffffu, p0, 1);
            p1 += __shfl_xor_sync(0xffffffffu, p1, 1);
            p0 += __shfl_xor_sync(0xffffffffu, p0, 2);
            p1 += __shfl_xor_sync(0xffffffffu, p1, 2);
            p0 += __shfl_xor_sync(0xffffffffu, p0, 4);
            p1 += __shfl_xor_sync(0xffffffffu, p1, 4);

            float ex0 = __expf(p0 * 0.125f);
            float ex1 = __expf(p1 * 0.125f);
            if (tx == 0)
                atomicAdd((float2*)&g_denom[2 * d], make_float2(ex0, ex1));

            __half2 s0h = __float2half2_rn(ex0 * LAMBDA);
            __half2 s1h = __float2half2_rn(ex1 * LAMBDA);
            uint32_t s0u = *(uint32_t*)&s0h, s1u = *(uint32_t*)&s1h;

            uint32_t h00 = hmul2u(s0u, hadd2u(vu0.x, ev0h[0]));
            uint32_t h01 = hmul2u(s0u, hadd2u(vu0.y, ev0h[1]));
            uint32_t h02 = hmul2u(s0u, hadd2u(vu0.z, ev0h[2]));
            uint32_t h03 = hmul2u(s0u, hadd2u(vu0.w, ev0h[3]));
            uint32_t h10 = hmul2u(s1u, hadd2u(vu1.x, ev1h[0]));
            uint32_t h11 = hmul2u(s1u, hadd2u(vu1.y, ev1h[1]));
            uint32_t h12 = hmul2u(s1u, hadd2u(vu1.z, ev1h[2]));
            uint32_t h13 = hmul2u(s1u, hadd2u(vu1.w, ev1h[3]));

            uint32_t* op = &g_outh[(size_t)d * 64 + tx * 4];
            asm volatile("red.global.add.noftz.v4.f16x2 [%0], {%1,%2,%3,%4};"
                         :: "l"(op), "r"(h00), "r"(h01), "r"(h02), "r"(h03) : "memory");
            asm volatile("red.global.add.noftz.v4.f16x2 [%0], {%1,%2,%3,%4};"
                         :: "l"(op + 32), "r"(h10), "r"(h11), "r"(h12), "r"(h13) : "memory");
        }
    }
}

// ---------------------------------------------------------------------------
// K3: out = outh/(lambda*(denom+1e-16)) + skip
// ---------------------------------------------------------------------------
__global__ void finalize_kernel(float* __restrict__ out) {
    int idx = blockIdx.x * blockDim.x + threadIdx.x;
    int stride = gridDim.x * blockDim.x;
    const int total4 = NN * OUTD / 4;
    for (int i = idx; i < total4; i += stride) {
        int n = i >> 5;
        int gi = i & 31;
        int h = gi >> 4;
        float inv = (1.0f / LAMBDA) / (g_denom[2 * n + h] + 1e-16f);
        uint2 u = *(const uint2*)&g_outh[(size_t)n * 64 + gi * 2];
        float2 a = u2f(u.x), b = u2f(u.y);
        float4 sk = ((const float4*)g_skip)[i];
        float4 o;
        o.x = a.x * inv + sk.x;
        o.y = a.y * inv + sk.y;
        o.z = b.x * inv + sk.z;
        o.w = b.y * inv + sk.w;
        ((float4*)out)[i] = o;
    }
}

// ---------------------------------------------------------------------------
extern "C" void kernel_launch(void* const* d_in, const int* in_sizes, int n_in,
                              void* d_out, int out_size)
{
    const float* x     = (const float*)d_in[0];
    const float* lu    = (const float*)d_in[1];
    const float* t     = (const float*)d_in[2];
    const float* msg   = (const float*)d_in[3];
    const int*   ei    = (const int*)d_in[4];     // int32 (JAX x64 disabled)
    const float* Wtime = (const float*)d_in[5];
    const float* btime = (const float*)d_in[6];
    const float* Wq = (const float*)d_in[7];  const float* bq = (const float*)d_in[8];
    const float* Wk = (const float*)d_in[9];  const float* bk = (const float*)d_in[10];
    const float* Wv = (const float*)d_in[11]; const float* bv = (const float*)d_in[12];
    const float* We = (const float*)d_in[13]; const float* be = (const float*)d_in[14];
    const float* Wsk = (const float*)d_in[15]; const float* bsk = (const float*)d_in[16];
    float* out = (float*)d_out;

    cudaFuncSetAttribute(proj_f16, cudaFuncAttributeMaxDynamicSharedMemorySize, PROJ_SMEM_BYTES);
    cudaFuncSetAttribute(edge_kernel_mma, cudaFuncAttributeMaxDynamicSharedMemorySize, EDGE_SMEM_BYTES);

    dim3 pgrid(98, 4);   // 98*4*128 = 50176 >= NN rows, 4 row-tiles per CTA
    proj_f16<<<pgrid, 256, PROJ_SMEM_BYTES>>>(x, Wq, bq, Wk, bk, Wv, bv, Wsk, bsk);

    edge_kernel_mma<<<NCTA, 256, EDGE_SMEM_BYTES>>>(lu, t, msg, ei, Wtime, btime, We, be);

    finalize_kernel<<<2048, 256>>>(out);
}

// round 16
// speedup vs baseline: 4.2930x; 1.0371x over previous
#include <cuda_runtime.h>
#include <cuda_fp16.h>
#include <math.h>
#include <stdint.h>

#define NN   50000
#define EE   800000
#define IND  128
#define OUTD 128
#define TILES_PER_CTA 2
#define NTILES (EE / 128)                 // 6250
#define NCTA   (NTILES / TILES_PER_CTA)   // 3125

#define AH_STRIDE 52    // edge attr row stride in half2 words
#define WH_STRIDE 136   // WeH / WsH k2-row stride in half2 words
#define ESH 68          // estage row stride in half2 words
#define XH_STRIDE 68    // proj x row stride in half2 words

#define LAMBDA 0.0625f  // softmax scale shift (cancels in normalization)

// ---- scratch (static device arrays; no allocation) ----
__device__ uint32_t g_qh[NN * 64];   // q as half2 words
__device__ uint32_t g_kh[NN * 64];
__device__ uint32_t g_vh[NN * 64];
__device__ uint32_t g_outh[NN * 64]; // unnormalized attention accum (half2)
__device__ float    g_skip[NN * OUTD];
__device__ float    g_denom[NN * 2];

extern __shared__ float smem_dyn[];

__device__ __forceinline__ void mma_f16(float* d, const uint32_t* a, const uint32_t* b) {
    asm volatile("mma.sync.aligned.m16n8k16.row.col.f32.f16.f16.f32 "
                 "{%0,%1,%2,%3}, {%4,%5,%6,%7}, {%8,%9}, {%0,%1,%2,%3};"
                 : "+f"(d[0]), "+f"(d[1]), "+f"(d[2]), "+f"(d[3])
                 : "r"(a[0]), "r"(a[1]), "r"(a[2]), "r"(a[3]), "r"(b[0]), "r"(b[1]));
}
__device__ __forceinline__ uint32_t h2u(float a, float b) {
    __half2 h = __floats2half2_rn(a, b);
    return *(uint32_t*)&h;
}
__device__ __forceinline__ float2 u2f(uint32_t u) {
    return __half22float2(*(__half2*)&u);
}
__device__ __forceinline__ uint32_t hadd2u(uint32_t a, uint32_t b) {
    __half2 r = __hadd2(*(__half2*)&a, *(__half2*)&b);
    return *(uint32_t*)&r;
}
__device__ __forceinline__ uint32_t hmul2u(uint32_t a, uint32_t b) {
    __half2 r = __hmul2(*(__half2*)&a, *(__half2*)&b);
    return *(uint32_t*)&r;
}

// ---------------------------------------------------------------------------
// K1: node projections, fp16 m16n8k16, 2D warp tiling (4 m-strips x 2 n-halves)
// persistent over 4 row-tiles; y==0 CTAs zero accumulators.
// ---------------------------------------------------------------------------
#define PROJ_SMEM_BYTES ((128 * XH_STRIDE + 64 * WH_STRIDE) * 4)

__global__ __launch_bounds__(256, 3) void proj_f16(
    const float* __restrict__ x,
    const float* __restrict__ Wq, const float* __restrict__ bq,
    const float* __restrict__ Wk, const float* __restrict__ bk,
    const float* __restrict__ Wv, const float* __restrict__ bv,
    const float* __restrict__ Wsk, const float* __restrict__ bsk)
{
    uint32_t* xsH = (uint32_t*)smem_dyn;                     // [128][68]
    uint32_t* WsH = (uint32_t*)smem_dyn + 128 * XH_STRIDE;   // [64][136]

    const float* W; const float* bias;
    uint32_t* outh = 0; float* outf = 0;
    switch (blockIdx.y) {
        case 0:  W = Wq;  bias = bq;  outh = g_qh;   break;
        case 1:  W = Wk;  bias = bk;  outh = g_kh;   break;
        case 2:  W = Wv;  bias = bv;  outh = g_vh;   break;
        default: W = Wsk; bias = bsk; outf = g_skip; break;
    }

    int tid  = threadIdx.x;
    int w    = tid >> 5;
    int lane = tid & 31;
    int g = lane >> 2, c = lane & 3;
    int ms  = w & 3;    // m-strip: rows ms*32 .. +32
    int nh2 = w >> 2;   // n-half:  cols nh2*64 .. +64

    // Weight -> smem once per CTA
    for (int i = tid; i < 64 * 128; i += 256) {
        int k2 = i >> 7, n = i & 127;
        float w0 = W[(2 * k2) * 128 + n];
        float w1 = W[(2 * k2 + 1) * 128 + n];
        WsH[k2 * WH_STRIDE + n] = h2u(w0, w1);
    }

    // y==0 CTAs: zero accumulators for node range [bx*512, bx*512+512)
    if (blockIdx.y == 0) {
        size_t base = (size_t)blockIdx.x * 512 * 64;
        size_t lim  = (size_t)NN * 64;
        for (int i = tid; i < 512 * 64 / 4; i += 256) {
            size_t wd = base + (size_t)i * 4;
            if (wd + 3 < lim)
                *(uint4*)&g_outh[wd] = make_uint4(0, 0, 0, 0);
            else
                for (int j = 0; j < 4 && wd + j < lim; j++) g_outh[wd + j] = 0;
        }
        int nb = blockIdx.x * 512;
        for (int i = tid; i < 1024; i += 256) {
            int n = nb + (i >> 1);
            if (n < NN) g_denom[2 * n + (i & 1)] = 0.f;
        }
    }

    for (int r4 = 0; r4 < 4; r4++) {
        int row0 = (blockIdx.x * 4 + r4) * 128;
        __syncthreads();        // xsH free (prev MMA reads done)

        for (int i = tid; i < 128 * 32; i += 256) {
            int r = i >> 5, j = i & 31;
            int gr = row0 + r;
            float4 v = make_float4(0.f, 0.f, 0.f, 0.f);
            if (gr < NN) v = ((const float4*)x)[(size_t)gr * 32 + j];
            uint2 u = make_uint2(h2u(v.x, v.y), h2u(v.z, v.w));
            *(uint2*)&xsH[r * XH_STRIDE + 2 * j] = u;
        }
        __syncthreads();

        float acc[2][8][4];
        #pragma unroll
        for (int mt = 0; mt < 2; mt++)
            #pragma unroll
            for (int j = 0; j < 8; j++) {
                acc[mt][j][0] = 0.f; acc[mt][j][1] = 0.f;
                acc[mt][j][2] = 0.f; acc[mt][j][3] = 0.f;
            }
        const uint32_t* a0p = xsH + (ms * 32 + g) * XH_STRIDE;
        const uint32_t* a1p = a0p + 8 * XH_STRIDE;
        const uint32_t* a2p = a0p + 16 * XH_STRIDE;
        const uint32_t* a3p = a0p + 24 * XH_STRIDE;
        #pragma unroll
        for (int kk = 0; kk < 8; kk++) {
            uint32_t af0[4], af1[4];
            af0[0] = a0p[kk * 8 + c];      af0[1] = a1p[kk * 8 + c];
            af0[2] = a0p[kk * 8 + c + 4];  af0[3] = a1p[kk * 8 + c + 4];
            af1[0] = a2p[kk * 8 + c];      af1[1] = a3p[kk * 8 + c];
            af1[2] = a2p[kk * 8 + c + 4];  af1[3] = a3p[kk * 8 + c + 4];
            const uint32_t* b0p = WsH + (kk * 8 + c) * WH_STRIDE + nh2 * 64 + g;
            const uint32_t* b4p = b0p + 4 * WH_STRIDE;
            #pragma unroll
            for (int j = 0; j < 8; j++) {
                uint32_t bf[2];
                bf[0] = b0p[j * 8];
                bf[1] = b4p[j * 8];
                mma_f16(acc[0][j], af0, bf);
                mma_f16(acc[1][j], af1, bf);
            }
        }

        #pragma unroll
        for (int mt = 0; mt < 2; mt++) {
            int r0 = row0 + ms * 32 + mt * 16 + g;
            int r1 = r0 + 8;
            if (outh) {
                #pragma unroll
                for (int j = 0; j < 8; j++) {
                    int col = nh2 * 64 + j * 8 + 2 * c;
                    float b0 = bias[col], b1 = bias[col + 1];
                    if (r0 < NN) outh[(size_t)r0 * 64 + (col >> 1)] = h2u(acc[mt][j][0] + b0, acc[mt][j][1] + b1);
                    if (r1 < NN) outh[(size_t)r1 * 64 + (col >> 1)] = h2u(acc[mt][j][2] + b0, acc[mt][j][3] + b1);
                }
            } else {
                #pragma unroll
                for (int j = 0; j < 8; j++) {
                    int col = nh2 * 64 + j * 8 + 2 * c;
                    float b0 = bias[col], b1 = bias[col + 1];
                    if (r0 < NN) {
                        float2 o = make_float2(acc[mt][j][0] + b0, acc[mt][j][1] + b1);
                        *(float2*)&outf[(size_t)r0 * 128 + col] = o;
                    }
                    if (r1 < NN) {
                        float2 o = make_float2(acc[mt][j][2] + b0, acc[mt][j][3] + b1);
                        *(float2*)&outf[(size_t)r1 * 128 + col] = o;
                    }
                }
            }
        }
    }
}

// ---------------------------------------------------------------------------
// K2: edge kernel — fp16 e-GEMM (2D warp tiling), half gathers, f16x2 REDs
// ---------------------------------------------------------------------------
#define EDGE_SMEM_BYTES (22272 * 4)

__global__ __launch_bounds__(256, 2) void edge_kernel_mma(
    const float* __restrict__ lu, const float* __restrict__ tt,
    const float* __restrict__ msg, const int* __restrict__ ei,
    const float* __restrict__ Wtime, const float* __restrict__ btime,
    const float* __restrict__ We, const float* __restrict__ be)
{
    int*      srcS  = (int*)smem_dyn;
    int*      dstS  = (int*)smem_dyn + 128;
    float*    relS  = smem_dyn + 256;
    uint32_t* attrH = (uint32_t*)smem_dyn + 384;
    uint32_t* WeH   = (uint32_t*)smem_dyn + 7040;
    uint32_t* estageH = (uint32_t*)smem_dyn + 13568;

    int tid = threadIdx.x;
    int w    = tid >> 5;
    int lane = tid & 31;
    int g = lane >> 2, c = lane & 3;
    int ms  = w & 3;    // m-strip: edges ms*32 .. +32
    int nh2 = w >> 2;   // n-half:  cols nh2*64 .. +64

    for (int i = tid; i < 48 * 128; i += 256) {
        int k2 = i >> 7, n = i & 127;
        float w0 = We[(2 * k2) * 128 + n];
        float w1 = We[(2 * k2 + 1) * 128 + n];
        WeH[k2 * WH_STRIDE + n] = h2u(w0, w1);
    }

    int tx = tid & 7;
    int ey = tid >> 3;

    uint32_t beh0[4], beh1[4];
    #pragma unroll
    for (int j = 0; j < 4; j++) {
        beh0[j] = h2u(be[tx * 8 + 2 * j], be[tx * 8 + 2 * j + 1]);
        beh1[j] = h2u(be[64 + tx * 8 + 2 * j], be[64 + tx * 8 + 2 * j + 1]);
    }

    for (int t = 0; t < TILES_PER_CTA; t++) {
        int eb = (blockIdx.x * TILES_PER_CTA + t) * 128;

        __syncthreads();
        if (tid < 128) {
            int e = eb + tid;
            int s = ei[e];
            srcS[tid] = s;
            dstS[tid] = ei[EE + e];
            relS[tid] = lu[s] - tt[e];
        }
        __syncthreads();

        for (int i = tid; i < 128 * 16; i += 256) {
            int row = i >> 4, kp = i & 15;
            float rel = relS[row];
            float v0 = __cosf(rel * Wtime[2 * kp]     + btime[2 * kp]);
            float v1 = __cosf(rel * Wtime[2 * kp + 1] + btime[2 * kp + 1]);
            attrH[row * AH_STRIDE + kp] = h2u(v0, v1);
        }
        for (int i = tid; i < 128 * 16; i += 256) {
            int row = i >> 4, j = i & 15;
            float4 m = ((const float4*)msg)[(size_t)(eb + row) * 16 + j];
            uint2 u = make_uint2(h2u(m.x, m.y), h2u(m.z, m.w));
            *(uint2*)&attrH[row * AH_STRIDE + 16 + 2 * j] = u;
        }
        __syncthreads();

        float acc[2][8][4];
        #pragma unroll
        for (int mt = 0; mt < 2; mt++)
            #pragma unroll
            for (int j = 0; j < 8; j++) {
                acc[mt][j][0] = 0.f; acc[mt][j][1] = 0.f;
                acc[mt][j][2] = 0.f; acc[mt][j][3] = 0.f;
            }
        const uint32_t* a0p = attrH + (ms * 32 + g) * AH_STRIDE;
        const uint32_t* a1p = a0p + 8 * AH_STRIDE;
        const uint32_t* a2p = a0p + 16 * AH_STRIDE;
        const uint32_t* a3p = a0p + 24 * AH_STRIDE;
        #pragma unroll
        for (int kk = 0; kk < 6; kk++) {
            uint32_t af0[4], af1[4];
            af0[0] = a0p[kk * 8 + c];      af0[1] = a1p[kk * 8 + c];
            af0[2] = a0p[kk * 8 + c + 4];  af0[3] = a1p[kk * 8 + c + 4];
            af1[0] = a2p[kk * 8 + c];      af1[1] = a3p[kk * 8 + c];
            af1[2] = a2p[kk * 8 + c + 4];  af1[3] = a3p[kk * 8 + c + 4];
            const uint32_t* b0p = WeH + (kk * 8 + c) * WH_STRIDE + nh2 * 64 + g;
            const uint32_t* b4p = b0p + 4 * WH_STRIDE;
            #pragma unroll
            for (int j = 0; j < 8; j++) {
                uint32_t bf[2];
                bf[0] = b0p[j * 8];
                bf[1] = b4p[j * 8];
                mma_f16(acc[0][j], af0, bf);
                mma_f16(acc[1][j], af1, bf);
            }
        }

        #pragma unroll
        for (int mt = 0; mt < 2; mt++) {
            int row = ms * 32 + mt * 16 + g;
            #pragma unroll
            for (int j = 0; j < 8; j++) {
                int cw = nh2 * 32 + j * 4 + c;
                estageH[row * ESH + cw]       = h2u(acc[mt][j][0], acc[mt][j][1]);
                estageH[(row + 8) * ESH + cw] = h2u(acc[mt][j][2], acc[mt][j][3]);
            }
        }
        __syncthreads();

        #pragma unroll
        for (int m4 = 0; m4 < 4; m4++) {
            int el = ey + 32 * m4;
            int s = srcS[el], d = dstS[el];

            const uint32_t* qp = &g_qh[(size_t)d * 64 + tx * 4];
            const uint32_t* kp = &g_kh[(size_t)s * 64 + tx * 4];
            const uint32_t* vp = &g_vh[(size_t)s * 64 + tx * 4];
            uint4 qu0 = *(const uint4*)qp,        qu1 = *(const uint4*)(qp + 32);
            uint4 ku0 = *(const uint4*)kp,        ku1 = *(const uint4*)(kp + 32);
            uint4 vu0 = *(const uint4*)vp,        vu1 = *(const uint4*)(vp + 32);
            uint4 eu0 = *(uint4*)&estageH[el * ESH + tx * 4];
            uint4 eu1 = *(uint4*)&estageH[el * ESH + 32 + tx * 4];

            uint32_t ev0h[4], ev1h[4];
            ev0h[0] = hadd2u(eu0.x, beh0[0]); ev0h[1] = hadd2u(eu0.y, beh0[1]);
            ev0h[2] = hadd2u(eu0.z, beh0[2]); ev0h[3] = hadd2u(eu0.w, beh0[3]);
            ev1h[0] = hadd2u(eu1.x, beh1[0]); ev1h[1] = hadd2u(eu1.y, beh1[1]);
            ev1h[2] = hadd2u(eu1.z, beh1[2]); ev1h[3] = hadd2u(eu1.w, beh1[3]);

            float p0 = 0.f, p1 = 0.f;
            {
                const uint32_t* qw0 = (const uint32_t*)&qu0;
                const uint32_t* kw0 = (const uint32_t*)&ku0;
                const uint32_t* qw1 = (const uint32_t*)&qu1;
                const uint32_t* kw1 = (const uint32_t*)&ku1;
                #pragma unroll
                for (int j = 0; j < 4; j++) {
                    float2 qf = u2f(qw0[j]), kf = u2f(kw0[j]), ef = u2f(ev0h[j]);
                    p0 += qf.x * (kf.x + ef.x) + qf.y * (kf.y + ef.y);
                    float2 qg = u2f(qw1[j]), kg = u2f(kw1[j]), eg = u2f(ev1h[j]);
                    p1 += qg.x * (kg.x + eg.x) + qg.y * (kg.y + eg.y);
                }
            }

            p0 += __shfl_xor_sync(0xffffffffu, p0, 1);
            p1 += __shfl_xor_sync(0xffffffffu, p1, 1);
            p0 += __shfl_xor_sync(0xffffffffu, p0, 2);
            p1 += __shfl_xor_sync(0xffffffffu, p1, 2);
            p0 += __shfl_xor_sync(0xffffffffu, p0, 4);
            p1 += __shfl_xor_sync(0xffffffffu, p1, 4);

            float ex0 = __expf(p0 * 0.125f);
            float ex1 = __expf(p1 * 0.125f);
            if (tx == 0)
                atomicAdd((float2*)&g_denom[2 * d], make_float2(ex0, ex1));

            __half2 s0h = __float2half2_rn(ex0 * LAMBDA);
            __half2 s1h = __float2half2_rn(ex1 * LAMBDA);
            uint32_t s0u = *(uint32_t*)&s0h, s1u = *(uint32_t*)&s1h;

            uint32_t h00 = hmul2u(s0u, hadd2u(vu0.x, ev0h[0]));
            uint32_t h01 = hmul2u(s0u, hadd2u(vu0.y, ev0h[1]));
            uint32_t h02 = hmul2u(s0u, hadd2u(vu0.z, ev0h[2]));
            uint32_t h03 = hmul2u(s0u, hadd2u(vu0.w, ev0h[3]));
            uint32_t h10 = hmul2u(s1u, hadd2u(vu1.x, ev1h[0]));
            uint32_t h11 = hmul2u(s1u, hadd2u(vu1.y, ev1h[1]));
            uint32_t h12 = hmul2u(s1u, hadd2u(vu1.z, ev1h[2]));
            uint32_t h13 = hmul2u(s1u, hadd2u(vu1.w, ev1h[3]));

            uint32_t* op = &g_outh[(size_t)d * 64 + tx * 4];
            asm volatile("red.global.add.noftz.v4.f16x2 [%0], {%1,%2,%3,%4};"
                         :: "l"(op), "r"(h00), "r"(h01), "r"(h02), "r"(h03) : "memory");
            asm volatile("red.global.add.noftz.v4.f16x2 [%0], {%1,%2,%3,%4};"
                         :: "l"(op + 32), "r"(h10), "r"(h11), "r"(h12), "r"(h13) : "memory");
        }
    }
}

// ---------------------------------------------------------------------------
// K3: out = outh/(lambda*(denom+1e-16)) + skip
// ---------------------------------------------------------------------------
__global__ void finalize_kernel(float* __restrict__ out) {
    int idx = blockIdx.x * blockDim.x + threadIdx.x;
    int stride = gridDim.x * blockDim.x;
    const int total4 = NN * OUTD / 4;
    for (int i = idx; i < total4; i += stride) {
        int n = i >> 5;
        int gi = i & 31;
        int h = gi >> 4;
        float inv = (1.0f / LAMBDA) / (g_denom[2 * n + h] + 1e-16f);
        uint2 u = *(const uint2*)&g_outh[(size_t)n * 64 + gi * 2];
        float2 a = u2f(u.x), b = u2f(u.y);
        float4 sk = ((const float4*)g_skip)[i];
        float4 o;
        o.x = a.x * inv + sk.x;
        o.y = a.y * inv + sk.y;
        o.z = b.x * inv + sk.z;
        o.w = b.y * inv + sk.w;
        ((float4*)out)[i] = o;
    }
}

// ---------------------------------------------------------------------------
extern "C" void kernel_launch(void* const* d_in, const int* in_sizes, int n_in,
                              void* d_out, int out_size)
{
    const float* x     = (const float*)d_in[0];
    const float* lu    = (const float*)d_in[1];
    const float* t     = (const float*)d_in[2];
    const float* msg   = (const float*)d_in[3];
    const int*   ei    = (const int*)d_in[4];     // int32 (JAX x64 disabled)
    const float* Wtime = (const float*)d_in[5];
    const float* btime = (const float*)d_in[6];
    const float* Wq = (const float*)d_in[7];  const float* bq = (const float*)d_in[8];
    const float* Wk = (const float*)d_in[9];  const float* bk = (const float*)d_in[10];
    const float* Wv = (const float*)d_in[11]; const float* bv = (const float*)d_in[12];
    const float* We = (const float*)d_in[13]; const float* be = (const float*)d_in[14];
    const float* Wsk = (const float*)d_in[15]; const float* bsk = (const float*)d_in[16];
    float* out = (float*)d_out;

    cudaFuncSetAttribute(proj_f16, cudaFuncAttributeMaxDynamicSharedMemorySize, PROJ_SMEM_BYTES);
    cudaFuncSetAttribute(edge_kernel_mma, cudaFuncAttributeMaxDynamicSharedMemorySize, EDGE_SMEM_BYTES);

    dim3 pgrid(98, 4);   // 98*4*128 = 50176 >= NN rows, 4 row-tiles per CTA
    proj_f16<<<pgrid, 256, PROJ_SMEM_BYTES>>>(x, Wq, bq, Wk, bk, Wv, bv, Wsk, bsk);

    edge_kernel_mma<<<NCTA, 256, EDGE_SMEM_BYTES>>>(lu, t, msg, ei, Wtime, btime, We, be);

    finalize_kernel<<<2048, 256>>>(out);
}

// round 17
// speedup vs baseline: 4.5863x; 1.0683x over previous
#include <cuda_runtime.h>
#include <cuda_fp16.h>
#include <math.h>
#include <stdint.h>

#define NN   50000
#define EE   800000
#define IND  128
#define OUTD 128
#define TILES_PER_CTA 2
#define NTILES (EE / 128)                 // 6250
#define NCTA   (NTILES / TILES_PER_CTA)   // 3125

#define AH_STRIDE 52    // edge attr row stride in half2 words
#define WH_STRIDE 136   // WeH / WsH k2-row stride in half2 words
#define ESH 68          // estage row stride in half2 words
#define XH_STRIDE 68    // proj x row stride in half2 words

#define LAMBDA 0.0625f  // softmax scale shift (cancels in normalization)

// ---- scratch (static device arrays; no allocation) ----
__device__ uint32_t g_qh[NN * 64];   // q as half2 words
__device__ uint32_t g_kh[NN * 64];
__device__ uint32_t g_vh[NN * 64];
__device__ uint32_t g_outh[NN * 64]; // unnormalized attention accum (half2)
__device__ float    g_skip[NN * OUTD];
__device__ float    g_denom[NN * 2];

extern __shared__ float smem_dyn[];

__device__ __forceinline__ void mma_f16(float* d, const uint32_t* a, const uint32_t* b) {
    asm volatile("mma.sync.aligned.m16n8k16.row.col.f32.f16.f16.f32 "
                 "{%0,%1,%2,%3}, {%4,%5,%6,%7}, {%8,%9}, {%0,%1,%2,%3};"
                 : "+f"(d[0]), "+f"(d[1]), "+f"(d[2]), "+f"(d[3])
                 : "r"(a[0]), "r"(a[1]), "r"(a[2]), "r"(a[3]), "r"(b[0]), "r"(b[1]));
}
__device__ __forceinline__ uint32_t h2u(float a, float b) {
    __half2 h = __floats2half2_rn(a, b);
    return *(uint32_t*)&h;
}
__device__ __forceinline__ float2 u2f(uint32_t u) {
    return __half22float2(*(__half2*)&u);
}
__device__ __forceinline__ uint32_t hadd2u(uint32_t a, uint32_t b) {
    __half2 r = __hadd2(*(__half2*)&a, *(__half2*)&b);
    return *(uint32_t*)&r;
}
__device__ __forceinline__ uint32_t hmul2u(uint32_t a, uint32_t b) {
    __half2 r = __hmul2(*(__half2*)&a, *(__half2*)&b);
    return *(uint32_t*)&r;
}

// ---------------------------------------------------------------------------
// K1: node projections, fp16 m16n8k16, 2D warp tiling (proven R16)
// ---------------------------------------------------------------------------
#define PROJ_SMEM_BYTES ((128 * XH_STRIDE + 64 * WH_STRIDE) * 4)

__global__ __launch_bounds__(256, 3) void proj_f16(
    const float* __restrict__ x,
    const float* __restrict__ Wq, const float* __restrict__ bq,
    const float* __restrict__ Wk, const float* __restrict__ bk,
    const float* __restrict__ Wv, const float* __restrict__ bv,
    const float* __restrict__ Wsk, const float* __restrict__ bsk)
{
    uint32_t* xsH = (uint32_t*)smem_dyn;                     // [128][68]
    uint32_t* WsH = (uint32_t*)smem_dyn + 128 * XH_STRIDE;   // [64][136]

    const float* W; const float* bias;
    uint32_t* outh = 0; float* outf = 0;
    switch (blockIdx.y) {
        case 0:  W = Wq;  bias = bq;  outh = g_qh;   break;
        case 1:  W = Wk;  bias = bk;  outh = g_kh;   break;
        case 2:  W = Wv;  bias = bv;  outh = g_vh;   break;
        default: W = Wsk; bias = bsk; outf = g_skip; break;
    }

    int tid  = threadIdx.x;
    int w    = tid >> 5;
    int lane = tid & 31;
    int g = lane >> 2, c = lane & 3;
    int ms  = w & 3;
    int nh2 = w >> 2;

    for (int i = tid; i < 64 * 128; i += 256) {
        int k2 = i >> 7, n = i & 127;
        float w0 = W[(2 * k2) * 128 + n];
        float w1 = W[(2 * k2 + 1) * 128 + n];
        WsH[k2 * WH_STRIDE + n] = h2u(w0, w1);
    }

    if (blockIdx.y == 0) {
        size_t base = (size_t)blockIdx.x * 512 * 64;
        size_t lim  = (size_t)NN * 64;
        for (int i = tid; i < 512 * 64 / 4; i += 256) {
            size_t wd = base + (size_t)i * 4;
            if (wd + 3 < lim)
                *(uint4*)&g_outh[wd] = make_uint4(0, 0, 0, 0);
            else
                for (int j = 0; j < 4 && wd + j < lim; j++) g_outh[wd + j] = 0;
        }
        int nb = blockIdx.x * 512;
        for (int i = tid; i < 1024; i += 256) {
            int n = nb + (i >> 1);
            if (n < NN) g_denom[2 * n + (i & 1)] = 0.f;
        }
    }

    for (int r4 = 0; r4 < 4; r4++) {
        int row0 = (blockIdx.x * 4 + r4) * 128;
        __syncthreads();

        for (int i = tid; i < 128 * 32; i += 256) {
            int r = i >> 5, j = i & 31;
            int gr = row0 + r;
            float4 v = make_float4(0.f, 0.f, 0.f, 0.f);
            if (gr < NN) v = ((const float4*)x)[(size_t)gr * 32 + j];
            uint2 u = make_uint2(h2u(v.x, v.y), h2u(v.z, v.w));
            *(uint2*)&xsH[r * XH_STRIDE + 2 * j] = u;
        }
        __syncthreads();

        float acc[2][8][4];
        #pragma unroll
        for (int mt = 0; mt < 2; mt++)
            #pragma unroll
            for (int j = 0; j < 8; j++) {
                acc[mt][j][0] = 0.f; acc[mt][j][1] = 0.f;
                acc[mt][j][2] = 0.f; acc[mt][j][3] = 0.f;
            }
        const uint32_t* a0p = xsH + (ms * 32 + g) * XH_STRIDE;
        const uint32_t* a1p = a0p + 8 * XH_STRIDE;
        const uint32_t* a2p = a0p + 16 * XH_STRIDE;
        const uint32_t* a3p = a0p + 24 * XH_STRIDE;
        #pragma unroll
        for (int kk = 0; kk < 8; kk++) {
            uint32_t af0[4], af1[4];
            af0[0] = a0p[kk * 8 + c];      af0[1] = a1p[kk * 8 + c];
            af0[2] = a0p[kk * 8 + c + 4];  af0[3] = a1p[kk * 8 + c + 4];
            af1[0] = a2p[kk * 8 + c];      af1[1] = a3p[kk * 8 + c];
            af1[2] = a2p[kk * 8 + c + 4];  af1[3] = a3p[kk * 8 + c + 4];
            const uint32_t* b0p = WsH + (kk * 8 + c) * WH_STRIDE + nh2 * 64 + g;
            const uint32_t* b4p = b0p + 4 * WH_STRIDE;
            #pragma unroll
            for (int j = 0; j < 8; j++) {
                uint32_t bf[2];
                bf[0] = b0p[j * 8];
                bf[1] = b4p[j * 8];
                mma_f16(acc[0][j], af0, bf);
                mma_f16(acc[1][j], af1, bf);
            }
        }

        #pragma unroll
        for (int mt = 0; mt < 2; mt++) {
            int r0 = row0 + ms * 32 + mt * 16 + g;
            int r1 = r0 + 8;
            if (outh) {
                #pragma unroll
                for (int j = 0; j < 8; j++) {
                    int col = nh2 * 64 + j * 8 + 2 * c;
                    float b0 = bias[col], b1 = bias[col + 1];
                    if (r0 < NN) outh[(size_t)r0 * 64 + (col >> 1)] = h2u(acc[mt][j][0] + b0, acc[mt][j][1] + b1);
                    if (r1 < NN) outh[(size_t)r1 * 64 + (col >> 1)] = h2u(acc[mt][j][2] + b0, acc[mt][j][3] + b1);
                }
            } else {
                #pragma unroll
                for (int j = 0; j < 8; j++) {
                    int col = nh2 * 64 + j * 8 + 2 * c;
                    float b0 = bias[col], b1 = bias[col + 1];
                    if (r0 < NN) {
                        float2 o = make_float2(acc[mt][j][0] + b0, acc[mt][j][1] + b1);
                        *(float2*)&outf[(size_t)r0 * 128 + col] = o;
                    }
                    if (r1 < NN) {
                        float2 o = make_float2(acc[mt][j][2] + b0, acc[mt][j][3] + b1);
                        *(float2*)&outf[(size_t)r1 * 128 + col] = o;
                    }
                }
            }
        }
    }
}

// ---------------------------------------------------------------------------
// K2: edge kernel — attrH/estageH ALIASED (smem 62.5KB -> 3 CTA/SM)
// smem words: [0:128) srcS, [128:256) dstS, [256:384) relS,
//   [384:9088)   union { attrH 128 x AH_STRIDE ; estageH 128 x ESH }
//   [9088:15616) WeH 48 x WH_STRIDE
// ---------------------------------------------------------------------------
#define EDGE_SMEM_BYTES (15616 * 4)

__global__ __launch_bounds__(256, 3) void edge_kernel_mma(
    const float* __restrict__ lu, const float* __restrict__ tt,
    const float* __restrict__ msg, const int* __restrict__ ei,
    const float* __restrict__ Wtime, const float* __restrict__ btime,
    const float* __restrict__ We, const float* __restrict__ be)
{
    int*      srcS  = (int*)smem_dyn;
    int*      dstS  = (int*)smem_dyn + 128;
    float*    relS  = smem_dyn + 256;
    uint32_t* attrH = (uint32_t*)smem_dyn + 384;     // aliased with estageH
    uint32_t* estageH = (uint32_t*)smem_dyn + 384;
    uint32_t* WeH   = (uint32_t*)smem_dyn + 9088;

    int tid = threadIdx.x;
    int w    = tid >> 5;
    int lane = tid & 31;
    int g = lane >> 2, c = lane & 3;
    int ms  = w & 3;
    int nh2 = w >> 2;

    for (int i = tid; i < 48 * 128; i += 256) {
        int k2 = i >> 7, n = i & 127;
        float w0 = We[(2 * k2) * 128 + n];
        float w1 = We[(2 * k2 + 1) * 128 + n];
        WeH[k2 * WH_STRIDE + n] = h2u(w0, w1);
    }

    int tx = tid & 7;
    int ey = tid >> 3;

    uint32_t beh0[4], beh1[4];
    #pragma unroll
    for (int j = 0; j < 4; j++) {
        beh0[j] = h2u(be[tx * 8 + 2 * j], be[tx * 8 + 2 * j + 1]);
        beh1[j] = h2u(be[64 + tx * 8 + 2 * j], be[64 + tx * 8 + 2 * j + 1]);
    }

    for (int t = 0; t < TILES_PER_CTA; t++) {
        int eb = (blockIdx.x * TILES_PER_CTA + t) * 128;

        __syncthreads();   // prev consume done (estageH/srcS free)
        if (tid < 128) {
            int e = eb + tid;
            int s = ei[e];
            srcS[tid] = s;
            dstS[tid] = ei[EE + e];
            relS[tid] = lu[s] - tt[e];
        }
        __syncthreads();

        for (int i = tid; i < 128 * 16; i += 256) {
            int row = i >> 4, kp = i & 15;
            float rel = relS[row];
            float v0 = __cosf(rel * Wtime[2 * kp]     + btime[2 * kp]);
            float v1 = __cosf(rel * Wtime[2 * kp + 1] + btime[2 * kp + 1]);
            attrH[row * AH_STRIDE + kp] = h2u(v0, v1);
        }
        for (int i = tid; i < 128 * 16; i += 256) {
            int row = i >> 4, j = i & 15;
            float4 m = ((const float4*)msg)[(size_t)(eb + row) * 16 + j];
            uint2 u = make_uint2(h2u(m.x, m.y), h2u(m.z, m.w));
            *(uint2*)&attrH[row * AH_STRIDE + 16 + 2 * j] = u;
        }
        __syncthreads();

        float acc[2][8][4];
        #pragma unroll
        for (int mt = 0; mt < 2; mt++)
            #pragma unroll
            for (int j = 0; j < 8; j++) {
                acc[mt][j][0] = 0.f; acc[mt][j][1] = 0.f;
                acc[mt][j][2] = 0.f; acc[mt][j][3] = 0.f;
            }
        const uint32_t* a0p = attrH + (ms * 32 + g) * AH_STRIDE;
        const uint32_t* a1p = a0p + 8 * AH_STRIDE;
        const uint32_t* a2p = a0p + 16 * AH_STRIDE;
        const uint32_t* a3p = a0p + 24 * AH_STRIDE;
        #pragma unroll
        for (int kk = 0; kk < 6; kk++) {
            uint32_t af0[4], af1[4];
            af0[0] = a0p[kk * 8 + c];      af0[1] = a1p[kk * 8 + c];
            af0[2] = a0p[kk * 8 + c + 4];  af0[3] = a1p[kk * 8 + c + 4];
            af1[0] = a2p[kk * 8 + c];      af1[1] = a3p[kk * 8 + c];
            af1[2] = a2p[kk * 8 + c + 4];  af1[3] = a3p[kk * 8 + c + 4];
            const uint32_t* b0p = WeH + (kk * 8 + c) * WH_STRIDE + nh2 * 64 + g;
            const uint32_t* b4p = b0p + 4 * WH_STRIDE;
            #pragma unroll
            for (int j = 0; j < 8; j++) {
                uint32_t bf[2];
                bf[0] = b0p[j * 8];
                bf[1] = b4p[j * 8];
                mma_f16(acc[0][j], af0, bf);
                mma_f16(acc[1][j], af1, bf);
            }
        }
        __syncthreads();   // all attrH reads done before estage overwrite (ALIASED)

        #pragma unroll
        for (int mt = 0; mt < 2; mt++) {
            int row = ms * 32 + mt * 16 + g;
            #pragma unroll
            for (int j = 0; j < 8; j++) {
                int cw = nh2 * 32 + j * 4 + c;
                estageH[row * ESH + cw]       = h2u(acc[mt][j][0], acc[mt][j][1]);
                estageH[(row + 8) * ESH + cw] = h2u(acc[mt][j][2], acc[mt][j][3]);
            }
        }
        __syncthreads();

        #pragma unroll
        for (int m4 = 0; m4 < 4; m4++) {
            int el = ey + 32 * m4;
            int s = srcS[el], d = dstS[el];

            const uint32_t* qp = &g_qh[(size_t)d * 64 + tx * 4];
            const uint32_t* kp = &g_kh[(size_t)s * 64 + tx * 4];
            const uint32_t* vp = &g_vh[(size_t)s * 64 + tx * 4];
            uint4 qu0 = *(const uint4*)qp,        qu1 = *(const uint4*)(qp + 32);
            uint4 ku0 = *(const uint4*)kp,        ku1 = *(const uint4*)(kp + 32);
            uint4 vu0 = *(const uint4*)vp,        vu1 = *(const uint4*)(vp + 32);
            uint4 eu0 = *(uint4*)&estageH[el * ESH + tx * 4];
            uint4 eu1 = *(uint4*)&estageH[el * ESH + 32 + tx * 4];

            uint32_t ev0h[4], ev1h[4];
            ev0h[0] = hadd2u(eu0.x, beh0[0]); ev0h[1] = hadd2u(eu0.y, beh0[1]);
            ev0h[2] = hadd2u(eu0.z, beh0[2]); ev0h[3] = hadd2u(eu0.w, beh0[3]);
            ev1h[0] = hadd2u(eu1.x, beh1[0]); ev1h[1] = hadd2u(eu1.y, beh1[1]);
            ev1h[2] = hadd2u(eu1.z, beh1[2]); ev1h[3] = hadd2u(eu1.w, beh1[3]);

            float p0 = 0.f, p1 = 0.f;
            {
                const uint32_t* qw0 = (const uint32_t*)&qu0;
                const uint32_t* kw0 = (const uint32_t*)&ku0;
                const uint32_t* qw1 = (const uint32_t*)&qu1;
                const uint32_t* kw1 = (const uint32_t*)&ku1;
                #pragma unroll
                for (int j = 0; j < 4; j++) {
                    float2 qf = u2f(qw0[j]), kf = u2f(kw0[j]), ef = u2f(ev0h[j]);
                    p0 += qf.x * (kf.x + ef.x) + qf.y * (kf.y + ef.y);
                    float2 qg = u2f(qw1[j]), kg = u2f(kw1[j]), eg = u2f(ev1h[j]);
                    p1 += qg.x * (kg.x + eg.x) + qg.y * (kg.y + eg.y);
                }
            }

            p0 += __shfl_xor_sync(0xffffffffu, p0, 1);
            p1 += __shfl_xor_sync(0xffffffffu, p1, 1);
            p0 += __shfl_xor_sync(0xffffffffu, p0, 2);
            p1 += __shfl_xor_sync(0xffffffffu, p1, 2);
            p0 += __shfl_xor_sync(0xffffffffu, p0, 4);
            p1 += __shfl_xor_sync(0xffffffffu, p1, 4);

            float ex0 = __expf(p0 * 0.125f);
            float ex1 = __expf(p1 * 0.125f);
            if (tx == 0)
                atomicAdd((float2*)&g_denom[2 * d], make_float2(ex0, ex1));

            __half2 s0h = __float2half2_rn(ex0 * LAMBDA);
            __half2 s1h = __float2half2_rn(ex1 * LAMBDA);
            uint32_t s0u = *(uint32_t*)&s0h, s1u = *(uint32_t*)&s1h;

            uint32_t h00 = hmul2u(s0u, hadd2u(vu0.x, ev0h[0]));
            uint32_t h01 = hmul2u(s0u, hadd2u(vu0.y, ev0h[1]));
            uint32_t h02 = hmul2u(s0u, hadd2u(vu0.z, ev0h[2]));
            uint32_t h03 = hmul2u(s0u, hadd2u(vu0.w, ev0h[3]));
            uint32_t h10 = hmul2u(s1u, hadd2u(vu1.x, ev1h[0]));
            uint32_t h11 = hmul2u(s1u, hadd2u(vu1.y, ev1h[1]));
            uint32_t h12 = hmul2u(s1u, hadd2u(vu1.z, ev1h[2]));
            uint32_t h13 = hmul2u(s1u, hadd2u(vu1.w, ev1h[3]));

            uint32_t* op = &g_outh[(size_t)d * 64 + tx * 4];
            asm volatile("red.global.add.noftz.v4.f16x2 [%0], {%1,%2,%3,%4};"
                         :: "l"(op), "r"(h00), "r"(h01), "r"(h02), "r"(h03) : "memory");
            asm volatile("red.global.add.noftz.v4.f16x2 [%0], {%1,%2,%3,%4};"
                         :: "l"(op + 32), "r"(h10), "r"(h11), "r"(h12), "r"(h13) : "memory");
        }
    }
}

// ---------------------------------------------------------------------------
// K3: out = outh/(lambda*(denom+1e-16)) + skip
// ---------------------------------------------------------------------------
__global__ void finalize_kernel(float* __restrict__ out) {
    int idx = blockIdx.x * blockDim.x + threadIdx.x;
    int stride = gridDim.x * blockDim.x;
    const int total4 = NN * OUTD / 4;
    for (int i = idx; i < total4; i += stride) {
        int n = i >> 5;
        int gi = i & 31;
        int h = gi >> 4;
        float inv = (1.0f / LAMBDA) / (g_denom[2 * n + h] + 1e-16f);
        uint2 u = *(const uint2*)&g_outh[(size_t)n * 64 + gi * 2];
        float2 a = u2f(u.x), b = u2f(u.y);
        float4 sk = ((const float4*)g_skip)[i];
        float4 o;
        o.x = a.x * inv + sk.x;
        o.y = a.y * inv + sk.y;
        o.z = b.x * inv + sk.z;
        o.w = b.y * inv + sk.w;
        ((float4*)out)[i] = o;
    }
}

// ---------------------------------------------------------------------------
extern "C" void kernel_launch(void* const* d_in, const int* in_sizes, int n_in,
                              void* d_out, int out_size)
{
    const float* x     = (const float*)d_in[0];
    const float* lu    = (const float*)d_in[1];
    const float* t     = (const float*)d_in[2];
    const float* msg   = (const float*)d_in[3];
    const int*   ei    = (const int*)d_in[4];     // int32 (JAX x64 disabled)
    const float* Wtime = (const float*)d_in[5];
    const float* btime = (const float*)d_in[6];
    const float* Wq = (const float*)d_in[7];  const float* bq = (const float*)d_in[8];
    const float* Wk = (const float*)d_in[9];  const float* bk = (const float*)d_in[10];
    const float* Wv = (const float*)d_in[11]; const float* bv = (const float*)d_in[12];
    const float* We = (const float*)d_in[13]; const float* be = (const float*)d_in[14];
    const float* Wsk = (const float*)d_in[15]; const float* bsk = (const float*)d_in[16];
    float* out = (float*)d_out;

    cudaFuncSetAttribute(proj_f16, cudaFuncAttributeMaxDynamicSharedMemorySize, PROJ_SMEM_BYTES);
    cudaFuncSetAttribute(edge_kernel_mma, cudaFuncAttributeMaxDynamicSharedMemorySize, EDGE_SMEM_BYTES);

    dim3 pgrid(98, 4);   // 98*4*128 = 50176 >= NN rows, 4 row-tiles per CTA
    proj_f16<<<pgrid, 256, PROJ_SMEM_BYTES>>>(x, Wq, bq, Wk, bk, Wv, bv, Wsk, bsk);

    edge_kernel_mma<<<NCTA, 256, EDGE_SMEM_BYTES>>>(lu, t, msg, ei, Wtime, btime, We, be);

    finalize_kernel<<<2048, 256>>>(out);
}